// round 3
// baseline (speedup 1.0000x reference)
#include <cuda_runtime.h>

namespace {

using ull = unsigned long long;

constexpr int Lc = 2048, Hc = 8, Ec = 64;
constexpr int BM = 64, BN = 128;
constexpr int TSQ = 68;              // Qs row stride (floats), e-major
constexpr int TSK = 132;             // Ks/Ps row stride (floats)
constexpr int RE = Hc * Ec;          // 512
constexpr float SCL2E = 0.125f * 1.44269504088896340736f;

// smem offsets in floats
constexpr int OFF_Q = 0;                         // [Ec][TSQ]
constexpr int OFF_KP = OFF_Q + Ec * TSQ;         // [64][TSK]  K-tile (e-major), aliased as P-tile
constexpr int OFF_V = OFF_KP + 64 * TSK;         // [BN][Ec]
constexpr int OFF_L = OFF_V + BN * Ec;           // [64][4]
constexpr int SMEM_FLOATS = OFF_L + BM * 4;

__device__ __forceinline__ float ex2f(float x) {
  float y; asm("ex2.approx.ftz.f32 %0, %1;" : "=f"(y) : "f"(x)); return y;
}
__device__ __forceinline__ void fma2(ull& d, ull a, ull b) {
  asm("fma.rn.f32x2 %0, %1, %2, %0;" : "+l"(d) : "l"(a), "l"(b));
}
__device__ __forceinline__ void mul2(ull& d, ull a) {
  asm("mul.rn.f32x2 %0, %0, %1;" : "+l"(d) : "l"(a));
}
__device__ __forceinline__ ull bcast2(float x) {
  ull r; asm("mov.b64 %0, {%1, %1};" : "=l"(r) : "f"(x)); return r;
}
__device__ __forceinline__ void unp2(ull v, float& lo, float& hi) {
  asm("mov.b64 {%0, %1}, %2;" : "=f"(lo), "=f"(hi) : "l"(v));
}

__global__ __launch_bounds__(256, 2)
void hybrid_attn(const float* __restrict__ Q, const float* __restrict__ K,
                 const float* __restrict__ V, float* __restrict__ O) {
  extern __shared__ float smf[];
  float* Qs = smf + OFF_Q;
  float* KP = smf + OFF_KP;
  float* Vs = smf + OFF_V;
  float* Ls = smf + OFF_L;

  const int tid = threadIdx.x;
  const int tx = tid & 15;           // 16 col groups
  const int ty = tid >> 4;           // 16 row groups
  const int r0 = ty << 2;            // 4 query rows
  const int c0 = tx << 2;            // key cols [4tx..4tx+3] / e-cols in PV
  const int c1 = 64 + c0;            // key cols [64+4tx..+3]

  const int m0 = blockIdx.x * BM;
  const int bh = blockIdx.y;
  const int base = ((bh >> 3) * Lc * Hc + (bh & 7)) * Ec;
  const float* Qg = Q + base;
  const float* Kg = K + base;
  const float* Vg = V + base;
  float* Og = O + base;

  const int le4 = (tid & 15) << 2;   // loader e-chunk
  const int lrow = tid >> 4;         // loader row base (0..15)

  // ---- prologue: Q tile -> Qs (e-major, scaled) ----
  #pragma unroll
  for (int it = 0; it < 4; ++it) {
    const int r = lrow + it * 16;
    const float4 q = *reinterpret_cast<const float4*>(&Qg[(m0 + r) * RE + le4]);
    Qs[(le4 + 0) * TSQ + r] = q.x * SCL2E;
    Qs[(le4 + 1) * TSQ + r] = q.y * SCL2E;
    Qs[(le4 + 2) * TSQ + r] = q.z * SCL2E;
    Qs[(le4 + 3) * TSQ + r] = q.w * SCL2E;
  }

  float mi[4], li[4];
  ull acc[4][2];
  #pragma unroll
  for (int i = 0; i < 4; ++i) { mi[i] = -1e30f; li[i] = 0.f; acc[i][0] = 0ull; acc[i][1] = 0ull; }

  for (int n0 = 0; n0 < Lc; n0 += BN) {
    __syncthreads();  // prev PV done reading KP(=Ps)/Vs

    // ---- load K (transposed into KP, e-major) and V (natural) ----
    #pragma unroll
    for (int it = 0; it < 8; ++it) {
      const int r = lrow + it * 16;
      const float4 kk = *reinterpret_cast<const float4*>(&Kg[(n0 + r) * RE + le4]);
      KP[(le4 + 0) * TSK + r] = kk.x;
      KP[(le4 + 1) * TSK + r] = kk.y;
      KP[(le4 + 2) * TSK + r] = kk.z;
      KP[(le4 + 3) * TSK + r] = kk.w;
      const float4 vv = *reinterpret_cast<const float4*>(&Vg[(n0 + r) * RE + le4]);
      *reinterpret_cast<float4*>(&Vs[r * Ec + le4]) = vv;
    }
    __syncthreads();

    // ---- QK^T: s[4 rows][8 cols as 4 f32x2 pairs] ----
    ull s[4][4];
    #pragma unroll
    for (int i = 0; i < 4; ++i)
      #pragma unroll
      for (int p = 0; p < 4; ++p) s[i][p] = 0ull;

    #pragma unroll 8
    for (int e = 0; e < Ec; ++e) {
      const ulonglong2 b0 = *reinterpret_cast<const ulonglong2*>(&KP[e * TSK + c0]);
      const ulonglong2 b1 = *reinterpret_cast<const ulonglong2*>(&KP[e * TSK + c1]);
      const float4 a0 = *reinterpret_cast<const float4*>(&Qs[e * TSQ + r0]);
      ull aa;
      aa = bcast2(a0.x); fma2(s[0][0], aa, b0.x); fma2(s[0][1], aa, b0.y); fma2(s[0][2], aa, b1.x); fma2(s[0][3], aa, b1.y);
      aa = bcast2(a0.y); fma2(s[1][0], aa, b0.x); fma2(s[1][1], aa, b0.y); fma2(s[1][2], aa, b1.x); fma2(s[1][3], aa, b1.y);
      aa = bcast2(a0.z); fma2(s[2][0], aa, b0.x); fma2(s[2][1], aa, b0.y); fma2(s[2][2], aa, b1.x); fma2(s[2][3], aa, b1.y);
      aa = bcast2(a0.w); fma2(s[3][0], aa, b0.x); fma2(s[3][1], aa, b0.y); fma2(s[3][2], aa, b1.x); fma2(s[3][3], aa, b1.y);
    }
    __syncthreads();  // all threads done reading KP as K-tile

    // ---- online softmax; write P into KP (aliased) ----
    #pragma unroll
    for (int i = 0; i < 4; ++i) {
      float v0, v1, v2, v3, v4, v5, v6, v7;
      unp2(s[i][0], v0, v1); unp2(s[i][1], v2, v3);
      unp2(s[i][2], v4, v5); unp2(s[i][3], v6, v7);
      float tm = fmaxf(fmaxf(fmaxf(v0, v1), fmaxf(v2, v3)),
                       fmaxf(fmaxf(v4, v5), fmaxf(v6, v7)));
      #pragma unroll
      for (int off = 8; off; off >>= 1)
        tm = fmaxf(tm, __shfl_xor_sync(0xffffffffu, tm, off));
      const float newm = fmaxf(mi[i], tm);
      const float fac = ex2f(mi[i] - newm);
      v0 = ex2f(v0 - newm); v1 = ex2f(v1 - newm); v2 = ex2f(v2 - newm); v3 = ex2f(v3 - newm);
      v4 = ex2f(v4 - newm); v5 = ex2f(v5 - newm); v6 = ex2f(v6 - newm); v7 = ex2f(v7 - newm);
      float psum = (v0 + v1) + (v2 + v3) + (v4 + v5) + (v6 + v7);
      #pragma unroll
      for (int off = 8; off; off >>= 1)
        psum += __shfl_xor_sync(0xffffffffu, psum, off);
      li[i] = li[i] * fac + psum;
      mi[i] = newm;
      const ull fv = bcast2(fac);
      mul2(acc[i][0], fv); mul2(acc[i][1], fv);
      *reinterpret_cast<float4*>(&KP[(r0 + i) * TSK + c0]) = make_float4(v0, v1, v2, v3);
      *reinterpret_cast<float4*>(&KP[(r0 + i) * TSK + c1]) = make_float4(v4, v5, v6, v7);
    }
    __syncthreads();

    // ---- PV: acc[4 rows][4 e-cols as 2 pairs] ----
    #pragma unroll 4
    for (int j0 = 0; j0 < BN; j0 += 4) {
      const ulonglong2 w0 = *reinterpret_cast<const ulonglong2*>(&Vs[(j0 + 0) * Ec + c0]);
      const ulonglong2 w1 = *reinterpret_cast<const ulonglong2*>(&Vs[(j0 + 1) * Ec + c0]);
      const ulonglong2 w2 = *reinterpret_cast<const ulonglong2*>(&Vs[(j0 + 2) * Ec + c0]);
      const ulonglong2 w3 = *reinterpret_cast<const ulonglong2*>(&Vs[(j0 + 3) * Ec + c0]);
      #pragma unroll
      for (int i = 0; i < 4; ++i) {
        const float4 p = *reinterpret_cast<const float4*>(&KP[(r0 + i) * TSK + j0]);
        ull aa;
        aa = bcast2(p.x); fma2(acc[i][0], aa, w0.x); fma2(acc[i][1], aa, w0.y);
        aa = bcast2(p.y); fma2(acc[i][0], aa, w1.x); fma2(acc[i][1], aa, w1.y);
        aa = bcast2(p.z); fma2(acc[i][0], aa, w2.x); fma2(acc[i][1], aa, w2.y);
        aa = bcast2(p.w); fma2(acc[i][0], aa, w3.x); fma2(acc[i][1], aa, w3.y);
      }
    }
  }

  // ---- local branch scores: one (row, jj) per thread ----
  __syncthreads();
  {
    const int row = tid >> 2;          // 0..63
    const int jj = tid & 3;            // 0..3
    const int ig = m0 + row;
    const int j = ig - 2 + jj;
    float sc = -1e30f;
    if (j >= 0 && j < Lc) {
      float dot = 0.f;
      #pragma unroll
      for (int e4 = 0; e4 < Ec; e4 += 4) {
        const float4 kk = *reinterpret_cast<const float4*>(&Kg[j * RE + e4]);
        dot += Qs[(e4 + 0) * TSQ + row] * kk.x
             + Qs[(e4 + 1) * TSQ + row] * kk.y
             + Qs[(e4 + 2) * TSQ + row] * kk.z
             + Qs[(e4 + 3) * TSQ + row] * kk.w;
      }
      sc = dot;  // already includes scale*log2e via Qs
    }
    Ls[(row << 2) + jj] = sc;
  }
  __syncthreads();

  // ---- combine global + local, write output ----
  #pragma unroll
  for (int i = 0; i < 4; ++i) {
    const int r = r0 + i;
    const int ig = m0 + r;
    const float4 lsc = *reinterpret_cast<const float4*>(&Ls[r << 2]);
    const float mx = fmaxf(fmaxf(lsc.x, lsc.y), fmaxf(lsc.z, lsc.w));
    float w[4];
    w[0] = ex2f(lsc.x - mx); w[1] = ex2f(lsc.y - mx);
    w[2] = ex2f(lsc.z - mx); w[3] = ex2f(lsc.w - mx);
    const float winv = 1.f / (w[0] + w[1] + w[2] + w[3]);
    const float invl = 1.f / li[i];
    float o0, o1, o2, o3;
    unp2(acc[i][0], o0, o1); unp2(acc[i][1], o2, o3);
    float4 outv = make_float4(o0 * invl, o1 * invl, o2 * invl, o3 * invl);
    #pragma unroll
    for (int jj = 0; jj < 4; ++jj) {
      const int j = ig - 2 + jj;
      if (j >= 0 && j < Lc) {
        const float wj = w[jj] * winv;
        const float4 v = *reinterpret_cast<const float4*>(&Vg[j * RE + c0]);
        outv.x += wj * v.x; outv.y += wj * v.y;
        outv.z += wj * v.z; outv.w += wj * v.w;
      }
    }
    *reinterpret_cast<float4*>(&Og[ig * RE + c0]) = outv;
  }
}

}  // namespace

extern "C" void kernel_launch(void* const* d_in, const int* in_sizes, int n_in,
                              void* d_out, int out_size) {
  const float* Q = (const float*)d_in[0];
  const float* K = (const float*)d_in[1];
  const float* V = (const float*)d_in[2];
  float* O = (float*)d_out;

  const size_t smem = (size_t)SMEM_FLOATS * sizeof(float);
  cudaFuncSetAttribute(hybrid_attn, cudaFuncAttributeMaxDynamicSharedMemorySize, (int)smem);

  dim3 grid(Lc / BM, 4 * Hc);
  hybrid_attn<<<grid, 256, smem>>>(Q, K, V, O);
}

// round 6
// speedup vs baseline: 2.9289x; 2.9289x over previous
#include <cuda_runtime.h>
#include <cuda_fp16.h>
#include <cstdint>

// tcgen05 is only legal on arch-specific (sm_103a/sm_100a) device passes.
#if defined(__CUDA_ARCH_FEAT_SM103_ALL) || defined(__CUDA_ARCH_FEAT_SM100_ALL) || \
    defined(__CUDA_ARCH_FEAT_SM101_ALL) ||                                        \
    (defined(__CUDA_ARCH_SPECIFIC__) && (__CUDA_ARCH_SPECIFIC__ >= 1000)) ||       \
    (defined(__CUDA_ARCH_FAMILY_SPECIFIC__) && (__CUDA_ARCH_FAMILY_SPECIFIC__ >= 1000))
#define HAS_TC 1
#else
#define HAS_TC 0
#endif

namespace {

using ull = unsigned long long;

constexpr int Lc = 2048, Hc = 8, Ec = 64;
constexpr int RE = Hc * Ec;                  // 512
constexpr float SCL2E = 0.125f * 1.44269504088896340736f;

__device__ __forceinline__ float ex2f(float x) {
  float y; asm("ex2.approx.ftz.f32 %0, %1;" : "=f"(y) : "f"(x)); return y;
}

// ======================= TC kernel (sm_103a path) ==========================

constexpr int BMt = 128, BNt = 64;
constexpr int NTt = Lc / BNt;                // 32 key tiles
constexpr float PBIAS = 4.0f;                // keeps p in fp16-normal range
constexpr unsigned IDESC = 0x08100010u;      // kind::f16: F32 acc, f16 a/b, M=128, N=64

constexpr unsigned TM_S = 0, TM_O = 64, TM_PH = 128, TM_PL = 160;
constexpr unsigned TM_COLS = 256;

constexpr int OFF_PTR = 0, OFF_MB_S = 8, OFF_MB_O = 16;
constexpr int OFF_QH = 1024;
constexpr int OFF_QL = OFF_QH + 16384;
constexpr int OFF_K0 = OFF_QL + 16384;       // KH @ +0, KL @ +8192
constexpr int OFF_K1 = OFF_K0 + 16384;
constexpr int OFF_V0 = OFF_K1 + 16384;       // VHt @ +0, VLt @ +8192
constexpr int OFF_V1 = OFF_V0 + 16384;
constexpr int SMEM_TC = OFF_V1 + 16384;      // 99328 B

#if HAS_TC

constexpr unsigned long long DESC_BASE =
    (2ull << 61) | (1ull << 46) | (64ull << 32) | (1ull << 16);

__device__ __forceinline__ unsigned sm32(const void* p) {
  unsigned a;
  asm("{ .reg .u64 t; cvta.to.shared.u64 t, %1; cvt.u32.u64 %0, t; }" : "=r"(a) : "l"(p));
  return a;
}
__device__ __forceinline__ unsigned long long mkdesc(unsigned addr) {
  return DESC_BASE | ((unsigned long long)(addr >> 4) & 0x3FFF);
}
__device__ __forceinline__ unsigned swzb(unsigned off) { return off ^ ((off >> 3) & 0x70); }
__device__ __forceinline__ unsigned packh2(float a, float b) {
  __half2 t = __floats2half2_rn(a, b);
  return reinterpret_cast<unsigned&>(t);
}
__device__ __forceinline__ void split1(float x, float& h, float& l) {
  __half b = __float2half_rn(x);
  h = __half2float(b);
  l = x - h;
}
__device__ __forceinline__ unsigned elect1() {
  unsigned p;
  asm volatile("{\n\t.reg .pred p;\n\telect.sync _|p, 0xFFFFFFFF;\n\tselp.b32 %0, 1, 0, p;\n\t}" : "=r"(p));
  return p;
}
__device__ __forceinline__ void mbar_init(unsigned mbar, unsigned cnt) {
  asm volatile("mbarrier.init.shared.b64 [%0], %1;" :: "r"(mbar), "r"(cnt) : "memory");
}
__device__ __forceinline__ void mbar_wait(unsigned mbar, unsigned parity) {
  asm volatile(
      "{\n\t.reg .pred P1;\n\t"
      "LWAIT_%=:\n\t"
      "mbarrier.try_wait.parity.acquire.cta.shared::cta.b64 P1, [%0], %1, 0x989680;\n\t"
      "@P1 bra.uni LDONE_%=;\n\t"
      "bra.uni LWAIT_%=;\n\t"
      "LDONE_%=:\n\t}"
      :: "r"(mbar), "r"(parity) : "memory");
}
__device__ __forceinline__ void tc_commit(unsigned mbar) {
  asm volatile(
      "tcgen05.commit.cta_group::1.mbarrier::arrive::one.shared::cluster.b64 [%0];"
      :: "r"(mbar) : "memory");
}
__device__ __forceinline__ void tc_alloc(unsigned dst, unsigned ncols) {
  asm volatile("tcgen05.alloc.cta_group::1.sync.aligned.shared::cta.b32 [%0], %1;"
               :: "r"(dst), "r"(ncols) : "memory");
}
__device__ __forceinline__ void tc_relinq() {
  asm volatile("tcgen05.relinquish_alloc_permit.cta_group::1.sync.aligned;");
}
__device__ __forceinline__ void tc_dealloc(unsigned base, unsigned ncols) {
  asm volatile("tcgen05.dealloc.cta_group::1.sync.aligned.b32 %0, %1;" :: "r"(base), "r"(ncols));
}
__device__ __forceinline__ void fence_before() {
  asm volatile("tcgen05.fence::before_thread_sync;" ::: "memory");
}
__device__ __forceinline__ void fence_after() {
  asm volatile("tcgen05.fence::after_thread_sync;" ::: "memory");
}
__device__ __forceinline__ void fence_proxy() {
  asm volatile("fence.proxy.async.shared::cta;" ::: "memory");
}
__device__ __forceinline__ void wait_ld() { asm volatile("tcgen05.wait::ld.sync.aligned;" ::: "memory"); }
__device__ __forceinline__ void wait_st() { asm volatile("tcgen05.wait::st.sync.aligned;" ::: "memory"); }

__device__ __forceinline__ void mma_ss(unsigned d, unsigned long long ad,
                                       unsigned long long bd, unsigned idesc, bool en) {
  unsigned e = en ? 1u : 0u;
  asm volatile(
      "{\n\t.reg .pred p;\n\tsetp.ne.u32 p, %5, 0;\n\t"
      "tcgen05.mma.cta_group::1.kind::f16 [%0], %1, %2, %3, {%4, %4, %4, %4}, p;\n\t}"
      :: "r"(d), "l"(ad), "l"(bd), "r"(idesc), "r"(0u), "r"(e) : "memory");
}
__device__ __forceinline__ void mma_ts(unsigned d, unsigned a,
                                       unsigned long long bd, unsigned idesc, bool en) {
  unsigned e = en ? 1u : 0u;
  asm volatile(
      "{\n\t.reg .pred p;\n\tsetp.ne.u32 p, %5, 0;\n\t"
      "tcgen05.mma.cta_group::1.kind::f16 [%0], [%1], %2, %3, {%4, %4, %4, %4}, p;\n\t}"
      :: "r"(d), "r"(a), "l"(bd), "r"(idesc), "r"(0u), "r"(e) : "memory");
}

#define TLD32(r, addr)                                                        \
  asm volatile(                                                               \
      "tcgen05.ld.sync.aligned.32x32b.x32.b32 "                               \
      "{%0, %1, %2, %3, %4, %5, %6, %7, "                                     \
      " %8, %9, %10, %11, %12, %13, %14, %15, "                               \
      " %16, %17, %18, %19, %20, %21, %22, %23, "                             \
      " %24, %25, %26, %27, %28, %29, %30, %31}, [%32];"                      \
      : "=r"((r)[0]),  "=r"((r)[1]),  "=r"((r)[2]),  "=r"((r)[3]),            \
        "=r"((r)[4]),  "=r"((r)[5]),  "=r"((r)[6]),  "=r"((r)[7]),            \
        "=r"((r)[8]),  "=r"((r)[9]),  "=r"((r)[10]), "=r"((r)[11]),           \
        "=r"((r)[12]), "=r"((r)[13]), "=r"((r)[14]), "=r"((r)[15]),           \
        "=r"((r)[16]), "=r"((r)[17]), "=r"((r)[18]), "=r"((r)[19]),           \
        "=r"((r)[20]), "=r"((r)[21]), "=r"((r)[22]), "=r"((r)[23]),           \
        "=r"((r)[24]), "=r"((r)[25]), "=r"((r)[26]), "=r"((r)[27]),           \
        "=r"((r)[28]), "=r"((r)[29]), "=r"((r)[30]), "=r"((r)[31])            \
      : "r"(addr))

#define TST16(addr, r)                                                        \
  asm volatile(                                                               \
      "tcgen05.st.sync.aligned.32x32b.x16.b32 [%0], "                         \
      "{%1, %2, %3, %4, %5, %6, %7, %8, "                                     \
      " %9, %10, %11, %12, %13, %14, %15, %16};"                              \
      :: "r"(addr),                                                           \
         "r"((r)[0]),  "r"((r)[1]),  "r"((r)[2]),  "r"((r)[3]),               \
         "r"((r)[4]),  "r"((r)[5]),  "r"((r)[6]),  "r"((r)[7]),               \
         "r"((r)[8]),  "r"((r)[9]),  "r"((r)[10]), "r"((r)[11]),              \
         "r"((r)[12]), "r"((r)[13]), "r"((r)[14]), "r"((r)[15])               \
      : "memory")

#endif  // HAS_TC

__global__ __launch_bounds__(128, 2)
void hybrid_attn_tc(const float* __restrict__ Q, const float* __restrict__ K,
                    const float* __restrict__ V, float* __restrict__ O) {
#if HAS_TC
  extern __shared__ char smc[];
  const unsigned sb = sm32(smc);
  const int tid = threadIdx.x;
  const int wid = tid >> 5;
  const int m0 = blockIdx.x * BMt;
  const int bh = blockIdx.y;
  const int base = ((bh >> 3) * Lc * Hc + (bh & 7)) * Ec;
  const float* Qg = Q + base;
  const float* Kg = K + base;
  const float* Vg = V + base;
  float* Og = O + base;

  if (tid == 0) { mbar_init(sb + OFF_MB_S, 1); mbar_init(sb + OFF_MB_O, 1); }
  if (wid == 0) { tc_alloc(sb + OFF_PTR, TM_COLS); tc_relinq(); }
  __syncthreads();
  unsigned tb;
  asm volatile("ld.shared.b32 %0, [%1];" : "=r"(tb) : "r"(sb + OFF_PTR));

  // ---- Q tile -> QH/QL (fp16 split, SW128, 128B rows) ----
  #pragma unroll
  for (int it = 0; it < 16; ++it) {
    const int idx = tid + it * 128;
    const int r = idx >> 4, e4 = (idx & 15) << 2;
    const float4 q = *reinterpret_cast<const float4*>(&Qg[(m0 + r) * RE + e4]);
    float hx, hy, hz, hw, lx, ly, lz, lw;
    split1(q.x, hx, lx); split1(q.y, hy, ly); split1(q.z, hz, lz); split1(q.w, hw, lw);
    const unsigned sw = swzb((unsigned)(r * 128 + e4 * 2));
    *reinterpret_cast<unsigned*>(smc + OFF_QH + sw)     = packh2(hx, hy);
    *reinterpret_cast<unsigned*>(smc + OFF_QH + sw + 4) = packh2(hz, hw);
    *reinterpret_cast<unsigned*>(smc + OFF_QL + sw)     = packh2(lx, ly);
    *reinterpret_cast<unsigned*>(smc + OFF_QL + sw + 4) = packh2(lz, lw);
  }

  unsigned ps = 0, po = 0;
  float lsum = 0.f;
  const unsigned woff = (unsigned)wid << 21;

  for (int nt = 0; nt < NTt; ++nt) {
    const int n0 = nt * BNt;
    const int kb = (nt & 1) ? OFF_K1 : OFF_K0;
    const int vb = (nt & 1) ? OFF_V1 : OFF_V0;

    // ---- load K (natural rows, split) + V (transposed, split) ----
    #pragma unroll
    for (int it = 0; it < 8; ++it) {
      const int idx = tid + it * 128;
      const int j = idx >> 4, e4 = (idx & 15) << 2;
      const float4 kk = *reinterpret_cast<const float4*>(&Kg[(n0 + j) * RE + e4]);
      float hx, hy, hz, hw, lx, ly, lz, lw;
      split1(kk.x, hx, lx); split1(kk.y, hy, ly); split1(kk.z, hz, lz); split1(kk.w, hw, lw);
      const unsigned sw = swzb((unsigned)(j * 128 + e4 * 2));
      *reinterpret_cast<unsigned*>(smc + kb + sw)            = packh2(hx, hy);
      *reinterpret_cast<unsigned*>(smc + kb + sw + 4)        = packh2(hz, hw);
      *reinterpret_cast<unsigned*>(smc + kb + 8192 + sw)     = packh2(lx, ly);
      *reinterpret_cast<unsigned*>(smc + kb + 8192 + sw + 4) = packh2(lz, lw);
      const float4 vv = *reinterpret_cast<const float4*>(&Vg[(n0 + j) * RE + e4]);
      #pragma unroll
      for (int t = 0; t < 4; ++t) {
        const float x = (t == 0) ? vv.x : (t == 1) ? vv.y : (t == 2) ? vv.z : vv.w;
        float h, l;
        split1(x, h, l);
        const unsigned sv = swzb((unsigned)((e4 + t) * 128 + j * 2));
        *reinterpret_cast<__half*>(smc + vb + sv)        = __float2half_rn(h);
        *reinterpret_cast<__half*>(smc + vb + 8192 + sv) = __float2half_rn(l);
      }
    }
    fence_proxy();
    __syncthreads();

    // ---- S = Qh·Kh + Qh·Kl + Ql·Kh ----
    if (wid == 0) {
      if (elect1()) {
        const unsigned long long dqh = mkdesc(sb + OFF_QH), dql = mkdesc(sb + OFF_QL);
        const unsigned long long dkh = mkdesc(sb + kb), dkl = mkdesc(sb + kb + 8192);
        #pragma unroll
        for (int k = 0; k < 4; ++k) mma_ss(tb + TM_S, dqh + 2 * k, dkh + 2 * k, IDESC, k > 0);
        #pragma unroll
        for (int k = 0; k < 4; ++k) mma_ss(tb + TM_S, dqh + 2 * k, dkl + 2 * k, IDESC, true);
        #pragma unroll
        for (int k = 0; k < 4; ++k) mma_ss(tb + TM_S, dql + 2 * k, dkh + 2 * k, IDESC, true);
        tc_commit(sb + OFF_MB_S);
      }
    }
    mbar_wait(sb + OFF_MB_S, ps); ps ^= 1;
    fence_after();

    // ---- epilogue in two 32-column halves: p = 2^(s*scl2e - bias) ----
    #pragma unroll
    for (int hblk = 0; hblk < 2; ++hblk) {
      unsigned sr[32];
      TLD32(sr, tb + TM_S + 32 * hblk);
      wait_ld();
      unsigned ph[16], pl[16];
      #pragma unroll
      for (int c = 0; c < 16; ++c) {
        const float s0 = __uint_as_float(sr[2 * c]);
        const float s1 = __uint_as_float(sr[2 * c + 1]);
        const float p0 = ex2f(fmaf(s0, SCL2E, -PBIAS));
        const float p1 = ex2f(fmaf(s1, SCL2E, -PBIAS));
        lsum += p0 + p1;
        float h0, l0, h1, l1;
        split1(p0, h0, l0); split1(p1, h1, l1);
        ph[c] = packh2(h0, h1);
        pl[c] = packh2(l0, l1);
      }
      if (hblk == 0 && nt > 0) { mbar_wait(sb + OFF_MB_O, po); po ^= 1; }
      TST16(tb + TM_PH + 16 * hblk + woff, ph);
      TST16(tb + TM_PL + 16 * hblk + woff, pl);
    }
    wait_st();
    fence_before();
    __syncthreads();

    // ---- O += Ph·Vh + Ph·Vl + Pl·Vh ----
    if (wid == 0) {
      if (elect1()) {
        fence_after();
        fence_proxy();
        const unsigned long long dvh = mkdesc(sb + vb), dvl = mkdesc(sb + vb + 8192);
        #pragma unroll
        for (int k = 0; k < 4; ++k)
          mma_ts(tb + TM_O, tb + TM_PH + 8 * k, dvh + 2 * k, IDESC, !(nt == 0 && k == 0));
        #pragma unroll
        for (int k = 0; k < 4; ++k)
          mma_ts(tb + TM_O, tb + TM_PH + 8 * k, dvl + 2 * k, IDESC, true);
        #pragma unroll
        for (int k = 0; k < 4; ++k)
          mma_ts(tb + TM_O, tb + TM_PL + 8 * k, dvh + 2 * k, IDESC, true);
        tc_commit(sb + OFF_MB_O);
      }
    }
  }

  mbar_wait(sb + OFF_MB_O, po);
  fence_after();

  unsigned orr[64];
  TLD32(orr, tb + TM_O);
  TLD32(orr + 32, tb + TM_O + 32);
  wait_ld();
  fence_before();

  // ---- local branch (fp32 from gmem) + combine + write ----
  {
    const int ig = m0 + tid;
    const bool b0 = (ig - 2) >= 0;
    const bool b1 = (ig - 1) >= 0;
    const bool b3 = (ig + 1) < Lc;
    const float* qrow = Qg + ig * RE;
    const float* k0 = Kg + (ig - 2) * RE;
    const float* k1 = Kg + (ig - 1) * RE;
    const float* k2 = Kg + ig * RE;
    const float* k3 = Kg + (ig + 1) * RE;
    float d0 = 0.f, d1 = 0.f, d2 = 0.f, d3 = 0.f;
    #pragma unroll 4
    for (int e4 = 0; e4 < Ec; e4 += 4) {
      const float4 q = *reinterpret_cast<const float4*>(&qrow[e4]);
      if (b0) { const float4 kk = *reinterpret_cast<const float4*>(&k0[e4]);
                d0 += q.x * kk.x + q.y * kk.y + q.z * kk.z + q.w * kk.w; }
      if (b1) { const float4 kk = *reinterpret_cast<const float4*>(&k1[e4]);
                d1 += q.x * kk.x + q.y * kk.y + q.z * kk.z + q.w * kk.w; }
      {       const float4 kk = *reinterpret_cast<const float4*>(&k2[e4]);
                d2 += q.x * kk.x + q.y * kk.y + q.z * kk.z + q.w * kk.w; }
      if (b3) { const float4 kk = *reinterpret_cast<const float4*>(&k3[e4]);
                d3 += q.x * kk.x + q.y * kk.y + q.z * kk.z + q.w * kk.w; }
    }
    const float s0 = b0 ? d0 * SCL2E : -1e30f;
    const float s1 = b1 ? d1 * SCL2E : -1e30f;
    const float s2 = d2 * SCL2E;
    const float s3 = b3 ? d3 * SCL2E : -1e30f;
    const float mx = fmaxf(fmaxf(s0, s1), fmaxf(s2, s3));
    const float w0 = ex2f(s0 - mx), w1 = ex2f(s1 - mx);
    const float w2 = ex2f(s2 - mx), w3 = ex2f(s3 - mx);
    const float winv = 1.f / (w0 + w1 + w2 + w3);
    const float n0w = w0 * winv, n1w = w1 * winv, n2w = w2 * winv, n3w = w3 * winv;
    const float invl = 1.f / lsum;
    const float* vp0 = Vg + (ig - 2) * RE;
    const float* vp1 = Vg + (ig - 1) * RE;
    const float* vp2 = Vg + ig * RE;
    const float* vp3 = Vg + (ig + 1) * RE;
    #pragma unroll
    for (int e4 = 0; e4 < Ec; e4 += 4) {
      float4 o;
      o.x = __uint_as_float(orr[e4 + 0]) * invl;
      o.y = __uint_as_float(orr[e4 + 1]) * invl;
      o.z = __uint_as_float(orr[e4 + 2]) * invl;
      o.w = __uint_as_float(orr[e4 + 3]) * invl;
      if (b0) { const float4 vv = *reinterpret_cast<const float4*>(&vp0[e4]);
                o.x += n0w * vv.x; o.y += n0w * vv.y; o.z += n0w * vv.z; o.w += n0w * vv.w; }
      if (b1) { const float4 vv = *reinterpret_cast<const float4*>(&vp1[e4]);
                o.x += n1w * vv.x; o.y += n1w * vv.y; o.z += n1w * vv.z; o.w += n1w * vv.w; }
      {       const float4 vv = *reinterpret_cast<const float4*>(&vp2[e4]);
                o.x += n2w * vv.x; o.y += n2w * vv.y; o.z += n2w * vv.z; o.w += n2w * vv.w; }
      if (b3) { const float4 vv = *reinterpret_cast<const float4*>(&vp3[e4]);
                o.x += n3w * vv.x; o.y += n3w * vv.y; o.z += n3w * vv.z; o.w += n3w * vv.w; }
      *reinterpret_cast<float4*>(&Og[ig * RE + e4]) = o;
    }
  }

  __syncthreads();
  if (wid == 0) tc_dealloc(tb, TM_COLS);
#endif  // HAS_TC
}

// ===================== SIMT fallback (plain sm_103 path) ====================

constexpr int BM = 64, BN = 128;
constexpr int TSQ = 68;
constexpr int TSK = 132;
constexpr int OFF_Q = 0;
constexpr int OFF_KP = OFF_Q + Ec * TSQ;
constexpr int OFF_V = OFF_KP + 64 * TSK;
constexpr int OFF_L = OFF_V + BN * Ec;
constexpr int SMEM_FLOATS = OFF_L + BM * 4;

#if !HAS_TC
__device__ __forceinline__ void fma2(ull& d, ull a, ull b) {
  asm("fma.rn.f32x2 %0, %1, %2, %0;" : "+l"(d) : "l"(a), "l"(b));
}
__device__ __forceinline__ void mul2(ull& d, ull a) {
  asm("mul.rn.f32x2 %0, %0, %1;" : "+l"(d) : "l"(a));
}
__device__ __forceinline__ ull bcast2(float x) {
  ull r; asm("mov.b64 %0, {%1, %1};" : "=l"(r) : "f"(x)); return r;
}
__device__ __forceinline__ void unp2(ull v, float& lo, float& hi) {
  asm("mov.b64 {%0, %1}, %2;" : "=f"(lo), "=f"(hi) : "l"(v));
}
#endif

__global__ __launch_bounds__(128, 2)
void hybrid_attn_simt(const float* __restrict__ Q, const float* __restrict__ K,
                      const float* __restrict__ V, float* __restrict__ O) {
#if !HAS_TC
  extern __shared__ float smf[];
  float* Qs = smf + OFF_Q;
  float* KP = smf + OFF_KP;
  float* Vs = smf + OFF_V;
  float* Ls = smf + OFF_L;

  const int tid = threadIdx.x;
  const int tx = tid & 15;
  const int ty = tid >> 4;
  const int r0 = ty << 3;
  const int c0 = tx << 2;
  const int c1 = 64 + c0;

  const int m0 = blockIdx.x * BM;
  const int bh = blockIdx.y;
  const int base = ((bh >> 3) * Lc * Hc + (bh & 7)) * Ec;
  const float* Qg = Q + base;
  const float* Kg = K + base;
  const float* Vg = V + base;
  float* Og = O + base;

  const int le4 = (tid & 15) << 2;
  const int lr = tid >> 4;

  #pragma unroll
  for (int it = 0; it < 8; ++it) {
    const int r = lr + it * 8;
    const float4 q = *reinterpret_cast<const float4*>(&Qg[(m0 + r) * RE + le4]);
    Qs[(le4 + 0) * TSQ + r] = q.x * SCL2E;
    Qs[(le4 + 1) * TSQ + r] = q.y * SCL2E;
    Qs[(le4 + 2) * TSQ + r] = q.z * SCL2E;
    Qs[(le4 + 3) * TSQ + r] = q.w * SCL2E;
  }

  float mi[8], li[8];
  ull acc[8][2];
  #pragma unroll
  for (int i = 0; i < 8; ++i) { mi[i] = -1e30f; li[i] = 0.f; acc[i][0] = 0ull; acc[i][1] = 0ull; }

  for (int n0 = 0; n0 < Lc; n0 += BN) {
    __syncthreads();
    #pragma unroll
    for (int it = 0; it < 16; ++it) {
      const int r = lr + it * 8;
      const float4 kk = *reinterpret_cast<const float4*>(&Kg[(n0 + r) * RE + le4]);
      KP[(le4 + 0) * TSK + r] = kk.x;
      KP[(le4 + 1) * TSK + r] = kk.y;
      KP[(le4 + 2) * TSK + r] = kk.z;
      KP[(le4 + 3) * TSK + r] = kk.w;
      const float4 vv = *reinterpret_cast<const float4*>(&Vg[(n0 + r) * RE + le4]);
      *reinterpret_cast<float4*>(&Vs[r * Ec + le4]) = vv;
    }
    __syncthreads();

    ull s[8][4];
    #pragma unroll
    for (int i = 0; i < 8; ++i)
      #pragma unroll
      for (int p = 0; p < 4; ++p) s[i][p] = 0ull;

    #pragma unroll 4
    for (int e = 0; e < Ec; ++e) {
      const ulonglong2 b0 = *reinterpret_cast<const ulonglong2*>(&KP[e * TSK + c0]);
      const ulonglong2 b1 = *reinterpret_cast<const ulonglong2*>(&KP[e * TSK + c1]);
      const float4 a0 = *reinterpret_cast<const float4*>(&Qs[e * TSQ + r0]);
      const float4 a1 = *reinterpret_cast<const float4*>(&Qs[e * TSQ + r0 + 4]);
      ull aa;
      aa = bcast2(a0.x); fma2(s[0][0], aa, b0.x); fma2(s[0][1], aa, b0.y); fma2(s[0][2], aa, b1.x); fma2(s[0][3], aa, b1.y);
      aa = bcast2(a0.y); fma2(s[1][0], aa, b0.x); fma2(s[1][1], aa, b0.y); fma2(s[1][2], aa, b1.x); fma2(s[1][3], aa, b1.y);
      aa = bcast2(a0.z); fma2(s[2][0], aa, b0.x); fma2(s[2][1], aa, b0.y); fma2(s[2][2], aa, b1.x); fma2(s[2][3], aa, b1.y);
      aa = bcast2(a0.w); fma2(s[3][0], aa, b0.x); fma2(s[3][1], aa, b0.y); fma2(s[3][2], aa, b1.x); fma2(s[3][3], aa, b1.y);
      aa = bcast2(a1.x); fma2(s[4][0], aa, b0.x); fma2(s[4][1], aa, b0.y); fma2(s[4][2], aa, b1.x); fma2(s[4][3], aa, b1.y);
      aa = bcast2(a1.y); fma2(s[5][0], aa, b0.x); fma2(s[5][1], aa, b0.y); fma2(s[5][2], aa, b1.x); fma2(s[5][3], aa, b1.y);
      aa = bcast2(a1.z); fma2(s[6][0], aa, b0.x); fma2(s[6][1], aa, b0.y); fma2(s[6][2], aa, b1.x); fma2(s[6][3], aa, b1.y);
      aa = bcast2(a1.w); fma2(s[7][0], aa, b0.x); fma2(s[7][1], aa, b0.y); fma2(s[7][2], aa, b1.x); fma2(s[7][3], aa, b1.y);
    }
    __syncthreads();

    #pragma unroll
    for (int i = 0; i < 8; ++i) {
      float v0, v1, v2, v3, v4, v5, v6, v7;
      unp2(s[i][0], v0, v1); unp2(s[i][1], v2, v3);
      unp2(s[i][2], v4, v5); unp2(s[i][3], v6, v7);
      float tm = fmaxf(fmaxf(fmaxf(v0, v1), fmaxf(v2, v3)),
                       fmaxf(fmaxf(v4, v5), fmaxf(v6, v7)));
      #pragma unroll
      for (int off = 8; off; off >>= 1)
        tm = fmaxf(tm, __shfl_xor_sync(0xffffffffu, tm, off));
      const float newm = fmaxf(mi[i], tm);
      const float fac = ex2f(mi[i] - newm);
      v0 = ex2f(v0 - newm); v1 = ex2f(v1 - newm); v2 = ex2f(v2 - newm); v3 = ex2f(v3 - newm);
      v4 = ex2f(v4 - newm); v5 = ex2f(v5 - newm); v6 = ex2f(v6 - newm); v7 = ex2f(v7 - newm);
      float psum = (v0 + v1) + (v2 + v3) + (v4 + v5) + (v6 + v7);
      #pragma unroll
      for (int off = 8; off; off >>= 1)
        psum += __shfl_xor_sync(0xffffffffu, psum, off);
      li[i] = li[i] * fac + psum;
      mi[i] = newm;
      const ull fv = bcast2(fac);
      mul2(acc[i][0], fv); mul2(acc[i][1], fv);
      *reinterpret_cast<float4*>(&KP[(r0 + i) * TSK + c0]) = make_float4(v0, v1, v2, v3);
      *reinterpret_cast<float4*>(&KP[(r0 + i) * TSK + c1]) = make_float4(v4, v5, v6, v7);
    }
    __syncthreads();

    #pragma unroll 2
    for (int j0 = 0; j0 < BN; j0 += 4) {
      const ulonglong2 w0 = *reinterpret_cast<const ulonglong2*>(&Vs[(j0 + 0) * Ec + c0]);
      const ulonglong2 w1 = *reinterpret_cast<const ulonglong2*>(&Vs[(j0 + 1) * Ec + c0]);
      const ulonglong2 w2 = *reinterpret_cast<const ulonglong2*>(&Vs[(j0 + 2) * Ec + c0]);
      const ulonglong2 w3 = *reinterpret_cast<const ulonglong2*>(&Vs[(j0 + 3) * Ec + c0]);
      #pragma unroll
      for (int i = 0; i < 8; ++i) {
        const float4 p = *reinterpret_cast<const float4*>(&KP[(r0 + i) * TSK + j0]);
        ull aa;
        aa = bcast2(p.x); fma2(acc[i][0], aa, w0.x); fma2(acc[i][1], aa, w0.y);
        aa = bcast2(p.y); fma2(acc[i][0], aa, w1.x); fma2(acc[i][1], aa, w1.y);
        aa = bcast2(p.z); fma2(acc[i][0], aa, w2.x); fma2(acc[i][1], aa, w2.y);
        aa = bcast2(p.w); fma2(acc[i][0], aa, w3.x); fma2(acc[i][1], aa, w3.y);
      }
    }
  }

  __syncthreads();
  {
    const int row = tid >> 1;
    const int jbase = (tid & 1) << 1;
    #pragma unroll
    for (int t = 0; t < 2; ++t) {
      const int jj = jbase + t;
      const int ig = m0 + row;
      const int j = ig - 2 + jj;
      float sc = -1e30f;
      if (j >= 0 && j < Lc) {
        float dot = 0.f;
        #pragma unroll
        for (int e4 = 0; e4 < Ec; e4 += 4) {
          const float4 kk = *reinterpret_cast<const float4*>(&Kg[j * RE + e4]);
          dot += Qs[(e4 + 0) * TSQ + row] * kk.x
               + Qs[(e4 + 1) * TSQ + row] * kk.y
               + Qs[(e4 + 2) * TSQ + row] * kk.z
               + Qs[(e4 + 3) * TSQ + row] * kk.w;
        }
        sc = dot;
      }
      Ls[(row << 2) + jj] = sc;
    }
  }
  __syncthreads();

  #pragma unroll
  for (int i = 0; i < 8; ++i) {
    const int r = r0 + i;
    const int ig = m0 + r;
    const float4 lsc = *reinterpret_cast<const float4*>(&Ls[r << 2]);
    const float mx = fmaxf(fmaxf(lsc.x, lsc.y), fmaxf(lsc.z, lsc.w));
    float w[4];
    w[0] = ex2f(lsc.x - mx); w[1] = ex2f(lsc.y - mx);
    w[2] = ex2f(lsc.z - mx); w[3] = ex2f(lsc.w - mx);
    const float winv = 1.f / (w[0] + w[1] + w[2] + w[3]);
    const float invl = 1.f / li[i];
    float o0, o1, o2, o3;
    unp2(acc[i][0], o0, o1); unp2(acc[i][1], o2, o3);
    float4 outv = make_float4(o0 * invl, o1 * invl, o2 * invl, o3 * invl);
    #pragma unroll
    for (int jj = 0; jj < 4; ++jj) {
      const int j = ig - 2 + jj;
      if (j >= 0 && j < Lc) {
        const float wj = w[jj] * winv;
        const float4 v = *reinterpret_cast<const float4*>(&Vg[j * RE + c0]);
        outv.x += wj * v.x; outv.y += wj * v.y;
        outv.z += wj * v.z; outv.w += wj * v.w;
      }
    }
    *reinterpret_cast<float4*>(&Og[ig * RE + c0]) = outv;
  }
#endif  // !HAS_TC
}

}  // namespace

extern "C" void kernel_launch(void* const* d_in, const int* in_sizes, int n_in,
                              void* d_out, int out_size) {
  const float* Q = (const float*)d_in[0];
  const float* K = (const float*)d_in[1];
  const float* V = (const float*)d_in[2];
  float* O = (float*)d_out;

  cudaFuncSetAttribute(hybrid_attn_tc, cudaFuncAttributeMaxDynamicSharedMemorySize, SMEM_TC);
  const size_t smemS = (size_t)SMEM_FLOATS * sizeof(float);
  cudaFuncSetAttribute(hybrid_attn_simt, cudaFuncAttributeMaxDynamicSharedMemorySize, (int)smemS);

  dim3 gridTC(Lc / BMt, 4 * Hc);
  hybrid_attn_tc<<<gridTC, 128, SMEM_TC>>>(Q, K, V, O);
  dim3 gridS(Lc / BM, 4 * Hc);
  hybrid_attn_simt<<<gridS, 128, smemS>>>(Q, K, V, O);
}

// round 9
// speedup vs baseline: 3.3063x; 1.1289x over previous
#include <cuda_runtime.h>
#include <cuda_fp16.h>
#include <cstdint>

// tcgen05 is only legal on arch-specific (sm_103a/sm_100a) device passes.
#if defined(__CUDA_ARCH_FEAT_SM103_ALL) || defined(__CUDA_ARCH_FEAT_SM100_ALL) || \
    defined(__CUDA_ARCH_FEAT_SM101_ALL) ||                                        \
    (defined(__CUDA_ARCH_SPECIFIC__) && (__CUDA_ARCH_SPECIFIC__ >= 1000)) ||       \
    (defined(__CUDA_ARCH_FAMILY_SPECIFIC__) && (__CUDA_ARCH_FAMILY_SPECIFIC__ >= 1000))
#define HAS_TC 1
#else
#define HAS_TC 0
#endif

namespace {

using ull = unsigned long long;

constexpr int Lc = 2048, Hc = 8, Ec = 64;
constexpr int RE = Hc * Ec;                  // 512
constexpr float SCL2E = 0.125f * 1.44269504088896340736f;

__device__ __forceinline__ float ex2f(float x) {
  float y; asm("ex2.approx.ftz.f32 %0, %1;" : "=f"(y) : "f"(x)); return y;
}

// ======================= TC kernel (sm_103a path) ==========================

constexpr int BMt = 128, BNt = 64;
constexpr int NTt = Lc / BNt;                // 32 key tiles
constexpr float PBIAS = 4.0f;
constexpr unsigned IDESC = 0x08100010u;      // kind::f16: F32 acc, f16 a/b, M=128, N=64

constexpr unsigned TM_S = 0, TM_O = 64, TM_PH = 128, TM_PL = 160;
constexpr unsigned TM_COLS = 256;

constexpr int OFF_PTR = 0, OFF_MB_S = 8, OFF_MB_O = 16;
constexpr int OFF_QH = 1024;
constexpr int OFF_QL = OFF_QH + 16384;
constexpr int OFF_K0 = OFF_QL + 16384;       // KH @ +0, KL @ +8192 (64 rows x 128B)
constexpr int OFF_K1 = OFF_K0 + 16384;
constexpr int OFF_V0 = OFF_K1 + 16384;       // VHt @ +0, VLt @ +8192 (e-major transposed)
constexpr int OFF_V1 = OFF_V0 + 16384;
constexpr int OFF_LS = OFF_V1 + 16384;       // float Ls[128][4] local scores
constexpr int OFF_LSUM = OFF_LS + 2048;      // float Lsum[128]
constexpr int SMEM_TC = OFF_LSUM + 512;      // 101888 B

#if HAS_TC

// K-major SW128 descriptor: LBO=1, SBO=64
constexpr unsigned long long DESC_BASE =
    (2ull << 61) | (1ull << 46) | (64ull << 32) | (1ull << 16);

__device__ __forceinline__ unsigned sm32(const void* p) {
  unsigned a;
  asm("{ .reg .u64 t; cvta.to.shared.u64 t, %1; cvt.u32.u64 %0, t; }" : "=r"(a) : "l"(p));
  return a;
}
__device__ __forceinline__ unsigned long long mkdesc(unsigned addr) {
  return DESC_BASE | ((unsigned long long)(addr >> 4) & 0x3FFF);
}
__device__ __forceinline__ unsigned swzb(unsigned off) { return off ^ ((off >> 3) & 0x70); }
__device__ __forceinline__ unsigned packh2(float a, float b) {
  __half2 t = __floats2half2_rn(a, b);
  return reinterpret_cast<unsigned&>(t);
}
__device__ __forceinline__ void split1(float x, float& h, float& l) {
  __half b = __float2half_rn(x);
  h = __half2float(b);
  l = x - h;
}
__device__ __forceinline__ unsigned elect1() {
  unsigned p;
  asm volatile("{\n\t.reg .pred p;\n\telect.sync _|p, 0xFFFFFFFF;\n\tselp.b32 %0, 1, 0, p;\n\t}" : "=r"(p));
  return p;
}
__device__ __forceinline__ void mbar_init(unsigned mbar, unsigned cnt) {
  asm volatile("mbarrier.init.shared.b64 [%0], %1;" :: "r"(mbar), "r"(cnt) : "memory");
}
__device__ __forceinline__ void mbar_wait(unsigned mbar, unsigned parity) {
  asm volatile(
      "{\n\t.reg .pred P1;\n\t"
      "LWAIT_%=:\n\t"
      "mbarrier.try_wait.parity.acquire.cta.shared::cta.b64 P1, [%0], %1, 0x989680;\n\t"
      "@P1 bra.uni LDONE_%=;\n\t"
      "bra.uni LWAIT_%=;\n\t"
      "LDONE_%=:\n\t}"
      :: "r"(mbar), "r"(parity) : "memory");
}
__device__ __forceinline__ void tc_commit(unsigned mbar) {
  asm volatile(
      "tcgen05.commit.cta_group::1.mbarrier::arrive::one.shared::cluster.b64 [%0];"
      :: "r"(mbar) : "memory");
}
__device__ __forceinline__ void tc_alloc(unsigned dst, unsigned ncols) {
  asm volatile("tcgen05.alloc.cta_group::1.sync.aligned.shared::cta.b32 [%0], %1;"
               :: "r"(dst), "r"(ncols) : "memory");
}
__device__ __forceinline__ void tc_relinq() {
  asm volatile("tcgen05.relinquish_alloc_permit.cta_group::1.sync.aligned;");
}
__device__ __forceinline__ void tc_dealloc(unsigned base, unsigned ncols) {
  asm volatile("tcgen05.dealloc.cta_group::1.sync.aligned.b32 %0, %1;" :: "r"(base), "r"(ncols));
}
__device__ __forceinline__ void fence_before() {
  asm volatile("tcgen05.fence::before_thread_sync;" ::: "memory");
}
__device__ __forceinline__ void fence_after() {
  asm volatile("tcgen05.fence::after_thread_sync;" ::: "memory");
}
__device__ __forceinline__ void fence_proxy() {
  asm volatile("fence.proxy.async.shared::cta;" ::: "memory");
}
__device__ __forceinline__ void wait_ld() { asm volatile("tcgen05.wait::ld.sync.aligned;" ::: "memory"); }
__device__ __forceinline__ void wait_st() { asm volatile("tcgen05.wait::st.sync.aligned;" ::: "memory"); }

__device__ __forceinline__ void mma_ss(unsigned d, unsigned long long ad,
                                       unsigned long long bd, unsigned idesc, bool en) {
  unsigned e = en ? 1u : 0u;
  asm volatile(
      "{\n\t.reg .pred p;\n\tsetp.ne.u32 p, %5, 0;\n\t"
      "tcgen05.mma.cta_group::1.kind::f16 [%0], %1, %2, %3, {%4, %4, %4, %4}, p;\n\t}"
      :: "r"(d), "l"(ad), "l"(bd), "r"(idesc), "r"(0u), "r"(e) : "memory");
}
__device__ __forceinline__ void mma_ts(unsigned d, unsigned a,
                                       unsigned long long bd, unsigned idesc, bool en) {
  unsigned e = en ? 1u : 0u;
  asm volatile(
      "{\n\t.reg .pred p;\n\tsetp.ne.u32 p, %5, 0;\n\t"
      "tcgen05.mma.cta_group::1.kind::f16 [%0], [%1], %2, %3, {%4, %4, %4, %4}, p;\n\t}"
      :: "r"(d), "r"(a), "l"(bd), "r"(idesc), "r"(0u), "r"(e) : "memory");
}

#define TLD32(r, addr)                                                        \
  asm volatile(                                                               \
      "tcgen05.ld.sync.aligned.32x32b.x32.b32 "                               \
      "{%0, %1, %2, %3, %4, %5, %6, %7, "                                     \
      " %8, %9, %10, %11, %12, %13, %14, %15, "                               \
      " %16, %17, %18, %19, %20, %21, %22, %23, "                             \
      " %24, %25, %26, %27, %28, %29, %30, %31}, [%32];"                      \
      : "=r"((r)[0]),  "=r"((r)[1]),  "=r"((r)[2]),  "=r"((r)[3]),            \
        "=r"((r)[4]),  "=r"((r)[5]),  "=r"((r)[6]),  "=r"((r)[7]),            \
        "=r"((r)[8]),  "=r"((r)[9]),  "=r"((r)[10]), "=r"((r)[11]),           \
        "=r"((r)[12]), "=r"((r)[13]), "=r"((r)[14]), "=r"((r)[15]),           \
        "=r"((r)[16]), "=r"((r)[17]), "=r"((r)[18]), "=r"((r)[19]),           \
        "=r"((r)[20]), "=r"((r)[21]), "=r"((r)[22]), "=r"((r)[23]),           \
        "=r"((r)[24]), "=r"((r)[25]), "=r"((r)[26]), "=r"((r)[27]),           \
        "=r"((r)[28]), "=r"((r)[29]), "=r"((r)[30]), "=r"((r)[31])            \
      : "r"(addr))

#define TST16(addr, r)                                                        \
  asm volatile(                                                               \
      "tcgen05.st.sync.aligned.32x32b.x16.b32 [%0], "                         \
      "{%1, %2, %3, %4, %5, %6, %7, %8, "                                     \
      " %9, %10, %11, %12, %13, %14, %15, %16};"                              \
      :: "r"(addr),                                                           \
         "r"((r)[0]),  "r"((r)[1]),  "r"((r)[2]),  "r"((r)[3]),               \
         "r"((r)[4]),  "r"((r)[5]),  "r"((r)[6]),  "r"((r)[7]),               \
         "r"((r)[8]),  "r"((r)[9]),  "r"((r)[10]), "r"((r)[11]),              \
         "r"((r)[12]), "r"((r)[13]), "r"((r)[14]), "r"((r)[15])               \
      : "memory")

#endif  // HAS_TC

__global__ __launch_bounds__(256, 2)
void hybrid_attn_tc(const float* __restrict__ Q, const float* __restrict__ K,
                    const float* __restrict__ V, float* __restrict__ O) {
#if HAS_TC
  extern __shared__ char smc[];
  const unsigned sb = sm32(smc);
  const int tid = threadIdx.x;
  const int wid = tid >> 5;
  const int lane = tid & 31;
  const int sub = wid & 3;          // TMEM subpartition (SMSP = wid % 4)
  const int half = wid >> 2;        // column half this warp owns (0: cols 0-31, 1: 32-63)
  const int m0 = blockIdx.x * BMt;
  const int bh = blockIdx.y;
  const int base = ((bh >> 3) * Lc * Hc + (bh & 7)) * Ec;
  const float* Qg = Q + base;
  const float* Kg = K + base;
  const float* Vg = V + base;
  float* Og = O + base;

  if (tid == 0) { mbar_init(sb + OFF_MB_S, 1); mbar_init(sb + OFF_MB_O, 1); }
  if (wid == 0) { tc_alloc(sb + OFF_PTR, TM_COLS); tc_relinq(); }
  __syncthreads();
  unsigned tb;
  asm volatile("ld.shared.b32 %0, [%1];" : "=r"(tb) : "r"(sb + OFF_PTR));

  // ---- Q tile -> QH/QL (fp16 split, SW128, 128B rows) ----
  #pragma unroll
  for (int it = 0; it < 8; ++it) {
    const int idx = tid + it * 256;
    const int r = idx >> 4, e4 = (idx & 15) << 2;
    const float4 q = *reinterpret_cast<const float4*>(&Qg[(m0 + r) * RE + e4]);
    float hx, hy, hz, hw, lx, ly, lz, lw;
    split1(q.x, hx, lx); split1(q.y, hy, ly); split1(q.z, hz, lz); split1(q.w, hw, lw);
    const unsigned sw = swzb((unsigned)(r * 128 + e4 * 2));
    *reinterpret_cast<unsigned*>(smc + OFF_QH + sw)     = packh2(hx, hy);
    *reinterpret_cast<unsigned*>(smc + OFF_QH + sw + 4) = packh2(hz, hw);
    *reinterpret_cast<unsigned*>(smc + OFF_QL + sw)     = packh2(lx, ly);
    *reinterpret_cast<unsigned*>(smc + OFF_QL + sw + 4) = packh2(lz, lw);
  }

  unsigned ps = 0, po = 0;
  float lsum = 0.f;                  // partial over this warp's 32 columns
  const unsigned woff = (unsigned)sub << 21;

  for (int nt = 0; nt < NTt; ++nt) {
    const int n0 = nt * BNt;
    const int kb = (nt & 1) ? OFF_K1 : OFF_K0;
    const int vb = (nt & 1) ? OFF_V1 : OFF_V0;

    // ---- load K (natural rows, split) + V (transposed, split) ----
    #pragma unroll
    for (int it = 0; it < 4; ++it) {
      const int idx = tid + it * 256;
      const int j = idx >> 4, e4 = (idx & 15) << 2;
      const float4 kk = *reinterpret_cast<const float4*>(&Kg[(n0 + j) * RE + e4]);
      float hx, hy, hz, hw, lx, ly, lz, lw;
      split1(kk.x, hx, lx); split1(kk.y, hy, ly); split1(kk.z, hz, lz); split1(kk.w, hw, lw);
      const unsigned sw = swzb((unsigned)(j * 128 + e4 * 2));
      *reinterpret_cast<unsigned*>(smc + kb + sw)            = packh2(hx, hy);
      *reinterpret_cast<unsigned*>(smc + kb + sw + 4)        = packh2(hz, hw);
      *reinterpret_cast<unsigned*>(smc + kb + 8192 + sw)     = packh2(lx, ly);
      *reinterpret_cast<unsigned*>(smc + kb + 8192 + sw + 4) = packh2(lz, lw);
      const float4 vv = *reinterpret_cast<const float4*>(&Vg[(n0 + j) * RE + e4]);
      #pragma unroll
      for (int t = 0; t < 4; ++t) {
        const float x = (t == 0) ? vv.x : (t == 1) ? vv.y : (t == 2) ? vv.z : vv.w;
        float h, l;
        split1(x, h, l);
        const unsigned sv = swzb((unsigned)((e4 + t) * 128 + j * 2));
        *reinterpret_cast<__half*>(smc + vb + sv)        = __float2half_rn(h);
        *reinterpret_cast<__half*>(smc + vb + 8192 + sv) = __float2half_rn(l);
      }
    }
    fence_proxy();
    __syncthreads();

    // ---- S = Qh·Kh + Qh·Kl + Ql·Kh ----
    if (wid == 0) {
      if (elect1()) {
        const unsigned long long dqh = mkdesc(sb + OFF_QH), dql = mkdesc(sb + OFF_QL);
        const unsigned long long dkh = mkdesc(sb + kb), dkl = mkdesc(sb + kb + 8192);
        #pragma unroll
        for (int k = 0; k < 4; ++k) mma_ss(tb + TM_S, dqh + 2 * k, dkh + 2 * k, IDESC, k > 0);
        #pragma unroll
        for (int k = 0; k < 4; ++k) mma_ss(tb + TM_S, dqh + 2 * k, dkl + 2 * k, IDESC, true);
        #pragma unroll
        for (int k = 0; k < 4; ++k) mma_ss(tb + TM_S, dql + 2 * k, dkh + 2 * k, IDESC, true);
        tc_commit(sb + OFF_MB_S);
      }
    }
    mbar_wait(sb + OFF_MB_S, ps); ps ^= 1;
    fence_after();

    // ---- epilogue: each warp handles its 32-column half of S ----
    unsigned sr[32];
    TLD32(sr, tb + TM_S + 32 * half);
    wait_ld();
    unsigned ph[16], pl[16];
    #pragma unroll
    for (int c = 0; c < 16; ++c) {
      const float s0 = __uint_as_float(sr[2 * c]);
      const float s1 = __uint_as_float(sr[2 * c + 1]);
      const float p0 = ex2f(fmaf(s0, SCL2E, -PBIAS));
      const float p1 = ex2f(fmaf(s1, SCL2E, -PBIAS));
      lsum += p0 + p1;
      float h0, l0, h1, l1;
      split1(p0, h0, l0); split1(p1, h1, l1);
      ph[c] = packh2(h0, h1);
      pl[c] = packh2(l0, l1);
    }
    if (nt > 0) { mbar_wait(sb + OFF_MB_O, po); po ^= 1; }
    TST16(tb + TM_PH + 16 * half + woff, ph);
    TST16(tb + TM_PL + 16 * half + woff, pl);
    wait_st();
    fence_before();
    __syncthreads();

    // ---- O += Ph·Vh + Ph·Vl + Pl·Vh ----
    if (wid == 0) {
      if (elect1()) {
        fence_after();
        fence_proxy();
        const unsigned long long dvh = mkdesc(sb + vb), dvl = mkdesc(sb + vb + 8192);
        #pragma unroll
        for (int k = 0; k < 4; ++k)
          mma_ts(tb + TM_O, tb + TM_PH + 8 * k, dvh + 2 * k, IDESC, !(nt == 0 && k == 0));
        #pragma unroll
        for (int k = 0; k < 4; ++k)
          mma_ts(tb + TM_O, tb + TM_PH + 8 * k, dvl + 2 * k, IDESC, true);
        #pragma unroll
        for (int k = 0; k < 4; ++k)
          mma_ts(tb + TM_O, tb + TM_PL + 8 * k, dvh + 2 * k, IDESC, true);
        tc_commit(sb + OFF_MB_O);
      }
    }
  }

  mbar_wait(sb + OFF_MB_O, po);
  fence_after();

  // Each warp reads its 32-column half of O for its subpartition rows.
  unsigned orr[32];
  TLD32(orr, tb + TM_O + 32 * half);
  wait_ld();
  fence_before();

  float* Ls = reinterpret_cast<float*>(smc + OFF_LS);
  float* LsumS = reinterpret_cast<float*>(smc + OFF_LSUM);

  // ---- local branch scores: 2 (row, jj) pairs per thread ----
  {
    const int row = tid >> 1;
    const int jb = (tid & 1) << 1;
    #pragma unroll
    for (int t = 0; t < 2; ++t) {
      const int jj = jb + t;
      const int ig = m0 + row;
      const int j = ig - 2 + jj;
      float sc = -1e30f;
      if (j >= 0 && j < Lc) {
        const float* qrow = Qg + ig * RE;
        const float* krow = Kg + j * RE;
        float dot = 0.f;
        #pragma unroll 4
        for (int e4 = 0; e4 < Ec; e4 += 4) {
          const float4 q = *reinterpret_cast<const float4*>(&qrow[e4]);
          const float4 kk = *reinterpret_cast<const float4*>(&krow[e4]);
          dot += q.x * kk.x + q.y * kk.y + q.z * kk.z + q.w * kk.w;
        }
        sc = dot * SCL2E;
      }
      Ls[(row << 2) + jj] = sc;
    }
  }
  // ---- cross-warp lsum combine (two warps per row set) ----
  if (wid < 4) LsumS[sub * 32 + lane] = lsum;
  __syncthreads();
  if (wid >= 4) LsumS[sub * 32 + lane] += lsum;
  __syncthreads();

  // ---- combine global + local, write output (this warp's e-column half) ----
  {
    const int r = sub * 32 + lane;
    const int ig = m0 + r;
    const float4 lsc = *reinterpret_cast<const float4*>(&Ls[r << 2]);
    const float mx = fmaxf(fmaxf(lsc.x, lsc.y), fmaxf(lsc.z, lsc.w));
    const float w0 = ex2f(lsc.x - mx), w1 = ex2f(lsc.y - mx);
    const float w2 = ex2f(lsc.z - mx), w3 = ex2f(lsc.w - mx);
    const float winv = 1.f / (w0 + w1 + w2 + w3);
    const float n0w = w0 * winv, n1w = w1 * winv, n2w = w2 * winv, n3w = w3 * winv;
    const float invl = 1.f / LsumS[r];
    const bool b0 = (ig - 2) >= 0;
    const bool b1 = (ig - 1) >= 0;
    const bool b3 = (ig + 1) < Lc;
    const float* vp0 = Vg + (ig - 2) * RE;
    const float* vp1 = Vg + (ig - 1) * RE;
    const float* vp2 = Vg + ig * RE;
    const float* vp3 = Vg + (ig + 1) * RE;
    const int e0 = 32 * half;
    #pragma unroll
    for (int c4 = 0; c4 < 32; c4 += 4) {
      const int e4 = e0 + c4;
      float4 o;
      o.x = __uint_as_float(orr[c4 + 0]) * invl;
      o.y = __uint_as_float(orr[c4 + 1]) * invl;
      o.z = __uint_as_float(orr[c4 + 2]) * invl;
      o.w = __uint_as_float(orr[c4 + 3]) * invl;
      if (b0) { const float4 vv = *reinterpret_cast<const float4*>(&vp0[e4]);
                o.x += n0w * vv.x; o.y += n0w * vv.y; o.z += n0w * vv.z; o.w += n0w * vv.w; }
      if (b1) { const float4 vv = *reinterpret_cast<const float4*>(&vp1[e4]);
                o.x += n1w * vv.x; o.y += n1w * vv.y; o.z += n1w * vv.z; o.w += n1w * vv.w; }
      {       const float4 vv = *reinterpret_cast<const float4*>(&vp2[e4]);
                o.x += n2w * vv.x; o.y += n2w * vv.y; o.z += n2w * vv.z; o.w += n2w * vv.w; }
      if (b3) { const float4 vv = *reinterpret_cast<const float4*>(&vp3[e4]);
                o.x += n3w * vv.x; o.y += n3w * vv.y; o.z += n3w * vv.z; o.w += n3w * vv.w; }
      *reinterpret_cast<float4*>(&Og[ig * RE + e4]) = o;
    }
  }

  __syncthreads();
  if (wid == 0) tc_dealloc(tb, TM_COLS);
#endif  // HAS_TC
}

// ===================== SIMT fallback (plain sm_103 path) ====================

constexpr int BM = 64, BN = 128;
constexpr int TSQ = 68;
constexpr int TSK = 132;
constexpr int OFF_Q = 0;
constexpr int OFF_KP = OFF_Q + Ec * TSQ;
constexpr int OFF_V = OFF_KP + 64 * TSK;
constexpr int OFF_L = OFF_V + BN * Ec;
constexpr int SMEM_FLOATS = OFF_L + BM * 4;

#if !HAS_TC
__device__ __forceinline__ void fma2(ull& d, ull a, ull b) {
  asm("fma.rn.f32x2 %0, %1, %2, %0;" : "+l"(d) : "l"(a), "l"(b));
}
__device__ __forceinline__ void mul2(ull& d, ull a) {
  asm("mul.rn.f32x2 %0, %0, %1;" : "+l"(d) : "l"(a));
}
__device__ __forceinline__ ull bcast2(float x) {
  ull r; asm("mov.b64 %0, {%1, %1};" : "=l"(r) : "f"(x)); return r;
}
__device__ __forceinline__ void unp2(ull v, float& lo, float& hi) {
  asm("mov.b64 {%0, %1}, %2;" : "=f"(lo), "=f"(hi) : "l"(v));
}
#endif

__global__ __launch_bounds__(128, 2)
void hybrid_attn_simt(const float* __restrict__ Q, const float* __restrict__ K,
                      const float* __restrict__ V, float* __restrict__ O) {
#if !HAS_TC
  extern __shared__ float smf[];
  float* Qs = smf + OFF_Q;
  float* KP = smf + OFF_KP;
  float* Vs = smf + OFF_V;
  float* Ls = smf + OFF_L;

  const int tid = threadIdx.x;
  const int tx = tid & 15;
  const int ty = tid >> 4;
  const int r0 = ty << 3;
  const int c0 = tx << 2;
  const int c1 = 64 + c0;

  const int m0 = blockIdx.x * BM;
  const int bh = blockIdx.y;
  const int base = ((bh >> 3) * Lc * Hc + (bh & 7)) * Ec;
  const float* Qg = Q + base;
  const float* Kg = K + base;
  const float* Vg = V + base;
  float* Og = O + base;

  const int le4 = (tid & 15) << 2;
  const int lr = tid >> 4;

  #pragma unroll
  for (int it = 0; it < 8; ++it) {
    const int r = lr + it * 8;
    const float4 q = *reinterpret_cast<const float4*>(&Qg[(m0 + r) * RE + le4]);
    Qs[(le4 + 0) * TSQ + r] = q.x * SCL2E;
    Qs[(le4 + 1) * TSQ + r] = q.y * SCL2E;
    Qs[(le4 + 2) * TSQ + r] = q.z * SCL2E;
    Qs[(le4 + 3) * TSQ + r] = q.w * SCL2E;
  }

  float mi[8], li[8];
  ull acc[8][2];
  #pragma unroll
  for (int i = 0; i < 8; ++i) { mi[i] = -1e30f; li[i] = 0.f; acc[i][0] = 0ull; acc[i][1] = 0ull; }

  for (int n0 = 0; n0 < Lc; n0 += BN) {
    __syncthreads();
    #pragma unroll
    for (int it = 0; it < 16; ++it) {
      const int r = lr + it * 8;
      const float4 kk = *reinterpret_cast<const float4*>(&Kg[(n0 + r) * RE + le4]);
      KP[(le4 + 0) * TSK + r] = kk.x;
      KP[(le4 + 1) * TSK + r] = kk.y;
      KP[(le4 + 2) * TSK + r] = kk.z;
      KP[(le4 + 3) * TSK + r] = kk.w;
      const float4 vv = *reinterpret_cast<const float4*>(&Vg[(n0 + r) * RE + le4]);
      *reinterpret_cast<float4*>(&Vs[r * Ec + le4]) = vv;
    }
    __syncthreads();

    ull s[8][4];
    #pragma unroll
    for (int i = 0; i < 8; ++i)
      #pragma unroll
      for (int p = 0; p < 4; ++p) s[i][p] = 0ull;

    #pragma unroll 4
    for (int e = 0; e < Ec; ++e) {
      const ulonglong2 b0 = *reinterpret_cast<const ulonglong2*>(&KP[e * TSK + c0]);
      const ulonglong2 b1 = *reinterpret_cast<const ulonglong2*>(&KP[e * TSK + c1]);
      const float4 a0 = *reinterpret_cast<const float4*>(&Qs[e * TSQ + r0]);
      const float4 a1 = *reinterpret_cast<const float4*>(&Qs[e * TSQ + r0 + 4]);
      ull aa;
      aa = bcast2(a0.x); fma2(s[0][0], aa, b0.x); fma2(s[0][1], aa, b0.y); fma2(s[0][2], aa, b1.x); fma2(s[0][3], aa, b1.y);
      aa = bcast2(a0.y); fma2(s[1][0], aa, b0.x); fma2(s[1][1], aa, b0.y); fma2(s[1][2], aa, b1.x); fma2(s[1][3], aa, b1.y);
      aa = bcast2(a0.z); fma2(s[2][0], aa, b0.x); fma2(s[2][1], aa, b0.y); fma2(s[2][2], aa, b1.x); fma2(s[2][3], aa, b1.y);
      aa = bcast2(a0.w); fma2(s[3][0], aa, b0.x); fma2(s[3][1], aa, b0.y); fma2(s[3][2], aa, b1.x); fma2(s[3][3], aa, b1.y);
      aa = bcast2(a1.x); fma2(s[4][0], aa, b0.x); fma2(s[4][1], aa, b0.y); fma2(s[4][2], aa, b1.x); fma2(s[4][3], aa, b1.y);
      aa = bcast2(a1.y); fma2(s[5][0], aa, b0.x); fma2(s[5][1], aa, b0.y); fma2(s[5][2], aa, b1.x); fma2(s[5][3], aa, b1.y);
      aa = bcast2(a1.z); fma2(s[6][0], aa, b0.x); fma2(s[6][1], aa, b0.y); fma2(s[6][2], aa, b1.x); fma2(s[6][3], aa, b1.y);
      aa = bcast2(a1.w); fma2(s[7][0], aa, b0.x); fma2(s[7][1], aa, b0.y); fma2(s[7][2], aa, b1.x); fma2(s[7][3], aa, b1.y);
    }
    __syncthreads();

    #pragma unroll
    for (int i = 0; i < 8; ++i) {
      float v0, v1, v2, v3, v4, v5, v6, v7;
      unp2(s[i][0], v0, v1); unp2(s[i][1], v2, v3);
      unp2(s[i][2], v4, v5); unp2(s[i][3], v6, v7);
      float tm = fmaxf(fmaxf(fmaxf(v0, v1), fmaxf(v2, v3)),
                       fmaxf(fmaxf(v4, v5), fmaxf(v6, v7)));
      #pragma unroll
      for (int off = 8; off; off >>= 1)
        tm = fmaxf(tm, __shfl_xor_sync(0xffffffffu, tm, off));
      const float newm = fmaxf(mi[i], tm);
      const float fac = ex2f(mi[i] - newm);
      v0 = ex2f(v0 - newm); v1 = ex2f(v1 - newm); v2 = ex2f(v2 - newm); v3 = ex2f(v3 - newm);
      v4 = ex2f(v4 - newm); v5 = ex2f(v5 - newm); v6 = ex2f(v6 - newm); v7 = ex2f(v7 - newm);
      float psum = (v0 + v1) + (v2 + v3) + (v4 + v5) + (v6 + v7);
      #pragma unroll
      for (int off = 8; off; off >>= 1)
        psum += __shfl_xor_sync(0xffffffffu, psum, off);
      li[i] = li[i] * fac + psum;
      mi[i] = newm;
      const ull fv = bcast2(fac);
      mul2(acc[i][0], fv); mul2(acc[i][1], fv);
      *reinterpret_cast<float4*>(&KP[(r0 + i) * TSK + c0]) = make_float4(v0, v1, v2, v3);
      *reinterpret_cast<float4*>(&KP[(r0 + i) * TSK + c1]) = make_float4(v4, v5, v6, v7);
    }
    __syncthreads();

    #pragma unroll 2
    for (int j0 = 0; j0 < BN; j0 += 4) {
      const ulonglong2 w0 = *reinterpret_cast<const ulonglong2*>(&Vs[(j0 + 0) * Ec + c0]);
      const ulonglong2 w1 = *reinterpret_cast<const ulonglong2*>(&Vs[(j0 + 1) * Ec + c0]);
      const ulonglong2 w2 = *reinterpret_cast<const ulonglong2*>(&Vs[(j0 + 2) * Ec + c0]);
      const ulonglong2 w3 = *reinterpret_cast<const ulonglong2*>(&Vs[(j0 + 3) * Ec + c0]);
      #pragma unroll
      for (int i = 0; i < 8; ++i) {
        const float4 p = *reinterpret_cast<const float4*>(&KP[(r0 + i) * TSK + j0]);
        ull aa;
        aa = bcast2(p.x); fma2(acc[i][0], aa, w0.x); fma2(acc[i][1], aa, w0.y);
        aa = bcast2(p.y); fma2(acc[i][0], aa, w1.x); fma2(acc[i][1], aa, w1.y);
        aa = bcast2(p.z); fma2(acc[i][0], aa, w2.x); fma2(acc[i][1], aa, w2.y);
        aa = bcast2(p.w); fma2(acc[i][0], aa, w3.x); fma2(acc[i][1], aa, w3.y);
      }
    }
  }

  __syncthreads();
  {
    const int row = tid >> 1;
    const int jbase = (tid & 1) << 1;
    #pragma unroll
    for (int t = 0; t < 2; ++t) {
      const int jj = jbase + t;
      const int ig = m0 + row;
      const int j = ig - 2 + jj;
      float sc = -1e30f;
      if (j >= 0 && j < Lc) {
        float dot = 0.f;
        #pragma unroll
        for (int e4 = 0; e4 < Ec; e4 += 4) {
          const float4 kk = *reinterpret_cast<const float4*>(&Kg[j * RE + e4]);
          dot += Qs[(e4 + 0) * TSQ + row] * kk.x
               + Qs[(e4 + 1) * TSQ + row] * kk.y
               + Qs[(e4 + 2) * TSQ + row] * kk.z
               + Qs[(e4 + 3) * TSQ + row] * kk.w;
        }
        sc = dot;
      }
      Ls[(row << 2) + jj] = sc;
    }
  }
  __syncthreads();

  #pragma unroll
  for (int i = 0; i < 8; ++i) {
    const int r = r0 + i;
    const int ig = m0 + r;
    const float4 lsc = *reinterpret_cast<const float4*>(&Ls[r << 2]);
    const float mx = fmaxf(fmaxf(lsc.x, lsc.y), fmaxf(lsc.z, lsc.w));
    float w[4];
    w[0] = ex2f(lsc.x - mx); w[1] = ex2f(lsc.y - mx);
    w[2] = ex2f(lsc.z - mx); w[3] = ex2f(lsc.w - mx);
    const float winv = 1.f / (w[0] + w[1] + w[2] + w[3]);
    const float invl = 1.f / li[i];
    float o0, o1, o2, o3;
    unp2(acc[i][0], o0, o1); unp2(acc[i][1], o2, o3);
    float4 outv = make_float4(o0 * invl, o1 * invl, o2 * invl, o3 * invl);
    #pragma unroll
    for (int jj = 0; jj < 4; ++jj) {
      const int j = ig - 2 + jj;
      if (j >= 0 && j < Lc) {
        const float wj = w[jj] * winv;
        const float4 v = *reinterpret_cast<const float4*>(&Vg[j * RE + c0]);
        outv.x += wj * v.x; outv.y += wj * v.y;
        outv.z += wj * v.z; outv.w += wj * v.w;
      }
    }
    *reinterpret_cast<float4*>(&Og[ig * RE + c0]) = outv;
  }
#endif  // !HAS_TC
}

}  // namespace

extern "C" void kernel_launch(void* const* d_in, const int* in_sizes, int n_in,
                              void* d_out, int out_size) {
  const float* Q = (const float*)d_in[0];
  const float* K = (const float*)d_in[1];
  const float* V = (const float*)d_in[2];
  float* O = (float*)d_out;

  cudaFuncSetAttribute(hybrid_attn_tc, cudaFuncAttributeMaxDynamicSharedMemorySize, SMEM_TC);
  const size_t smemS = (size_t)SMEM_FLOATS * sizeof(float);
  cudaFuncSetAttribute(hybrid_attn_simt, cudaFuncAttributeMaxDynamicSharedMemorySize, (int)smemS);

  dim3 gridTC(Lc / BMt, 4 * Hc);
  hybrid_attn_tc<<<gridTC, 256, SMEM_TC>>>(Q, K, V, O);
  dim3 gridS(Lc / BM, 4 * Hc);
  hybrid_attn_simt<<<gridS, 128, smemS>>>(Q, K, V, O);
}

// round 10
// speedup vs baseline: 3.3905x; 1.0254x over previous
#include <cuda_runtime.h>
#include <cuda_fp16.h>
#include <cstdint>

// tcgen05 is only legal on arch-specific (sm_103a/sm_100a) device passes.
#if defined(__CUDA_ARCH_FEAT_SM103_ALL) || defined(__CUDA_ARCH_FEAT_SM100_ALL) || \
    defined(__CUDA_ARCH_FEAT_SM101_ALL) ||                                        \
    (defined(__CUDA_ARCH_SPECIFIC__) && (__CUDA_ARCH_SPECIFIC__ >= 1000)) ||       \
    (defined(__CUDA_ARCH_FAMILY_SPECIFIC__) && (__CUDA_ARCH_FAMILY_SPECIFIC__ >= 1000))
#define HAS_TC 1
#else
#define HAS_TC 0
#endif

namespace {

using ull = unsigned long long;

constexpr int Lc = 2048, Hc = 8, Ec = 64;
constexpr int RE = Hc * Ec;                  // 512
constexpr float SCL2E = 0.125f * 1.44269504088896340736f;

__device__ __forceinline__ float ex2f(float x) {
  float y; asm("ex2.approx.ftz.f32 %0, %1;" : "=f"(y) : "f"(x)); return y;
}

// ======================= TC kernel (sm_103a path) ==========================

constexpr int BMt = 128, BNt = 64;
constexpr int NTt = Lc / BNt;                // 32 key tiles
constexpr float PBIAS = 4.0f;
constexpr unsigned IDESC = 0x08100010u;      // kind::f16: F32 acc, f16 a/b, M=128, N=64

// TMEM: S double-buffered
constexpr unsigned TM_S0 = 0, TM_S1 = 64, TM_O = 128, TM_PH = 192, TM_PL = 224;
constexpr unsigned TM_COLS = 256;

constexpr int OFF_PTR = 0, OFF_MB_S0 = 8, OFF_MB_S1 = 16, OFF_MB_O = 24;
constexpr int OFF_QH = 1024;
constexpr int OFF_QL = OFF_QH + 16384;
constexpr int OFF_K0 = OFF_QL + 16384;       // KH @ +0, KL @ +8192 (64 rows x 128B)
constexpr int OFF_K1 = OFF_K0 + 16384;
constexpr int OFF_V0 = OFF_K1 + 16384;       // VHt @ +0, VLt @ +8192 (e-major transposed)
constexpr int OFF_V1 = OFF_V0 + 16384;
constexpr int OFF_LS = OFF_V1 + 16384;       // float Ls[128][4] local scores
constexpr int OFF_LSUM = OFF_LS + 2048;      // float Lsum[128]
constexpr int SMEM_TC = OFF_LSUM + 512;      // 101888 B

#if HAS_TC

// K-major SW128 descriptor: LBO=1, SBO=64
constexpr unsigned long long DESC_BASE =
    (2ull << 61) | (1ull << 46) | (64ull << 32) | (1ull << 16);

__device__ __forceinline__ unsigned sm32(const void* p) {
  unsigned a;
  asm("{ .reg .u64 t; cvta.to.shared.u64 t, %1; cvt.u32.u64 %0, t; }" : "=r"(a) : "l"(p));
  return a;
}
__device__ __forceinline__ unsigned long long mkdesc(unsigned addr) {
  return DESC_BASE | ((unsigned long long)(addr >> 4) & 0x3FFF);
}
__device__ __forceinline__ unsigned swzb(unsigned off) { return off ^ ((off >> 3) & 0x70); }
__device__ __forceinline__ unsigned packh2(float a, float b) {
  __half2 t = __floats2half2_rn(a, b);
  return reinterpret_cast<unsigned&>(t);
}
__device__ __forceinline__ void split1(float x, float& h, float& l) {
  __half b = __float2half_rn(x);
  h = __half2float(b);
  l = x - h;
}
__device__ __forceinline__ unsigned elect1() {
  unsigned p;
  asm volatile("{\n\t.reg .pred p;\n\telect.sync _|p, 0xFFFFFFFF;\n\tselp.b32 %0, 1, 0, p;\n\t}" : "=r"(p));
  return p;
}
__device__ __forceinline__ void mbar_init(unsigned mbar, unsigned cnt) {
  asm volatile("mbarrier.init.shared.b64 [%0], %1;" :: "r"(mbar), "r"(cnt) : "memory");
}
__device__ __forceinline__ void mbar_wait(unsigned mbar, unsigned parity) {
  asm volatile(
      "{\n\t.reg .pred P1;\n\t"
      "LWAIT_%=:\n\t"
      "mbarrier.try_wait.parity.acquire.cta.shared::cta.b64 P1, [%0], %1, 0x989680;\n\t"
      "@P1 bra.uni LDONE_%=;\n\t"
      "bra.uni LWAIT_%=;\n\t"
      "LDONE_%=:\n\t}"
      :: "r"(mbar), "r"(parity) : "memory");
}
__device__ __forceinline__ void tc_commit(unsigned mbar) {
  asm volatile(
      "tcgen05.commit.cta_group::1.mbarrier::arrive::one.shared::cluster.b64 [%0];"
      :: "r"(mbar) : "memory");
}
__device__ __forceinline__ void tc_alloc(unsigned dst, unsigned ncols) {
  asm volatile("tcgen05.alloc.cta_group::1.sync.aligned.shared::cta.b32 [%0], %1;"
               :: "r"(dst), "r"(ncols) : "memory");
}
__device__ __forceinline__ void tc_relinq() {
  asm volatile("tcgen05.relinquish_alloc_permit.cta_group::1.sync.aligned;");
}
__device__ __forceinline__ void tc_dealloc(unsigned base, unsigned ncols) {
  asm volatile("tcgen05.dealloc.cta_group::1.sync.aligned.b32 %0, %1;" :: "r"(base), "r"(ncols));
}
__device__ __forceinline__ void fence_before() {
  asm volatile("tcgen05.fence::before_thread_sync;" ::: "memory");
}
__device__ __forceinline__ void fence_after() {
  asm volatile("tcgen05.fence::after_thread_sync;" ::: "memory");
}
__device__ __forceinline__ void fence_proxy() {
  asm volatile("fence.proxy.async.shared::cta;" ::: "memory");
}
__device__ __forceinline__ void wait_ld() { asm volatile("tcgen05.wait::ld.sync.aligned;" ::: "memory"); }
__device__ __forceinline__ void wait_st() { asm volatile("tcgen05.wait::st.sync.aligned;" ::: "memory"); }

__device__ __forceinline__ void mma_ss(unsigned d, unsigned long long ad,
                                       unsigned long long bd, unsigned idesc, bool en) {
  unsigned e = en ? 1u : 0u;
  asm volatile(
      "{\n\t.reg .pred p;\n\tsetp.ne.u32 p, %5, 0;\n\t"
      "tcgen05.mma.cta_group::1.kind::f16 [%0], %1, %2, %3, {%4, %4, %4, %4}, p;\n\t}"
      :: "r"(d), "l"(ad), "l"(bd), "r"(idesc), "r"(0u), "r"(e) : "memory");
}
__device__ __forceinline__ void mma_ts(unsigned d, unsigned a,
                                       unsigned long long bd, unsigned idesc, bool en) {
  unsigned e = en ? 1u : 0u;
  asm volatile(
      "{\n\t.reg .pred p;\n\tsetp.ne.u32 p, %5, 0;\n\t"
      "tcgen05.mma.cta_group::1.kind::f16 [%0], [%1], %2, %3, {%4, %4, %4, %4}, p;\n\t}"
      :: "r"(d), "r"(a), "l"(bd), "r"(idesc), "r"(0u), "r"(e) : "memory");
}

#define TLD32(r, addr)                                                        \
  asm volatile(                                                               \
      "tcgen05.ld.sync.aligned.32x32b.x32.b32 "                               \
      "{%0, %1, %2, %3, %4, %5, %6, %7, "                                     \
      " %8, %9, %10, %11, %12, %13, %14, %15, "                               \
      " %16, %17, %18, %19, %20, %21, %22, %23, "                             \
      " %24, %25, %26, %27, %28, %29, %30, %31}, [%32];"                      \
      : "=r"((r)[0]),  "=r"((r)[1]),  "=r"((r)[2]),  "=r"((r)[3]),            \
        "=r"((r)[4]),  "=r"((r)[5]),  "=r"((r)[6]),  "=r"((r)[7]),            \
        "=r"((r)[8]),  "=r"((r)[9]),  "=r"((r)[10]), "=r"((r)[11]),           \
        "=r"((r)[12]), "=r"((r)[13]), "=r"((r)[14]), "=r"((r)[15]),           \
        "=r"((r)[16]), "=r"((r)[17]), "=r"((r)[18]), "=r"((r)[19]),           \
        "=r"((r)[20]), "=r"((r)[21]), "=r"((r)[22]), "=r"((r)[23]),           \
        "=r"((r)[24]), "=r"((r)[25]), "=r"((r)[26]), "=r"((r)[27]),           \
        "=r"((r)[28]), "=r"((r)[29]), "=r"((r)[30]), "=r"((r)[31])            \
      : "r"(addr))

#define TST16(addr, r)                                                        \
  asm volatile(                                                               \
      "tcgen05.st.sync.aligned.32x32b.x16.b32 [%0], "                         \
      "{%1, %2, %3, %4, %5, %6, %7, %8, "                                     \
      " %9, %10, %11, %12, %13, %14, %15, %16};"                              \
      :: "r"(addr),                                                           \
         "r"((r)[0]),  "r"((r)[1]),  "r"((r)[2]),  "r"((r)[3]),               \
         "r"((r)[4]),  "r"((r)[5]),  "r"((r)[6]),  "r"((r)[7]),               \
         "r"((r)[8]),  "r"((r)[9]),  "r"((r)[10]), "r"((r)[11]),              \
         "r"((r)[12]), "r"((r)[13]), "r"((r)[14]), "r"((r)[15])               \
      : "memory")

#endif  // HAS_TC

__global__ __launch_bounds__(256, 2)
void hybrid_attn_tc(const float* __restrict__ Q, const float* __restrict__ K,
                    const float* __restrict__ V, float* __restrict__ O) {
#if HAS_TC
  extern __shared__ char smc[];
  const unsigned sb = sm32(smc);
  const int tid = threadIdx.x;
  const int wid = tid >> 5;
  const int lane = tid & 31;
  const int sub = wid & 3;          // TMEM subpartition (SMSP = wid % 4)
  const int half = wid >> 2;        // column half this warp owns
  const int m0 = blockIdx.x * BMt;
  const int bh = blockIdx.y;
  const int base = ((bh >> 3) * Lc * Hc + (bh & 7)) * Ec;
  const float* Qg = Q + base;
  const float* Kg = K + base;
  const float* Vg = V + base;
  float* Og = O + base;

  if (tid == 0) {
    mbar_init(sb + OFF_MB_S0, 1);
    mbar_init(sb + OFF_MB_S1, 1);
    mbar_init(sb + OFF_MB_O, 1);
  }
  if (wid == 0) { tc_alloc(sb + OFF_PTR, TM_COLS); tc_relinq(); }
  __syncthreads();
  unsigned tb;
  asm volatile("ld.shared.b32 %0, [%1];" : "=r"(tb) : "r"(sb + OFF_PTR));

  const unsigned long long dqh = mkdesc(sb + OFF_QH), dql = mkdesc(sb + OFF_QL);

  // ---- Q tile -> QH/QL (fp16 split, SW128, 128B rows) ----
  #pragma unroll
  for (int it = 0; it < 8; ++it) {
    const int idx = tid + it * 256;
    const int r = idx >> 4, e4 = (idx & 15) << 2;
    const float4 q = *reinterpret_cast<const float4*>(&Qg[(m0 + r) * RE + e4]);
    float hx, hy, hz, hw, lx, ly, lz, lw;
    split1(q.x, hx, lx); split1(q.y, hy, ly); split1(q.z, hz, lz); split1(q.w, hw, lw);
    const unsigned sw = swzb((unsigned)(r * 128 + e4 * 2));
    *reinterpret_cast<unsigned*>(smc + OFF_QH + sw)     = packh2(hx, hy);
    *reinterpret_cast<unsigned*>(smc + OFF_QH + sw + 4) = packh2(hz, hw);
    *reinterpret_cast<unsigned*>(smc + OFF_QL + sw)     = packh2(lx, ly);
    *reinterpret_cast<unsigned*>(smc + OFF_QL + sw + 4) = packh2(lz, lw);
  }

  // ---- K/V tile 0 ----
  #pragma unroll
  for (int it = 0; it < 4; ++it) {
    const int idx = tid + it * 256;
    const int j = idx >> 4, e4 = (idx & 15) << 2;
    const float4 kk = *reinterpret_cast<const float4*>(&Kg[j * RE + e4]);
    float hx, hy, hz, hw, lx, ly, lz, lw;
    split1(kk.x, hx, lx); split1(kk.y, hy, ly); split1(kk.z, hz, lz); split1(kk.w, hw, lw);
    const unsigned sw = swzb((unsigned)(j * 128 + e4 * 2));
    *reinterpret_cast<unsigned*>(smc + OFF_K0 + sw)            = packh2(hx, hy);
    *reinterpret_cast<unsigned*>(smc + OFF_K0 + sw + 4)        = packh2(hz, hw);
    *reinterpret_cast<unsigned*>(smc + OFF_K0 + 8192 + sw)     = packh2(lx, ly);
    *reinterpret_cast<unsigned*>(smc + OFF_K0 + 8192 + sw + 4) = packh2(lz, lw);
    const float4 vv = *reinterpret_cast<const float4*>(&Vg[j * RE + e4]);
    #pragma unroll
    for (int t = 0; t < 4; ++t) {
      const float x = (t == 0) ? vv.x : (t == 1) ? vv.y : (t == 2) ? vv.z : vv.w;
      float h, l;
      split1(x, h, l);
      const unsigned sv = swzb((unsigned)((e4 + t) * 128 + j * 2));
      *reinterpret_cast<__half*>(smc + OFF_V0 + sv)        = __float2half_rn(h);
      *reinterpret_cast<__half*>(smc + OFF_V0 + 8192 + sv) = __float2half_rn(l);
    }
  }
  fence_proxy();
  __syncthreads();

  // ---- S-MMA(0) -> S0, commit MB_S0 ----
  if (wid == 0 && elect1()) {
    const unsigned long long dkh = mkdesc(sb + OFF_K0), dkl = mkdesc(sb + OFF_K0 + 8192);
    #pragma unroll
    for (int k = 0; k < 4; ++k) mma_ss(tb + TM_S0, dqh + 2 * k, dkh + 2 * k, IDESC, k > 0);
    #pragma unroll
    for (int k = 0; k < 4; ++k) mma_ss(tb + TM_S0, dqh + 2 * k, dkl + 2 * k, IDESC, true);
    #pragma unroll
    for (int k = 0; k < 4; ++k) mma_ss(tb + TM_S0, dql + 2 * k, dkh + 2 * k, IDESC, true);
    tc_commit(sb + OFF_MB_S0);
  }

  unsigned ps[2] = {0u, 0u};
  unsigned po = 0;
  float lsum = 0.f;
  const unsigned woff = (unsigned)sub << 21;

  for (int nt = 0; nt < NTt; ++nt) {
    const int kb = (nt & 1) ? OFF_K1 : OFF_K0;
    const int vb = (nt & 1) ? OFF_V1 : OFF_V0;
    const int kb2 = (nt & 1) ? OFF_K0 : OFF_K1;
    const int vb2 = (nt & 1) ? OFF_V0 : OFF_V1;

    // ---- load K(nt+1) (reader S(nt-1) finished: waited at iter nt-1) ----
    if (nt + 1 < NTt) {
      const int n0 = (nt + 1) * BNt;
      #pragma unroll
      for (int it = 0; it < 4; ++it) {
        const int idx = tid + it * 256;
        const int j = idx >> 4, e4 = (idx & 15) << 2;
        const float4 kk = *reinterpret_cast<const float4*>(&Kg[(n0 + j) * RE + e4]);
        float hx, hy, hz, hw, lx, ly, lz, lw;
        split1(kk.x, hx, lx); split1(kk.y, hy, ly); split1(kk.z, hz, lz); split1(kk.w, hw, lw);
        const unsigned sw = swzb((unsigned)(j * 128 + e4 * 2));
        *reinterpret_cast<unsigned*>(smc + kb2 + sw)            = packh2(hx, hy);
        *reinterpret_cast<unsigned*>(smc + kb2 + sw + 4)        = packh2(hz, hw);
        *reinterpret_cast<unsigned*>(smc + kb2 + 8192 + sw)     = packh2(lx, ly);
        *reinterpret_cast<unsigned*>(smc + kb2 + 8192 + sw + 4) = packh2(lz, lw);
      }
    }

    // ---- O(nt-1) must finish before overwriting its V buffer / P / issuing TST ----
    if (nt > 0) { mbar_wait(sb + OFF_MB_O, po); po ^= 1; }

    // ---- load V(nt+1) ----
    if (nt + 1 < NTt) {
      const int n0 = (nt + 1) * BNt;
      #pragma unroll
      for (int it = 0; it < 4; ++it) {
        const int idx = tid + it * 256;
        const int j = idx >> 4, e4 = (idx & 15) << 2;
        const float4 vv = *reinterpret_cast<const float4*>(&Vg[(n0 + j) * RE + e4]);
        #pragma unroll
        for (int t = 0; t < 4; ++t) {
          const float x = (t == 0) ? vv.x : (t == 1) ? vv.y : (t == 2) ? vv.z : vv.w;
          float h, l;
          split1(x, h, l);
          const unsigned sv = swzb((unsigned)((e4 + t) * 128 + j * 2));
          *reinterpret_cast<__half*>(smc + vb2 + sv)        = __float2half_rn(h);
          *reinterpret_cast<__half*>(smc + vb2 + 8192 + sv) = __float2half_rn(l);
        }
      }
    }
    fence_proxy();
    __syncthreads();

    // ---- issue S-MMA(nt+1) into the other S buffer (overlaps epilogue) ----
    if (nt + 1 < NTt && wid == 0 && elect1()) {
      const unsigned sdst = ((nt + 1) & 1) ? TM_S1 : TM_S0;
      const unsigned smb = ((nt + 1) & 1) ? (sb + OFF_MB_S1) : (sb + OFF_MB_S0);
      const unsigned long long dkh = mkdesc(sb + kb2), dkl = mkdesc(sb + kb2 + 8192);
      #pragma unroll
      for (int k = 0; k < 4; ++k) mma_ss(tb + sdst, dqh + 2 * k, dkh + 2 * k, IDESC, k > 0);
      #pragma unroll
      for (int k = 0; k < 4; ++k) mma_ss(tb + sdst, dqh + 2 * k, dkl + 2 * k, IDESC, true);
      #pragma unroll
      for (int k = 0; k < 4; ++k) mma_ss(tb + sdst, dql + 2 * k, dkh + 2 * k, IDESC, true);
      tc_commit(smb);
    }

    // ---- wait S(nt) (usually already complete) ----
    {
      const unsigned smb = (nt & 1) ? (sb + OFF_MB_S1) : (sb + OFF_MB_S0);
      mbar_wait(smb, ps[nt & 1]);
      ps[nt & 1] ^= 1;
    }
    fence_after();

    // ---- epilogue: each warp handles its 32-column half of S(nt) ----
    const unsigned ssrc = (nt & 1) ? TM_S1 : TM_S0;
    unsigned sr[32];
    TLD32(sr, tb + ssrc + 32 * half);
    wait_ld();
    unsigned ph[16], pl[16];
    #pragma unroll
    for (int c = 0; c < 16; ++c) {
      const float s0 = __uint_as_float(sr[2 * c]);
      const float s1 = __uint_as_float(sr[2 * c + 1]);
      const float p0 = ex2f(fmaf(s0, SCL2E, -PBIAS));
      const float p1 = ex2f(fmaf(s1, SCL2E, -PBIAS));
      lsum += p0 + p1;
      float h0, l0, h1, l1;
      split1(p0, h0, l0); split1(p1, h1, l1);
      ph[c] = packh2(h0, h1);
      pl[c] = packh2(l0, l1);
    }
    TST16(tb + TM_PH + 16 * half + woff, ph);
    TST16(tb + TM_PL + 16 * half + woff, pl);
    wait_st();
    fence_before();
    __syncthreads();

    // ---- O += Ph·Vh + Ph·Vl + Pl·Vh (reads vb(nt)) ----
    if (wid == 0 && elect1()) {
      fence_after();
      fence_proxy();
      const unsigned long long dvh = mkdesc(sb + vb), dvl = mkdesc(sb + vb + 8192);
      #pragma unroll
      for (int k = 0; k < 4; ++k)
        mma_ts(tb + TM_O, tb + TM_PH + 8 * k, dvh + 2 * k, IDESC, !(nt == 0 && k == 0));
      #pragma unroll
      for (int k = 0; k < 4; ++k)
        mma_ts(tb + TM_O, tb + TM_PH + 8 * k, dvl + 2 * k, IDESC, true);
      #pragma unroll
      for (int k = 0; k < 4; ++k)
        mma_ts(tb + TM_O, tb + TM_PL + 8 * k, dvh + 2 * k, IDESC, true);
      tc_commit(sb + OFF_MB_O);
    }
  }

  mbar_wait(sb + OFF_MB_O, po);
  fence_after();

  // Each warp reads its 32-column half of O for its subpartition rows.
  unsigned orr[32];
  TLD32(orr, tb + TM_O + 32 * half);
  wait_ld();
  fence_before();

  float* Ls = reinterpret_cast<float*>(smc + OFF_LS);
  float* LsumS = reinterpret_cast<float*>(smc + OFF_LSUM);

  // ---- local branch scores: 2 (row, jj) pairs per thread ----
  {
    const int row = tid >> 1;
    const int jb = (tid & 1) << 1;
    #pragma unroll
    for (int t = 0; t < 2; ++t) {
      const int jj = jb + t;
      const int ig = m0 + row;
      const int j = ig - 2 + jj;
      float sc = -1e30f;
      if (j >= 0 && j < Lc) {
        const float* qrow = Qg + ig * RE;
        const float* krow = Kg + j * RE;
        float dot = 0.f;
        #pragma unroll 4
        for (int e4 = 0; e4 < Ec; e4 += 4) {
          const float4 q = *reinterpret_cast<const float4*>(&qrow[e4]);
          const float4 kk = *reinterpret_cast<const float4*>(&krow[e4]);
          dot += q.x * kk.x + q.y * kk.y + q.z * kk.z + q.w * kk.w;
        }
        sc = dot * SCL2E;
      }
      Ls[(row << 2) + jj] = sc;
    }
  }
  // ---- cross-warp lsum combine ----
  if (wid < 4) LsumS[sub * 32 + lane] = lsum;
  __syncthreads();
  if (wid >= 4) LsumS[sub * 32 + lane] += lsum;
  __syncthreads();

  // ---- combine global + local, write output (this warp's e-column half) ----
  {
    const int r = sub * 32 + lane;
    const int ig = m0 + r;
    const float4 lsc = *reinterpret_cast<const float4*>(&Ls[r << 2]);
    const float mx = fmaxf(fmaxf(lsc.x, lsc.y), fmaxf(lsc.z, lsc.w));
    const float w0 = ex2f(lsc.x - mx), w1 = ex2f(lsc.y - mx);
    const float w2 = ex2f(lsc.z - mx), w3 = ex2f(lsc.w - mx);
    const float winv = 1.f / (w0 + w1 + w2 + w3);
    const float n0w = w0 * winv, n1w = w1 * winv, n2w = w2 * winv, n3w = w3 * winv;
    const float invl = 1.f / LsumS[r];
    const bool b0 = (ig - 2) >= 0;
    const bool b1 = (ig - 1) >= 0;
    const bool b3 = (ig + 1) < Lc;
    const float* vp0 = Vg + (ig - 2) * RE;
    const float* vp1 = Vg + (ig - 1) * RE;
    const float* vp2 = Vg + ig * RE;
    const float* vp3 = Vg + (ig + 1) * RE;
    const int e0 = 32 * half;
    #pragma unroll
    for (int c4 = 0; c4 < 32; c4 += 4) {
      const int e4 = e0 + c4;
      float4 o;
      o.x = __uint_as_float(orr[c4 + 0]) * invl;
      o.y = __uint_as_float(orr[c4 + 1]) * invl;
      o.z = __uint_as_float(orr[c4 + 2]) * invl;
      o.w = __uint_as_float(orr[c4 + 3]) * invl;
      if (b0) { const float4 vv = *reinterpret_cast<const float4*>(&vp0[e4]);
                o.x += n0w * vv.x; o.y += n0w * vv.y; o.z += n0w * vv.z; o.w += n0w * vv.w; }
      if (b1) { const float4 vv = *reinterpret_cast<const float4*>(&vp1[e4]);
                o.x += n1w * vv.x; o.y += n1w * vv.y; o.z += n1w * vv.z; o.w += n1w * vv.w; }
      {       const float4 vv = *reinterpret_cast<const float4*>(&vp2[e4]);
                o.x += n2w * vv.x; o.y += n2w * vv.y; o.z += n2w * vv.z; o.w += n2w * vv.w; }
      if (b3) { const float4 vv = *reinterpret_cast<const float4*>(&vp3[e4]);
                o.x += n3w * vv.x; o.y += n3w * vv.y; o.z += n3w * vv.z; o.w += n3w * vv.w; }
      *reinterpret_cast<float4*>(&Og[ig * RE + e4]) = o;
    }
  }

  __syncthreads();
  if (wid == 0) tc_dealloc(tb, TM_COLS);
#endif  // HAS_TC
}

// ===================== SIMT fallback (plain sm_103 path) ====================

constexpr int BM = 64, BN = 128;
constexpr int TSQ = 68;
constexpr int TSK = 132;
constexpr int OFF_Q = 0;
constexpr int OFF_KP = OFF_Q + Ec * TSQ;
constexpr int OFF_V = OFF_KP + 64 * TSK;
constexpr int OFF_L = OFF_V + BN * Ec;
constexpr int SMEM_FLOATS = OFF_L + BM * 4;

#if !HAS_TC
__device__ __forceinline__ void fma2(ull& d, ull a, ull b) {
  asm("fma.rn.f32x2 %0, %1, %2, %0;" : "+l"(d) : "l"(a), "l"(b));
}
__device__ __forceinline__ void mul2(ull& d, ull a) {
  asm("mul.rn.f32x2 %0, %0, %1;" : "+l"(d) : "l"(a));
}
__device__ __forceinline__ ull bcast2(float x) {
  ull r; asm("mov.b64 %0, {%1, %1};" : "=l"(r) : "f"(x)); return r;
}
__device__ __forceinline__ void unp2(ull v, float& lo, float& hi) {
  asm("mov.b64 {%0, %1}, %2;" : "=f"(lo), "=f"(hi) : "l"(v));
}
#endif

__global__ __launch_bounds__(128, 2)
void hybrid_attn_simt(const float* __restrict__ Q, const float* __restrict__ K,
                      const float* __restrict__ V, float* __restrict__ O) {
#if !HAS_TC
  extern __shared__ float smf[];
  float* Qs = smf + OFF_Q;
  float* KP = smf + OFF_KP;
  float* Vs = smf + OFF_V;
  float* Ls = smf + OFF_L;

  const int tid = threadIdx.x;
  const int tx = tid & 15;
  const int ty = tid >> 4;
  const int r0 = ty << 3;
  const int c0 = tx << 2;
  const int c1 = 64 + c0;

  const int m0 = blockIdx.x * BM;
  const int bh = blockIdx.y;
  const int base = ((bh >> 3) * Lc * Hc + (bh & 7)) * Ec;
  const float* Qg = Q + base;
  const float* Kg = K + base;
  const float* Vg = V + base;
  float* Og = O + base;

  const int le4 = (tid & 15) << 2;
  const int lr = tid >> 4;

  #pragma unroll
  for (int it = 0; it < 8; ++it) {
    const int r = lr + it * 8;
    const float4 q = *reinterpret_cast<const float4*>(&Qg[(m0 + r) * RE + le4]);
    Qs[(le4 + 0) * TSQ + r] = q.x * SCL2E;
    Qs[(le4 + 1) * TSQ + r] = q.y * SCL2E;
    Qs[(le4 + 2) * TSQ + r] = q.z * SCL2E;
    Qs[(le4 + 3) * TSQ + r] = q.w * SCL2E;
  }

  float mi[8], li[8];
  ull acc[8][2];
  #pragma unroll
  for (int i = 0; i < 8; ++i) { mi[i] = -1e30f; li[i] = 0.f; acc[i][0] = 0ull; acc[i][1] = 0ull; }

  for (int n0 = 0; n0 < Lc; n0 += BN) {
    __syncthreads();
    #pragma unroll
    for (int it = 0; it < 16; ++it) {
      const int r = lr + it * 8;
      const float4 kk = *reinterpret_cast<const float4*>(&Kg[(n0 + r) * RE + le4]);
      KP[(le4 + 0) * TSK + r] = kk.x;
      KP[(le4 + 1) * TSK + r] = kk.y;
      KP[(le4 + 2) * TSK + r] = kk.z;
      KP[(le4 + 3) * TSK + r] = kk.w;
      const float4 vv = *reinterpret_cast<const float4*>(&Vg[(n0 + r) * RE + le4]);
      *reinterpret_cast<float4*>(&Vs[r * Ec + le4]) = vv;
    }
    __syncthreads();

    ull s[8][4];
    #pragma unroll
    for (int i = 0; i < 8; ++i)
      #pragma unroll
      for (int p = 0; p < 4; ++p) s[i][p] = 0ull;

    #pragma unroll 4
    for (int e = 0; e < Ec; ++e) {
      const ulonglong2 b0 = *reinterpret_cast<const ulonglong2*>(&KP[e * TSK + c0]);
      const ulonglong2 b1 = *reinterpret_cast<const ulonglong2*>(&KP[e * TSK + c1]);
      const float4 a0 = *reinterpret_cast<const float4*>(&Qs[e * TSQ + r0]);
      const float4 a1 = *reinterpret_cast<const float4*>(&Qs[e * TSQ + r0 + 4]);
      ull aa;
      aa = bcast2(a0.x); fma2(s[0][0], aa, b0.x); fma2(s[0][1], aa, b0.y); fma2(s[0][2], aa, b1.x); fma2(s[0][3], aa, b1.y);
      aa = bcast2(a0.y); fma2(s[1][0], aa, b0.x); fma2(s[1][1], aa, b0.y); fma2(s[1][2], aa, b1.x); fma2(s[1][3], aa, b1.y);
      aa = bcast2(a0.z); fma2(s[2][0], aa, b0.x); fma2(s[2][1], aa, b0.y); fma2(s[2][2], aa, b1.x); fma2(s[2][3], aa, b1.y);
      aa = bcast2(a0.w); fma2(s[3][0], aa, b0.x); fma2(s[3][1], aa, b0.y); fma2(s[3][2], aa, b1.x); fma2(s[3][3], aa, b1.y);
      aa = bcast2(a1.x); fma2(s[4][0], aa, b0.x); fma2(s[4][1], aa, b0.y); fma2(s[4][2], aa, b1.x); fma2(s[4][3], aa, b1.y);
      aa = bcast2(a1.y); fma2(s[5][0], aa, b0.x); fma2(s[5][1], aa, b0.y); fma2(s[5][2], aa, b1.x); fma2(s[5][3], aa, b1.y);
      aa = bcast2(a1.z); fma2(s[6][0], aa, b0.x); fma2(s[6][1], aa, b0.y); fma2(s[6][2], aa, b1.x); fma2(s[6][3], aa, b1.y);
      aa = bcast2(a1.w); fma2(s[7][0], aa, b0.x); fma2(s[7][1], aa, b0.y); fma2(s[7][2], aa, b1.x); fma2(s[7][3], aa, b1.y);
    }
    __syncthreads();

    #pragma unroll
    for (int i = 0; i < 8; ++i) {
      float v0, v1, v2, v3, v4, v5, v6, v7;
      unp2(s[i][0], v0, v1); unp2(s[i][1], v2, v3);
      unp2(s[i][2], v4, v5); unp2(s[i][3], v6, v7);
      float tm = fmaxf(fmaxf(fmaxf(v0, v1), fmaxf(v2, v3)),
                       fmaxf(fmaxf(v4, v5), fmaxf(v6, v7)));
      #pragma unroll
      for (int off = 8; off; off >>= 1)
        tm = fmaxf(tm, __shfl_xor_sync(0xffffffffu, tm, off));
      const float newm = fmaxf(mi[i], tm);
      const float fac = ex2f(mi[i] - newm);
      v0 = ex2f(v0 - newm); v1 = ex2f(v1 - newm); v2 = ex2f(v2 - newm); v3 = ex2f(v3 - newm);
      v4 = ex2f(v4 - newm); v5 = ex2f(v5 - newm); v6 = ex2f(v6 - newm); v7 = ex2f(v7 - newm);
      float psum = (v0 + v1) + (v2 + v3) + (v4 + v5) + (v6 + v7);
      #pragma unroll
      for (int off = 8; off; off >>= 1)
        psum += __shfl_xor_sync(0xffffffffu, psum, off);
      li[i] = li[i] * fac + psum;
      mi[i] = newm;
      const ull fv = bcast2(fac);
      mul2(acc[i][0], fv); mul2(acc[i][1], fv);
      *reinterpret_cast<float4*>(&KP[(r0 + i) * TSK + c0]) = make_float4(v0, v1, v2, v3);
      *reinterpret_cast<float4*>(&KP[(r0 + i) * TSK + c1]) = make_float4(v4, v5, v6, v7);
    }
    __syncthreads();

    #pragma unroll 2
    for (int j0 = 0; j0 < BN; j0 += 4) {
      const ulonglong2 w0 = *reinterpret_cast<const ulonglong2*>(&Vs[(j0 + 0) * Ec + c0]);
      const ulonglong2 w1 = *reinterpret_cast<const ulonglong2*>(&Vs[(j0 + 1) * Ec + c0]);
      const ulonglong2 w2 = *reinterpret_cast<const ulonglong2*>(&Vs[(j0 + 2) * Ec + c0]);
      const ulonglong2 w3 = *reinterpret_cast<const ulonglong2*>(&Vs[(j0 + 3) * Ec + c0]);
      #pragma unroll
      for (int i = 0; i < 8; ++i) {
        const float4 p = *reinterpret_cast<const float4*>(&KP[(r0 + i) * TSK + j0]);
        ull aa;
        aa = bcast2(p.x); fma2(acc[i][0], aa, w0.x); fma2(acc[i][1], aa, w0.y);
        aa = bcast2(p.y); fma2(acc[i][0], aa, w1.x); fma2(acc[i][1], aa, w1.y);
        aa = bcast2(p.z); fma2(acc[i][0], aa, w2.x); fma2(acc[i][1], aa, w2.y);
        aa = bcast2(p.w); fma2(acc[i][0], aa, w3.x); fma2(acc[i][1], aa, w3.y);
      }
    }
  }

  __syncthreads();
  {
    const int row = tid >> 1;
    const int jbase = (tid & 1) << 1;
    #pragma unroll
    for (int t = 0; t < 2; ++t) {
      const int jj = jbase + t;
      const int ig = m0 + row;
      const int j = ig - 2 + jj;
      float sc = -1e30f;
      if (j >= 0 && j < Lc) {
        float dot = 0.f;
        #pragma unroll
        for (int e4 = 0; e4 < Ec; e4 += 4) {
          const float4 kk = *reinterpret_cast<const float4*>(&Kg[j * RE + e4]);
          dot += Qs[(e4 + 0) * TSQ + row] * kk.x
               + Qs[(e4 + 1) * TSQ + row] * kk.y
               + Qs[(e4 + 2) * TSQ + row] * kk.z
               + Qs[(e4 + 3) * TSQ + row] * kk.w;
        }
        sc = dot;
      }
      Ls[(row << 2) + jj] = sc;
    }
  }
  __syncthreads();

  #pragma unroll
  for (int i = 0; i < 8; ++i) {
    const int r = r0 + i;
    const int ig = m0 + r;
    const float4 lsc = *reinterpret_cast<const float4*>(&Ls[r << 2]);
    const float mx = fmaxf(fmaxf(lsc.x, lsc.y), fmaxf(lsc.z, lsc.w));
    float w[4];
    w[0] = ex2f(lsc.x - mx); w[1] = ex2f(lsc.y - mx);
    w[2] = ex2f(lsc.z - mx); w[3] = ex2f(lsc.w - mx);
    const float winv = 1.f / (w[0] + w[1] + w[2] + w[3]);
    const float invl = 1.f / li[i];
    float o0, o1, o2, o3;
    unp2(acc[i][0], o0, o1); unp2(acc[i][1], o2, o3);
    float4 outv = make_float4(o0 * invl, o1 * invl, o2 * invl, o3 * invl);
    #pragma unroll
    for (int jj = 0; jj < 4; ++jj) {
      const int j = ig - 2 + jj;
      if (j >= 0 && j < Lc) {
        const float wj = w[jj] * winv;
        const float4 v = *reinterpret_cast<const float4*>(&Vg[j * RE + c0]);
        outv.x += wj * v.x; outv.y += wj * v.y;
        outv.z += wj * v.z; outv.w += wj * v.w;
      }
    }
    *reinterpret_cast<float4*>(&Og[ig * RE + c0]) = outv;
  }
#endif  // !HAS_TC
}

}  // namespace

extern "C" void kernel_launch(void* const* d_in, const int* in_sizes, int n_in,
                              void* d_out, int out_size) {
  const float* Q = (const float*)d_in[0];
  const float* K = (const float*)d_in[1];
  const float* V = (const float*)d_in[2];
  float* O = (float*)d_out;

  cudaFuncSetAttribute(hybrid_attn_tc, cudaFuncAttributeMaxDynamicSharedMemorySize, SMEM_TC);
  const size_t smemS = (size_t)SMEM_FLOATS * sizeof(float);
  cudaFuncSetAttribute(hybrid_attn_simt, cudaFuncAttributeMaxDynamicSharedMemorySize, (int)smemS);

  dim3 gridTC(Lc / BMt, 4 * Hc);
  hybrid_attn_tc<<<gridTC, 256, SMEM_TC>>>(Q, K, V, O);
  dim3 gridS(Lc / BM, 4 * Hc);
  hybrid_attn_simt<<<gridS, 128, smemS>>>(Q, K, V, O);
}

// round 11
// speedup vs baseline: 3.3941x; 1.0011x over previous
#include <cuda_runtime.h>
#include <cuda_fp16.h>
#include <cstdint>

// tcgen05 is only legal on arch-specific (sm_103a/sm_100a) device passes.
#if defined(__CUDA_ARCH_FEAT_SM103_ALL) || defined(__CUDA_ARCH_FEAT_SM100_ALL) || \
    defined(__CUDA_ARCH_FEAT_SM101_ALL) ||                                        \
    (defined(__CUDA_ARCH_SPECIFIC__) && (__CUDA_ARCH_SPECIFIC__ >= 1000)) ||       \
    (defined(__CUDA_ARCH_FAMILY_SPECIFIC__) && (__CUDA_ARCH_FAMILY_SPECIFIC__ >= 1000))
#define HAS_TC 1
#else
#define HAS_TC 0
#endif

namespace {

using ull = unsigned long long;

constexpr int Lc = 2048, Hc = 8, Ec = 64;
constexpr int RE = Hc * Ec;                  // 512
constexpr float SCL2E = 0.125f * 1.44269504088896340736f;

__device__ __forceinline__ float ex2f(float x) {
  float y; asm("ex2.approx.ftz.f32 %0, %1;" : "=f"(y) : "f"(x)); return y;
}

// ======================= TC kernel (sm_103a path) ==========================

constexpr int BMt = 128, BNt = 64;
constexpr int NTt = Lc / BNt;                // 32 key tiles
constexpr float PBIAS = 4.0f;
constexpr unsigned IDESC = 0x08100010u;      // kind::f16: F32 acc, f16 a/b, M=128, N=64

// TMEM: S double-buffered
constexpr unsigned TM_S0 = 0, TM_S1 = 64, TM_O = 128, TM_PH = 192, TM_PL = 224;
constexpr unsigned TM_COLS = 256;

constexpr int OFF_PTR = 0, OFF_MB_S0 = 8, OFF_MB_S1 = 16, OFF_MB_O = 24;
constexpr int OFF_QH = 1024;
constexpr int OFF_QL = OFF_QH + 16384;
constexpr int OFF_K0 = OFF_QL + 16384;       // KH @ +0, KL @ +8192 (64 rows x 128B)
constexpr int OFF_K1 = OFF_K0 + 16384;
constexpr int OFF_V0 = OFF_K1 + 16384;       // VHt @ +0, VLt @ +8192 (e-major transposed)
constexpr int OFF_V1 = OFF_V0 + 16384;
constexpr int OFF_LS = OFF_V1 + 16384;       // float Ls[128][4] local scores
constexpr int OFF_LSUM = OFF_LS + 2048;      // float Lsum[128]
constexpr int SMEM_TC = OFF_LSUM + 512;      // 101888 B

#if HAS_TC

// K-major SW128 descriptor: LBO=1, SBO=64
constexpr unsigned long long DESC_BASE =
    (2ull << 61) | (1ull << 46) | (64ull << 32) | (1ull << 16);

__device__ __forceinline__ unsigned sm32(const void* p) {
  unsigned a;
  asm("{ .reg .u64 t; cvta.to.shared.u64 t, %1; cvt.u32.u64 %0, t; }" : "=r"(a) : "l"(p));
  return a;
}
__device__ __forceinline__ unsigned long long mkdesc(unsigned addr) {
  return DESC_BASE | ((unsigned long long)(addr >> 4) & 0x3FFF);
}
__device__ __forceinline__ unsigned swzb(unsigned off) { return off ^ ((off >> 3) & 0x70); }
__device__ __forceinline__ unsigned packh2(float a, float b) {
  __half2 t = __floats2half2_rn(a, b);
  return reinterpret_cast<unsigned&>(t);
}
__device__ __forceinline__ void split1(float x, float& h, float& l) {
  __half b = __float2half_rn(x);
  h = __half2float(b);
  l = x - h;
}
__device__ __forceinline__ unsigned elect1() {
  unsigned p;
  asm volatile("{\n\t.reg .pred p;\n\telect.sync _|p, 0xFFFFFFFF;\n\tselp.b32 %0, 1, 0, p;\n\t}" : "=r"(p));
  return p;
}
__device__ __forceinline__ void mbar_init(unsigned mbar, unsigned cnt) {
  asm volatile("mbarrier.init.shared.b64 [%0], %1;" :: "r"(mbar), "r"(cnt) : "memory");
}
__device__ __forceinline__ void mbar_wait(unsigned mbar, unsigned parity) {
  asm volatile(
      "{\n\t.reg .pred P1;\n\t"
      "LWAIT_%=:\n\t"
      "mbarrier.try_wait.parity.acquire.cta.shared::cta.b64 P1, [%0], %1, 0x989680;\n\t"
      "@P1 bra.uni LDONE_%=;\n\t"
      "bra.uni LWAIT_%=;\n\t"
      "LDONE_%=:\n\t}"
      :: "r"(mbar), "r"(parity) : "memory");
}
__device__ __forceinline__ void tc_commit(unsigned mbar) {
  asm volatile(
      "tcgen05.commit.cta_group::1.mbarrier::arrive::one.shared::cluster.b64 [%0];"
      :: "r"(mbar) : "memory");
}
__device__ __forceinline__ void tc_alloc(unsigned dst, unsigned ncols) {
  asm volatile("tcgen05.alloc.cta_group::1.sync.aligned.shared::cta.b32 [%0], %1;"
               :: "r"(dst), "r"(ncols) : "memory");
}
__device__ __forceinline__ void tc_relinq() {
  asm volatile("tcgen05.relinquish_alloc_permit.cta_group::1.sync.aligned;");
}
__device__ __forceinline__ void tc_dealloc(unsigned base, unsigned ncols) {
  asm volatile("tcgen05.dealloc.cta_group::1.sync.aligned.b32 %0, %1;" :: "r"(base), "r"(ncols));
}
__device__ __forceinline__ void fence_before() {
  asm volatile("tcgen05.fence::before_thread_sync;" ::: "memory");
}
__device__ __forceinline__ void fence_after() {
  asm volatile("tcgen05.fence::after_thread_sync;" ::: "memory");
}
__device__ __forceinline__ void fence_proxy() {
  asm volatile("fence.proxy.async.shared::cta;" ::: "memory");
}
__device__ __forceinline__ void wait_ld() { asm volatile("tcgen05.wait::ld.sync.aligned;" ::: "memory"); }
__device__ __forceinline__ void wait_st() { asm volatile("tcgen05.wait::st.sync.aligned;" ::: "memory"); }

__device__ __forceinline__ void mma_ss(unsigned d, unsigned long long ad,
                                       unsigned long long bd, unsigned idesc, bool en) {
  unsigned e = en ? 1u : 0u;
  asm volatile(
      "{\n\t.reg .pred p;\n\tsetp.ne.u32 p, %5, 0;\n\t"
      "tcgen05.mma.cta_group::1.kind::f16 [%0], %1, %2, %3, {%4, %4, %4, %4}, p;\n\t}"
      :: "r"(d), "l"(ad), "l"(bd), "r"(idesc), "r"(0u), "r"(e) : "memory");
}
__device__ __forceinline__ void mma_ts(unsigned d, unsigned a,
                                       unsigned long long bd, unsigned idesc, bool en) {
  unsigned e = en ? 1u : 0u;
  asm volatile(
      "{\n\t.reg .pred p;\n\tsetp.ne.u32 p, %5, 0;\n\t"
      "tcgen05.mma.cta_group::1.kind::f16 [%0], [%1], %2, %3, {%4, %4, %4, %4}, p;\n\t}"
      :: "r"(d), "r"(a), "l"(bd), "r"(idesc), "r"(0u), "r"(e) : "memory");
}

#define TLD32(r, addr)                                                        \
  asm volatile(                                                               \
      "tcgen05.ld.sync.aligned.32x32b.x32.b32 "                               \
      "{%0, %1, %2, %3, %4, %5, %6, %7, "                                     \
      " %8, %9, %10, %11, %12, %13, %14, %15, "                               \
      " %16, %17, %18, %19, %20, %21, %22, %23, "                             \
      " %24, %25, %26, %27, %28, %29, %30, %31}, [%32];"                      \
      : "=r"((r)[0]),  "=r"((r)[1]),  "=r"((r)[2]),  "=r"((r)[3]),            \
        "=r"((r)[4]),  "=r"((r)[5]),  "=r"((r)[6]),  "=r"((r)[7]),            \
        "=r"((r)[8]),  "=r"((r)[9]),  "=r"((r)[10]), "=r"((r)[11]),           \
        "=r"((r)[12]), "=r"((r)[13]), "=r"((r)[14]), "=r"((r)[15]),           \
        "=r"((r)[16]), "=r"((r)[17]), "=r"((r)[18]), "=r"((r)[19]),           \
        "=r"((r)[20]), "=r"((r)[21]), "=r"((r)[22]), "=r"((r)[23]),           \
        "=r"((r)[24]), "=r"((r)[25]), "=r"((r)[26]), "=r"((r)[27]),           \
        "=r"((r)[28]), "=r"((r)[29]), "=r"((r)[30]), "=r"((r)[31])            \
      : "r"(addr))

#define TST16(addr, r)                                                        \
  asm volatile(                                                               \
      "tcgen05.st.sync.aligned.32x32b.x16.b32 [%0], "                         \
      "{%1, %2, %3, %4, %5, %6, %7, %8, "                                     \
      " %9, %10, %11, %12, %13, %14, %15, %16};"                              \
      :: "r"(addr),                                                           \
         "r"((r)[0]),  "r"((r)[1]),  "r"((r)[2]),  "r"((r)[3]),               \
         "r"((r)[4]),  "r"((r)[5]),  "r"((r)[6]),  "r"((r)[7]),               \
         "r"((r)[8]),  "r"((r)[9]),  "r"((r)[10]), "r"((r)[11]),              \
         "r"((r)[12]), "r"((r)[13]), "r"((r)[14]), "r"((r)[15])               \
      : "memory")

#endif  // HAS_TC

__global__ __launch_bounds__(256, 2)
void hybrid_attn_tc(const float* __restrict__ Q, const float* __restrict__ K,
                    const float* __restrict__ V, float* __restrict__ O) {
#if HAS_TC
  extern __shared__ char smc[];
  const unsigned sb = sm32(smc);
  const int tid = threadIdx.x;
  const int wid = tid >> 5;
  const int lane = tid & 31;
  const int sub = wid & 3;          // TMEM subpartition (SMSP = wid % 4)
  const int half = wid >> 2;        // column half this warp owns
  const int m0 = blockIdx.x * BMt;
  const int bh = blockIdx.y;
  const int base = ((bh >> 3) * Lc * Hc + (bh & 7)) * Ec;
  const float* Qg = Q + base;
  const float* Kg = K + base;
  const float* Vg = V + base;
  float* Og = O + base;

  if (tid == 0) {
    mbar_init(sb + OFF_MB_S0, 1);
    mbar_init(sb + OFF_MB_S1, 1);
    mbar_init(sb + OFF_MB_O, 1);
  }
  if (wid == 0) { tc_alloc(sb + OFF_PTR, TM_COLS); tc_relinq(); }
  __syncthreads();
  unsigned tb;
  asm volatile("ld.shared.b32 %0, [%1];" : "=r"(tb) : "r"(sb + OFF_PTR));

  const unsigned long long dqh = mkdesc(sb + OFF_QH), dql = mkdesc(sb + OFF_QL);

  // ---- Q tile -> QH/QL (fp16 split, SW128, 128B rows) ----
  #pragma unroll
  for (int it = 0; it < 8; ++it) {
    const int idx = tid + it * 256;
    const int r = idx >> 4, e4 = (idx & 15) << 2;
    const float4 q = *reinterpret_cast<const float4*>(&Qg[(m0 + r) * RE + e4]);
    float hx, hy, hz, hw, lx, ly, lz, lw;
    split1(q.x, hx, lx); split1(q.y, hy, ly); split1(q.z, hz, lz); split1(q.w, hw, lw);
    const unsigned sw = swzb((unsigned)(r * 128 + e4 * 2));
    *reinterpret_cast<unsigned*>(smc + OFF_QH + sw)     = packh2(hx, hy);
    *reinterpret_cast<unsigned*>(smc + OFF_QH + sw + 4) = packh2(hz, hw);
    *reinterpret_cast<unsigned*>(smc + OFF_QL + sw)     = packh2(lx, ly);
    *reinterpret_cast<unsigned*>(smc + OFF_QL + sw + 4) = packh2(lz, lw);
  }

  // ---- K/V tile 0 ----
  #pragma unroll
  for (int it = 0; it < 4; ++it) {
    const int idx = tid + it * 256;
    const int j = idx >> 4, e4 = (idx & 15) << 2;
    const float4 kk = *reinterpret_cast<const float4*>(&Kg[j * RE + e4]);
    float hx, hy, hz, hw, lx, ly, lz, lw;
    split1(kk.x, hx, lx); split1(kk.y, hy, ly); split1(kk.z, hz, lz); split1(kk.w, hw, lw);
    const unsigned sw = swzb((unsigned)(j * 128 + e4 * 2));
    *reinterpret_cast<unsigned*>(smc + OFF_K0 + sw)            = packh2(hx, hy);
    *reinterpret_cast<unsigned*>(smc + OFF_K0 + sw + 4)        = packh2(hz, hw);
    *reinterpret_cast<unsigned*>(smc + OFF_K0 + 8192 + sw)     = packh2(lx, ly);
    *reinterpret_cast<unsigned*>(smc + OFF_K0 + 8192 + sw + 4) = packh2(lz, lw);
    const float4 vv = *reinterpret_cast<const float4*>(&Vg[j * RE + e4]);
    #pragma unroll
    for (int t = 0; t < 4; ++t) {
      const float x = (t == 0) ? vv.x : (t == 1) ? vv.y : (t == 2) ? vv.z : vv.w;
      float h, l;
      split1(x, h, l);
      const unsigned sv = swzb((unsigned)((e4 + t) * 128 + j * 2));
      *reinterpret_cast<__half*>(smc + OFF_V0 + sv)        = __float2half_rn(h);
      *reinterpret_cast<__half*>(smc + OFF_V0 + 8192 + sv) = __float2half_rn(l);
    }
  }
  fence_proxy();
  __syncthreads();

  // ---- S-MMA(0) -> S0, commit MB_S0 ----
  if (wid == 0 && elect1()) {
    const unsigned long long dkh = mkdesc(sb + OFF_K0), dkl = mkdesc(sb + OFF_K0 + 8192);
    #pragma unroll
    for (int k = 0; k < 4; ++k) mma_ss(tb + TM_S0, dqh + 2 * k, dkh + 2 * k, IDESC, k > 0);
    #pragma unroll
    for (int k = 0; k < 4; ++k) mma_ss(tb + TM_S0, dqh + 2 * k, dkl + 2 * k, IDESC, true);
    #pragma unroll
    for (int k = 0; k < 4; ++k) mma_ss(tb + TM_S0, dql + 2 * k, dkh + 2 * k, IDESC, true);
    tc_commit(sb + OFF_MB_S0);
  }

  unsigned ps[2] = {0u, 0u};
  unsigned po = 0;
  float lsum = 0.f;
  const unsigned woff = (unsigned)sub << 21;

  for (int nt = 0; nt < NTt; ++nt) {
    const int kb = (nt & 1) ? OFF_K1 : OFF_K0;
    const int vb = (nt & 1) ? OFF_V1 : OFF_V0;
    const int kb2 = (nt & 1) ? OFF_K0 : OFF_K1;
    const int vb2 = (nt & 1) ? OFF_V0 : OFF_V1;

    // ---- load K(nt+1) (reader S(nt-1) finished: waited at iter nt-1) ----
    if (nt + 1 < NTt) {
      const int n0 = (nt + 1) * BNt;
      #pragma unroll
      for (int it = 0; it < 4; ++it) {
        const int idx = tid + it * 256;
        const int j = idx >> 4, e4 = (idx & 15) << 2;
        const float4 kk = *reinterpret_cast<const float4*>(&Kg[(n0 + j) * RE + e4]);
        float hx, hy, hz, hw, lx, ly, lz, lw;
        split1(kk.x, hx, lx); split1(kk.y, hy, ly); split1(kk.z, hz, lz); split1(kk.w, hw, lw);
        const unsigned sw = swzb((unsigned)(j * 128 + e4 * 2));
        *reinterpret_cast<unsigned*>(smc + kb2 + sw)            = packh2(hx, hy);
        *reinterpret_cast<unsigned*>(smc + kb2 + sw + 4)        = packh2(hz, hw);
        *reinterpret_cast<unsigned*>(smc + kb2 + 8192 + sw)     = packh2(lx, ly);
        *reinterpret_cast<unsigned*>(smc + kb2 + 8192 + sw + 4) = packh2(lz, lw);
      }
    }

    // ---- O(nt-1) must finish before overwriting its V buffer / P / issuing TST ----
    if (nt > 0) { mbar_wait(sb + OFF_MB_O, po); po ^= 1; }

    // ---- load V(nt+1) ----
    if (nt + 1 < NTt) {
      const int n0 = (nt + 1) * BNt;
      #pragma unroll
      for (int it = 0; it < 4; ++it) {
        const int idx = tid + it * 256;
        const int j = idx >> 4, e4 = (idx & 15) << 2;
        const float4 vv = *reinterpret_cast<const float4*>(&Vg[(n0 + j) * RE + e4]);
        #pragma unroll
        for (int t = 0; t < 4; ++t) {
          const float x = (t == 0) ? vv.x : (t == 1) ? vv.y : (t == 2) ? vv.z : vv.w;
          float h, l;
          split1(x, h, l);
          const unsigned sv = swzb((unsigned)((e4 + t) * 128 + j * 2));
          *reinterpret_cast<__half*>(smc + vb2 + sv)        = __float2half_rn(h);
          *reinterpret_cast<__half*>(smc + vb2 + 8192 + sv) = __float2half_rn(l);
        }
      }
    }
    fence_proxy();
    __syncthreads();

    // ---- issue S-MMA(nt+1) into the other S buffer (overlaps epilogue) ----
    if (nt + 1 < NTt && wid == 0 && elect1()) {
      const unsigned sdst = ((nt + 1) & 1) ? TM_S1 : TM_S0;
      const unsigned smb = ((nt + 1) & 1) ? (sb + OFF_MB_S1) : (sb + OFF_MB_S0);
      const unsigned long long dkh = mkdesc(sb + kb2), dkl = mkdesc(sb + kb2 + 8192);
      #pragma unroll
      for (int k = 0; k < 4; ++k) mma_ss(tb + sdst, dqh + 2 * k, dkh + 2 * k, IDESC, k > 0);
      #pragma unroll
      for (int k = 0; k < 4; ++k) mma_ss(tb + sdst, dqh + 2 * k, dkl + 2 * k, IDESC, true);
      #pragma unroll
      for (int k = 0; k < 4; ++k) mma_ss(tb + sdst, dql + 2 * k, dkh + 2 * k, IDESC, true);
      tc_commit(smb);
    }

    // ---- wait S(nt) (usually already complete) ----
    {
      const unsigned smb = (nt & 1) ? (sb + OFF_MB_S1) : (sb + OFF_MB_S0);
      mbar_wait(smb, ps[nt & 1]);
      ps[nt & 1] ^= 1;
    }
    fence_after();

    // ---- epilogue: each warp handles its 32-column half of S(nt) ----
    const unsigned ssrc = (nt & 1) ? TM_S1 : TM_S0;
    unsigned sr[32];
    TLD32(sr, tb + ssrc + 32 * half);
    wait_ld();
    unsigned ph[16], pl[16];
    #pragma unroll
    for (int c = 0; c < 16; ++c) {
      const float s0 = __uint_as_float(sr[2 * c]);
      const float s1 = __uint_as_float(sr[2 * c + 1]);
      const float p0 = ex2f(fmaf(s0, SCL2E, -PBIAS));
      const float p1 = ex2f(fmaf(s1, SCL2E, -PBIAS));
      lsum += p0 + p1;
      float h0, l0, h1, l1;
      split1(p0, h0, l0); split1(p1, h1, l1);
      ph[c] = packh2(h0, h1);
      pl[c] = packh2(l0, l1);
    }
    TST16(tb + TM_PH + 16 * half + woff, ph);
    TST16(tb + TM_PL + 16 * half + woff, pl);
    wait_st();
    fence_before();
    __syncthreads();

    // ---- O += Ph·Vh + Ph·Vl + Pl·Vh (reads vb(nt)) ----
    if (wid == 0 && elect1()) {
      fence_after();
      fence_proxy();
      const unsigned long long dvh = mkdesc(sb + vb), dvl = mkdesc(sb + vb + 8192);
      #pragma unroll
      for (int k = 0; k < 4; ++k)
        mma_ts(tb + TM_O, tb + TM_PH + 8 * k, dvh + 2 * k, IDESC, !(nt == 0 && k == 0));
      #pragma unroll
      for (int k = 0; k < 4; ++k)
        mma_ts(tb + TM_O, tb + TM_PH + 8 * k, dvl + 2 * k, IDESC, true);
      #pragma unroll
      for (int k = 0; k < 4; ++k)
        mma_ts(tb + TM_O, tb + TM_PL + 8 * k, dvh + 2 * k, IDESC, true);
      tc_commit(sb + OFF_MB_O);
    }
  }

  mbar_wait(sb + OFF_MB_O, po);
  fence_after();

  // Each warp reads its 32-column half of O for its subpartition rows.
  unsigned orr[32];
  TLD32(orr, tb + TM_O + 32 * half);
  wait_ld();
  fence_before();

  float* Ls = reinterpret_cast<float*>(smc + OFF_LS);
  float* LsumS = reinterpret_cast<float*>(smc + OFF_LSUM);

  // ---- local branch scores: 2 (row, jj) pairs per thread ----
  {
    const int row = tid >> 1;
    const int jb = (tid & 1) << 1;
    #pragma unroll
    for (int t = 0; t < 2; ++t) {
      const int jj = jb + t;
      const int ig = m0 + row;
      const int j = ig - 2 + jj;
      float sc = -1e30f;
      if (j >= 0 && j < Lc) {
        const float* qrow = Qg + ig * RE;
        const float* krow = Kg + j * RE;
        float dot = 0.f;
        #pragma unroll 4
        for (int e4 = 0; e4 < Ec; e4 += 4) {
          const float4 q = *reinterpret_cast<const float4*>(&qrow[e4]);
          const float4 kk = *reinterpret_cast<const float4*>(&krow[e4]);
          dot += q.x * kk.x + q.y * kk.y + q.z * kk.z + q.w * kk.w;
        }
        sc = dot * SCL2E;
      }
      Ls[(row << 2) + jj] = sc;
    }
  }
  // ---- cross-warp lsum combine ----
  if (wid < 4) LsumS[sub * 32 + lane] = lsum;
  __syncthreads();
  if (wid >= 4) LsumS[sub * 32 + lane] += lsum;
  __syncthreads();

  // ---- combine global + local, write output (this warp's e-column half) ----
  {
    const int r = sub * 32 + lane;
    const int ig = m0 + r;
    const float4 lsc = *reinterpret_cast<const float4*>(&Ls[r << 2]);
    const float mx = fmaxf(fmaxf(lsc.x, lsc.y), fmaxf(lsc.z, lsc.w));
    const float w0 = ex2f(lsc.x - mx), w1 = ex2f(lsc.y - mx);
    const float w2 = ex2f(lsc.z - mx), w3 = ex2f(lsc.w - mx);
    const float winv = 1.f / (w0 + w1 + w2 + w3);
    const float n0w = w0 * winv, n1w = w1 * winv, n2w = w2 * winv, n3w = w3 * winv;
    const float invl = 1.f / LsumS[r];
    const bool b0 = (ig - 2) >= 0;
    const bool b1 = (ig - 1) >= 0;
    const bool b3 = (ig + 1) < Lc;
    const float* vp0 = Vg + (ig - 2) * RE;
    const float* vp1 = Vg + (ig - 1) * RE;
    const float* vp2 = Vg + ig * RE;
    const float* vp3 = Vg + (ig + 1) * RE;
    const int e0 = 32 * half;
    #pragma unroll
    for (int c4 = 0; c4 < 32; c4 += 4) {
      const int e4 = e0 + c4;
      float4 o;
      o.x = __uint_as_float(orr[c4 + 0]) * invl;
      o.y = __uint_as_float(orr[c4 + 1]) * invl;
      o.z = __uint_as_float(orr[c4 + 2]) * invl;
      o.w = __uint_as_float(orr[c4 + 3]) * invl;
      if (b0) { const float4 vv = *reinterpret_cast<const float4*>(&vp0[e4]);
                o.x += n0w * vv.x; o.y += n0w * vv.y; o.z += n0w * vv.z; o.w += n0w * vv.w; }
      if (b1) { const float4 vv = *reinterpret_cast<const float4*>(&vp1[e4]);
                o.x += n1w * vv.x; o.y += n1w * vv.y; o.z += n1w * vv.z; o.w += n1w * vv.w; }
      {       const float4 vv = *reinterpret_cast<const float4*>(&vp2[e4]);
                o.x += n2w * vv.x; o.y += n2w * vv.y; o.z += n2w * vv.z; o.w += n2w * vv.w; }
      if (b3) { const float4 vv = *reinterpret_cast<const float4*>(&vp3[e4]);
                o.x += n3w * vv.x; o.y += n3w * vv.y; o.z += n3w * vv.z; o.w += n3w * vv.w; }
      *reinterpret_cast<float4*>(&Og[ig * RE + e4]) = o;
    }
  }

  __syncthreads();
  if (wid == 0) tc_dealloc(tb, TM_COLS);
#endif  // HAS_TC
}

// ===================== SIMT fallback (plain sm_103 path) ====================

constexpr int BM = 64, BN = 128;
constexpr int TSQ = 68;
constexpr int TSK = 132;
constexpr int OFF_Q = 0;
constexpr int OFF_KP = OFF_Q + Ec * TSQ;
constexpr int OFF_V = OFF_KP + 64 * TSK;
constexpr int OFF_L = OFF_V + BN * Ec;
constexpr int SMEM_FLOATS = OFF_L + BM * 4;

#if !HAS_TC
__device__ __forceinline__ void fma2(ull& d, ull a, ull b) {
  asm("fma.rn.f32x2 %0, %1, %2, %0;" : "+l"(d) : "l"(a), "l"(b));
}
__device__ __forceinline__ void mul2(ull& d, ull a) {
  asm("mul.rn.f32x2 %0, %0, %1;" : "+l"(d) : "l"(a));
}
__device__ __forceinline__ ull bcast2(float x) {
  ull r; asm("mov.b64 %0, {%1, %1};" : "=l"(r) : "f"(x)); return r;
}
__device__ __forceinline__ void unp2(ull v, float& lo, float& hi) {
  asm("mov.b64 {%0, %1}, %2;" : "=f"(lo), "=f"(hi) : "l"(v));
}
#endif

__global__ __launch_bounds__(128, 2)
void hybrid_attn_simt(const float* __restrict__ Q, const float* __restrict__ K,
                      const float* __restrict__ V, float* __restrict__ O) {
#if !HAS_TC
  extern __shared__ float smf[];
  float* Qs = smf + OFF_Q;
  float* KP = smf + OFF_KP;
  float* Vs = smf + OFF_V;
  float* Ls = smf + OFF_L;

  const int tid = threadIdx.x;
  const int tx = tid & 15;
  const int ty = tid >> 4;
  const int r0 = ty << 3;
  const int c0 = tx << 2;
  const int c1 = 64 + c0;

  const int m0 = blockIdx.x * BM;
  const int bh = blockIdx.y;
  const int base = ((bh >> 3) * Lc * Hc + (bh & 7)) * Ec;
  const float* Qg = Q + base;
  const float* Kg = K + base;
  const float* Vg = V + base;
  float* Og = O + base;

  const int le4 = (tid & 15) << 2;
  const int lr = tid >> 4;

  #pragma unroll
  for (int it = 0; it < 8; ++it) {
    const int r = lr + it * 8;
    const float4 q = *reinterpret_cast<const float4*>(&Qg[(m0 + r) * RE + le4]);
    Qs[(le4 + 0) * TSQ + r] = q.x * SCL2E;
    Qs[(le4 + 1) * TSQ + r] = q.y * SCL2E;
    Qs[(le4 + 2) * TSQ + r] = q.z * SCL2E;
    Qs[(le4 + 3) * TSQ + r] = q.w * SCL2E;
  }

  float mi[8], li[8];
  ull acc[8][2];
  #pragma unroll
  for (int i = 0; i < 8; ++i) { mi[i] = -1e30f; li[i] = 0.f; acc[i][0] = 0ull; acc[i][1] = 0ull; }

  for (int n0 = 0; n0 < Lc; n0 += BN) {
    __syncthreads();
    #pragma unroll
    for (int it = 0; it < 16; ++it) {
      const int r = lr + it * 8;
      const float4 kk = *reinterpret_cast<const float4*>(&Kg[(n0 + r) * RE + le4]);
      KP[(le4 + 0) * TSK + r] = kk.x;
      KP[(le4 + 1) * TSK + r] = kk.y;
      KP[(le4 + 2) * TSK + r] = kk.z;
      KP[(le4 + 3) * TSK + r] = kk.w;
      const float4 vv = *reinterpret_cast<const float4*>(&Vg[(n0 + r) * RE + le4]);
      *reinterpret_cast<float4*>(&Vs[r * Ec + le4]) = vv;
    }
    __syncthreads();

    ull s[8][4];
    #pragma unroll
    for (int i = 0; i < 8; ++i)
      #pragma unroll
      for (int p = 0; p < 4; ++p) s[i][p] = 0ull;

    #pragma unroll 4
    for (int e = 0; e < Ec; ++e) {
      const ulonglong2 b0 = *reinterpret_cast<const ulonglong2*>(&KP[e * TSK + c0]);
      const ulonglong2 b1 = *reinterpret_cast<const ulonglong2*>(&KP[e * TSK + c1]);
      const float4 a0 = *reinterpret_cast<const float4*>(&Qs[e * TSQ + r0]);
      const float4 a1 = *reinterpret_cast<const float4*>(&Qs[e * TSQ + r0 + 4]);
      ull aa;
      aa = bcast2(a0.x); fma2(s[0][0], aa, b0.x); fma2(s[0][1], aa, b0.y); fma2(s[0][2], aa, b1.x); fma2(s[0][3], aa, b1.y);
      aa = bcast2(a0.y); fma2(s[1][0], aa, b0.x); fma2(s[1][1], aa, b0.y); fma2(s[1][2], aa, b1.x); fma2(s[1][3], aa, b1.y);
      aa = bcast2(a0.z); fma2(s[2][0], aa, b0.x); fma2(s[2][1], aa, b0.y); fma2(s[2][2], aa, b1.x); fma2(s[2][3], aa, b1.y);
      aa = bcast2(a0.w); fma2(s[3][0], aa, b0.x); fma2(s[3][1], aa, b0.y); fma2(s[3][2], aa, b1.x); fma2(s[3][3], aa, b1.y);
      aa = bcast2(a1.x); fma2(s[4][0], aa, b0.x); fma2(s[4][1], aa, b0.y); fma2(s[4][2], aa, b1.x); fma2(s[4][3], aa, b1.y);
      aa = bcast2(a1.y); fma2(s[5][0], aa, b0.x); fma2(s[5][1], aa, b0.y); fma2(s[5][2], aa, b1.x); fma2(s[5][3], aa, b1.y);
      aa = bcast2(a1.z); fma2(s[6][0], aa, b0.x); fma2(s[6][1], aa, b0.y); fma2(s[6][2], aa, b1.x); fma2(s[6][3], aa, b1.y);
      aa = bcast2(a1.w); fma2(s[7][0], aa, b0.x); fma2(s[7][1], aa, b0.y); fma2(s[7][2], aa, b1.x); fma2(s[7][3], aa, b1.y);
    }
    __syncthreads();

    #pragma unroll
    for (int i = 0; i < 8; ++i) {
      float v0, v1, v2, v3, v4, v5, v6, v7;
      unp2(s[i][0], v0, v1); unp2(s[i][1], v2, v3);
      unp2(s[i][2], v4, v5); unp2(s[i][3], v6, v7);
      float tm = fmaxf(fmaxf(fmaxf(v0, v1), fmaxf(v2, v3)),
                       fmaxf(fmaxf(v4, v5), fmaxf(v6, v7)));
      #pragma unroll
      for (int off = 8; off; off >>= 1)
        tm = fmaxf(tm, __shfl_xor_sync(0xffffffffu, tm, off));
      const float newm = fmaxf(mi[i], tm);
      const float fac = ex2f(mi[i] - newm);
      v0 = ex2f(v0 - newm); v1 = ex2f(v1 - newm); v2 = ex2f(v2 - newm); v3 = ex2f(v3 - newm);
      v4 = ex2f(v4 - newm); v5 = ex2f(v5 - newm); v6 = ex2f(v6 - newm); v7 = ex2f(v7 - newm);
      float psum = (v0 + v1) + (v2 + v3) + (v4 + v5) + (v6 + v7);
      #pragma unroll
      for (int off = 8; off; off >>= 1)
        psum += __shfl_xor_sync(0xffffffffu, psum, off);
      li[i] = li[i] * fac + psum;
      mi[i] = newm;
      const ull fv = bcast2(fac);
      mul2(acc[i][0], fv); mul2(acc[i][1], fv);
      *reinterpret_cast<float4*>(&KP[(r0 + i) * TSK + c0]) = make_float4(v0, v1, v2, v3);
      *reinterpret_cast<float4*>(&KP[(r0 + i) * TSK + c1]) = make_float4(v4, v5, v6, v7);
    }
    __syncthreads();

    #pragma unroll 2
    for (int j0 = 0; j0 < BN; j0 += 4) {
      const ulonglong2 w0 = *reinterpret_cast<const ulonglong2*>(&Vs[(j0 + 0) * Ec + c0]);
      const ulonglong2 w1 = *reinterpret_cast<const ulonglong2*>(&Vs[(j0 + 1) * Ec + c0]);
      const ulonglong2 w2 = *reinterpret_cast<const ulonglong2*>(&Vs[(j0 + 2) * Ec + c0]);
      const ulonglong2 w3 = *reinterpret_cast<const ulonglong2*>(&Vs[(j0 + 3) * Ec + c0]);
      #pragma unroll
      for (int i = 0; i < 8; ++i) {
        const float4 p = *reinterpret_cast<const float4*>(&KP[(r0 + i) * TSK + j0]);
        ull aa;
        aa = bcast2(p.x); fma2(acc[i][0], aa, w0.x); fma2(acc[i][1], aa, w0.y);
        aa = bcast2(p.y); fma2(acc[i][0], aa, w1.x); fma2(acc[i][1], aa, w1.y);
        aa = bcast2(p.z); fma2(acc[i][0], aa, w2.x); fma2(acc[i][1], aa, w2.y);
        aa = bcast2(p.w); fma2(acc[i][0], aa, w3.x); fma2(acc[i][1], aa, w3.y);
      }
    }
  }

  __syncthreads();
  {
    const int row = tid >> 1;
    const int jbase = (tid & 1) << 1;
    #pragma unroll
    for (int t = 0; t < 2; ++t) {
      const int jj = jbase + t;
      const int ig = m0 + row;
      const int j = ig - 2 + jj;
      float sc = -1e30f;
      if (j >= 0 && j < Lc) {
        float dot = 0.f;
        #pragma unroll
        for (int e4 = 0; e4 < Ec; e4 += 4) {
          const float4 kk = *reinterpret_cast<const float4*>(&Kg[j * RE + e4]);
          dot += Qs[(e4 + 0) * TSQ + row] * kk.x
               + Qs[(e4 + 1) * TSQ + row] * kk.y
               + Qs[(e4 + 2) * TSQ + row] * kk.z
               + Qs[(e4 + 3) * TSQ + row] * kk.w;
        }
        sc = dot;
      }
      Ls[(row << 2) + jj] = sc;
    }
  }
  __syncthreads();

  #pragma unroll
  for (int i = 0; i < 8; ++i) {
    const int r = r0 + i;
    const int ig = m0 + r;
    const float4 lsc = *reinterpret_cast<const float4*>(&Ls[r << 2]);
    const float mx = fmaxf(fmaxf(lsc.x, lsc.y), fmaxf(lsc.z, lsc.w));
    float w[4];
    w[0] = ex2f(lsc.x - mx); w[1] = ex2f(lsc.y - mx);
    w[2] = ex2f(lsc.z - mx); w[3] = ex2f(lsc.w - mx);
    const float winv = 1.f / (w[0] + w[1] + w[2] + w[3]);
    const float invl = 1.f / li[i];
    float o0, o1, o2, o3;
    unp2(acc[i][0], o0, o1); unp2(acc[i][1], o2, o3);
    float4 outv = make_float4(o0 * invl, o1 * invl, o2 * invl, o3 * invl);
    #pragma unroll
    for (int jj = 0; jj < 4; ++jj) {
      const int j = ig - 2 + jj;
      if (j >= 0 && j < Lc) {
        const float wj = w[jj] * winv;
        const float4 v = *reinterpret_cast<const float4*>(&Vg[j * RE + c0]);
        outv.x += wj * v.x; outv.y += wj * v.y;
        outv.z += wj * v.z; outv.w += wj * v.w;
      }
    }
    *reinterpret_cast<float4*>(&Og[ig * RE + c0]) = outv;
  }
#endif  // !HAS_TC
}

}  // namespace

extern "C" void kernel_launch(void* const* d_in, const int* in_sizes, int n_in,
                              void* d_out, int out_size) {
  const float* Q = (const float*)d_in[0];
  const float* K = (const float*)d_in[1];
  const float* V = (const float*)d_in[2];
  float* O = (float*)d_out;

  cudaFuncSetAttribute(hybrid_attn_tc, cudaFuncAttributeMaxDynamicSharedMemorySize, SMEM_TC);
  const size_t smemS = (size_t)SMEM_FLOATS * sizeof(float);
  cudaFuncSetAttribute(hybrid_attn_simt, cudaFuncAttributeMaxDynamicSharedMemorySize, (int)smemS);

  dim3 gridTC(Lc / BMt, 4 * Hc);
  hybrid_attn_tc<<<gridTC, 256, SMEM_TC>>>(Q, K, V, O);
  dim3 gridS(Lc / BM, 4 * Hc);
  hybrid_attn_simt<<<gridS, 128, smemS>>>(Q, K, V, O);
}

// round 12
// speedup vs baseline: 5.6297x; 1.6587x over previous
#include <cuda_runtime.h>
#include <cuda_fp16.h>
#include <cstdint>

// tcgen05 is only legal on arch-specific (sm_103a/sm_100a) device passes.
#if defined(__CUDA_ARCH_FEAT_SM103_ALL) || defined(__CUDA_ARCH_FEAT_SM100_ALL) || \
    defined(__CUDA_ARCH_FEAT_SM101_ALL) ||                                        \
    (defined(__CUDA_ARCH_SPECIFIC__) && (__CUDA_ARCH_SPECIFIC__ >= 1000)) ||       \
    (defined(__CUDA_ARCH_FAMILY_SPECIFIC__) && (__CUDA_ARCH_FAMILY_SPECIFIC__ >= 1000))
#define HAS_TC 1
#else
#define HAS_TC 0
#endif

namespace {

using ull = unsigned long long;

constexpr int Lc = 2048, Hc = 8, Ec = 64;
constexpr int RE = Hc * Ec;                  // 512
constexpr float SCL2E = 0.125f * 1.44269504088896340736f;

__device__ __forceinline__ float ex2f(float x) {
  float y; asm("ex2.approx.ftz.f32 %0, %1;" : "=f"(y) : "f"(x)); return y;
}

// ======================= TC kernel (sm_103a path) ==========================

constexpr int BMt = 128, BNt = 128;
constexpr int NTt = Lc / BNt;                // 16 key tiles
constexpr float PBIAS = 4.0f;
constexpr unsigned IDESC_S = 0x08200010u;    // kind::f16: F32 acc, f16, M=128, N=128
constexpr unsigned IDESC_O = 0x08100010u;    // kind::f16: F32 acc, f16, M=128, N=64

// TMEM columns (256 total, 2 CTAs/SM)
constexpr unsigned TM_S = 0;       // 128 cols: S[128 q][128 j] fp32
constexpr unsigned TM_O = 128;     // 64 cols:  O[128 q][64 e] fp32
constexpr unsigned TM_PH = 192;    // 64 cols:  P[128 q][128 j] fp16 packed
constexpr unsigned TM_COLS = 256;

constexpr int OFF_PTR = 0, OFF_MB_S = 8, OFF_MB_O = 16;
constexpr int OFF_QH = 1024;                 // Q fp16 [128 q][64 e], 128B rows
constexpr int OFF_K0 = OFF_QH + 16384;       // K fp16 [128 j][64 e], 128B rows
constexpr int OFF_K1 = OFF_K0 + 16384;
constexpr int OFF_V0 = OFF_K1 + 16384;       // Vt fp16: half0 [64 e][j 0..63] @+0, half1 @+8192
constexpr int OFF_V1 = OFF_V0 + 16384;
constexpr int OFF_LS = OFF_V1 + 16384;       // float Ls[128][4]
constexpr int OFF_LSUM = OFF_LS + 2048;      // float Lsum[128]
constexpr int SMEM_TC = OFF_LSUM + 512;      // ~85 KB

#if HAS_TC

// K-major SW128 descriptor: LBO=1, SBO=64
constexpr unsigned long long DESC_BASE =
    (2ull << 61) | (1ull << 46) | (64ull << 32) | (1ull << 16);

__device__ __forceinline__ unsigned sm32(const void* p) {
  unsigned a;
  asm("{ .reg .u64 t; cvta.to.shared.u64 t, %1; cvt.u32.u64 %0, t; }" : "=r"(a) : "l"(p));
  return a;
}
__device__ __forceinline__ unsigned long long mkdesc(unsigned addr) {
  return DESC_BASE | ((unsigned long long)(addr >> 4) & 0x3FFF);
}
__device__ __forceinline__ unsigned swzb(unsigned off) { return off ^ ((off >> 3) & 0x70); }
__device__ __forceinline__ unsigned packh2(float a, float b) {
  __half2 t = __floats2half2_rn(a, b);
  return reinterpret_cast<unsigned&>(t);
}
__device__ __forceinline__ unsigned elect1() {
  unsigned p;
  asm volatile("{\n\t.reg .pred p;\n\telect.sync _|p, 0xFFFFFFFF;\n\tselp.b32 %0, 1, 0, p;\n\t}" : "=r"(p));
  return p;
}
__device__ __forceinline__ void mbar_init(unsigned mbar, unsigned cnt) {
  asm volatile("mbarrier.init.shared.b64 [%0], %1;" :: "r"(mbar), "r"(cnt) : "memory");
}
__device__ __forceinline__ void mbar_wait(unsigned mbar, unsigned parity) {
  asm volatile(
      "{\n\t.reg .pred P1;\n\t"
      "LWAIT_%=:\n\t"
      "mbarrier.try_wait.parity.acquire.cta.shared::cta.b64 P1, [%0], %1, 0x989680;\n\t"
      "@P1 bra.uni LDONE_%=;\n\t"
      "bra.uni LWAIT_%=;\n\t"
      "LDONE_%=:\n\t}"
      :: "r"(mbar), "r"(parity) : "memory");
}
__device__ __forceinline__ void tc_commit(unsigned mbar) {
  asm volatile(
      "tcgen05.commit.cta_group::1.mbarrier::arrive::one.shared::cluster.b64 [%0];"
      :: "r"(mbar) : "memory");
}
__device__ __forceinline__ void tc_alloc(unsigned dst, unsigned ncols) {
  asm volatile("tcgen05.alloc.cta_group::1.sync.aligned.shared::cta.b32 [%0], %1;"
               :: "r"(dst), "r"(ncols) : "memory");
}
__device__ __forceinline__ void tc_relinq() {
  asm volatile("tcgen05.relinquish_alloc_permit.cta_group::1.sync.aligned;");
}
__device__ __forceinline__ void tc_dealloc(unsigned base, unsigned ncols) {
  asm volatile("tcgen05.dealloc.cta_group::1.sync.aligned.b32 %0, %1;" :: "r"(base), "r"(ncols));
}
__device__ __forceinline__ void fence_before() {
  asm volatile("tcgen05.fence::before_thread_sync;" ::: "memory");
}
__device__ __forceinline__ void fence_after() {
  asm volatile("tcgen05.fence::after_thread_sync;" ::: "memory");
}
__device__ __forceinline__ void fence_proxy() {
  asm volatile("fence.proxy.async.shared::cta;" ::: "memory");
}
__device__ __forceinline__ void wait_ld() { asm volatile("tcgen05.wait::ld.sync.aligned;" ::: "memory"); }
__device__ __forceinline__ void wait_st() { asm volatile("tcgen05.wait::st.sync.aligned;" ::: "memory"); }

__device__ __forceinline__ void mma_ss(unsigned d, unsigned long long ad,
                                       unsigned long long bd, unsigned idesc, bool en) {
  unsigned e = en ? 1u : 0u;
  asm volatile(
      "{\n\t.reg .pred p;\n\tsetp.ne.u32 p, %5, 0;\n\t"
      "tcgen05.mma.cta_group::1.kind::f16 [%0], %1, %2, %3, {%4, %4, %4, %4}, p;\n\t}"
      :: "r"(d), "l"(ad), "l"(bd), "r"(idesc), "r"(0u), "r"(e) : "memory");
}
__device__ __forceinline__ void mma_ts(unsigned d, unsigned a,
                                       unsigned long long bd, unsigned idesc, bool en) {
  unsigned e = en ? 1u : 0u;
  asm volatile(
      "{\n\t.reg .pred p;\n\tsetp.ne.u32 p, %5, 0;\n\t"
      "tcgen05.mma.cta_group::1.kind::f16 [%0], [%1], %2, %3, {%4, %4, %4, %4}, p;\n\t}"
      :: "r"(d), "r"(a), "l"(bd), "r"(idesc), "r"(0u), "r"(e) : "memory");
}

#define TLD32(r, addr)                                                        \
  asm volatile(                                                               \
      "tcgen05.ld.sync.aligned.32x32b.x32.b32 "                               \
      "{%0, %1, %2, %3, %4, %5, %6, %7, "                                     \
      " %8, %9, %10, %11, %12, %13, %14, %15, "                               \
      " %16, %17, %18, %19, %20, %21, %22, %23, "                             \
      " %24, %25, %26, %27, %28, %29, %30, %31}, [%32];"                      \
      : "=r"((r)[0]),  "=r"((r)[1]),  "=r"((r)[2]),  "=r"((r)[3]),            \
        "=r"((r)[4]),  "=r"((r)[5]),  "=r"((r)[6]),  "=r"((r)[7]),            \
        "=r"((r)[8]),  "=r"((r)[9]),  "=r"((r)[10]), "=r"((r)[11]),           \
        "=r"((r)[12]), "=r"((r)[13]), "=r"((r)[14]), "=r"((r)[15]),           \
        "=r"((r)[16]), "=r"((r)[17]), "=r"((r)[18]), "=r"((r)[19]),           \
        "=r"((r)[20]), "=r"((r)[21]), "=r"((r)[22]), "=r"((r)[23]),           \
        "=r"((r)[24]), "=r"((r)[25]), "=r"((r)[26]), "=r"((r)[27]),           \
        "=r"((r)[28]), "=r"((r)[29]), "=r"((r)[30]), "=r"((r)[31])            \
      : "r"(addr))

#define TST16(addr, r)                                                        \
  asm volatile(                                                               \
      "tcgen05.st.sync.aligned.32x32b.x16.b32 [%0], "                         \
      "{%1, %2, %3, %4, %5, %6, %7, %8, "                                     \
      " %9, %10, %11, %12, %13, %14, %15, %16};"                              \
      :: "r"(addr),                                                           \
         "r"((r)[0]),  "r"((r)[1]),  "r"((r)[2]),  "r"((r)[3]),               \
         "r"((r)[4]),  "r"((r)[5]),  "r"((r)[6]),  "r"((r)[7]),               \
         "r"((r)[8]),  "r"((r)[9]),  "r"((r)[10]), "r"((r)[11]),              \
         "r"((r)[12]), "r"((r)[13]), "r"((r)[14]), "r"((r)[15])               \
      : "memory")

#endif  // HAS_TC

__global__ __launch_bounds__(256, 2)
void hybrid_attn_tc(const float* __restrict__ Q, const float* __restrict__ K,
                    const float* __restrict__ V, float* __restrict__ O) {
#if HAS_TC
  extern __shared__ char smc[];
  const unsigned sb = sm32(smc);
  const int tid = threadIdx.x;
  const int wid = tid >> 5;
  const int lane = tid & 31;
  const int sub = wid & 3;          // TMEM subpartition (SMSP = wid % 4)
  const int half = wid >> 2;        // column half this warp owns
  const int m0 = blockIdx.x * BMt;
  const int bh = blockIdx.y;
  const int base = ((bh >> 3) * Lc * Hc + (bh & 7)) * Ec;
  const float* Qg = Q + base;
  const float* Kg = K + base;
  const float* Vg = V + base;
  float* Og = O + base;

  if (tid == 0) { mbar_init(sb + OFF_MB_S, 1); mbar_init(sb + OFF_MB_O, 1); }
  if (wid == 0) { tc_alloc(sb + OFF_PTR, TM_COLS); tc_relinq(); }
  __syncthreads();
  unsigned tb;
  asm volatile("ld.shared.b32 %0, [%1];" : "=r"(tb) : "r"(sb + OFF_PTR));

  const unsigned long long dq = mkdesc(sb + OFF_QH);

  // ---- Q tile -> fp16 (SW128, 128B rows) ----
  #pragma unroll
  for (int it = 0; it < 8; ++it) {
    const int idx = tid + it * 256;
    const int r = idx >> 4, e4 = (idx & 15) << 2;
    const float4 q = *reinterpret_cast<const float4*>(&Qg[(m0 + r) * RE + e4]);
    const unsigned sw = swzb((unsigned)(r * 128 + e4 * 2));
    *reinterpret_cast<unsigned*>(smc + OFF_QH + sw)     = packh2(q.x, q.y);
    *reinterpret_cast<unsigned*>(smc + OFF_QH + sw + 4) = packh2(q.z, q.w);
  }

  unsigned ps = 0, po = 0;
  float lsum = 0.f;
  const unsigned woff = (unsigned)sub << 21;

  for (int nt = 0; nt < NTt; ++nt) {
    const int n0 = nt * BNt;
    const int kb = (nt & 1) ? OFF_K1 : OFF_K0;
    const int vb = (nt & 1) ? OFF_V1 : OFF_V0;

    // ---- load K [128 j][64 e] fp16 + V transposed halves ----
    #pragma unroll
    for (int it = 0; it < 8; ++it) {
      const int idx = tid + it * 256;
      const int j = idx >> 4, e4 = (idx & 15) << 2;
      const float4 kk = *reinterpret_cast<const float4*>(&Kg[(n0 + j) * RE + e4]);
      const unsigned sw = swzb((unsigned)(j * 128 + e4 * 2));
      *reinterpret_cast<unsigned*>(smc + kb + sw)     = packh2(kk.x, kk.y);
      *reinterpret_cast<unsigned*>(smc + kb + sw + 4) = packh2(kk.z, kk.w);
      const float4 vv = *reinterpret_cast<const float4*>(&Vg[(n0 + j) * RE + e4]);
      const int vhb = vb + ((j >> 6) << 13);       // +8192 for j >= 64
      const int jl = j & 63;
      #pragma unroll
      for (int t = 0; t < 4; ++t) {
        const float x = (t == 0) ? vv.x : (t == 1) ? vv.y : (t == 2) ? vv.z : vv.w;
        const unsigned sv = swzb((unsigned)((e4 + t) * 128 + jl * 2));
        *reinterpret_cast<__half*>(smc + vhb + sv) = __float2half_rn(x);
      }
    }
    fence_proxy();
    __syncthreads();

    // ---- S[128 q][128 j] = Q · K^T ----
    if (wid == 0 && elect1()) {
      const unsigned long long dk = mkdesc(sb + kb);
      #pragma unroll
      for (int k = 0; k < 4; ++k) mma_ss(tb + TM_S, dq + 2 * k, dk + 2 * k, IDESC_S, k > 0);
      tc_commit(sb + OFF_MB_S);
    }
    mbar_wait(sb + OFF_MB_S, ps); ps ^= 1;
    fence_after();

    // ---- epilogue: p = 2^(s*scl2e - bias), fp16, to PH; warp owns 64 j-cols ----
    #pragma unroll
    for (int hb = 0; hb < 2; ++hb) {
      unsigned sr[32];
      TLD32(sr, tb + TM_S + 64 * half + 32 * hb);
      wait_ld();
      unsigned ph[16];
      #pragma unroll
      for (int c = 0; c < 16; ++c) {
        const float s0 = __uint_as_float(sr[2 * c]);
        const float s1 = __uint_as_float(sr[2 * c + 1]);
        const float p0 = ex2f(fmaf(s0, SCL2E, -PBIAS));
        const float p1 = ex2f(fmaf(s1, SCL2E, -PBIAS));
        lsum += p0 + p1;
        ph[c] = packh2(p0, p1);
      }
      if (hb == 0 && nt > 0) { mbar_wait(sb + OFF_MB_O, po); po ^= 1; }
      TST16(tb + TM_PH + 32 * half + 16 * hb + woff, ph);
    }
    wait_st();
    fence_before();
    __syncthreads();

    // ---- O[128 q][64 e] += P · Vt (8 K-chunks of 16 j) ----
    if (wid == 0 && elect1()) {
      fence_after();
      fence_proxy();
      const unsigned long long dv0 = mkdesc(sb + vb), dv1 = mkdesc(sb + vb + 8192);
      #pragma unroll
      for (int k = 0; k < 8; ++k) {
        const unsigned long long bd = (k < 4) ? (dv0 + 2 * k) : (dv1 + 2 * (k - 4));
        mma_ts(tb + TM_O, tb + TM_PH + 8 * k, bd, IDESC_O, !(nt == 0 && k == 0));
      }
      tc_commit(sb + OFF_MB_O);
    }
  }

  mbar_wait(sb + OFF_MB_O, po);
  fence_after();

  // Each warp reads its 32-column half of O for its subpartition rows.
  unsigned orr[32];
  TLD32(orr, tb + TM_O + 32 * half);
  wait_ld();
  fence_before();

  float* Ls = reinterpret_cast<float*>(smc + OFF_LS);
  float* LsumS = reinterpret_cast<float*>(smc + OFF_LSUM);

  // ---- local branch scores: 2 (row, jj) pairs per thread ----
  {
    const int row = tid >> 1;
    const int jb = (tid & 1) << 1;
    #pragma unroll
    for (int t = 0; t < 2; ++t) {
      const int jj = jb + t;
      const int ig = m0 + row;
      const int j = ig - 2 + jj;
      float sc = -1e30f;
      if (j >= 0 && j < Lc) {
        const float* qrow = Qg + ig * RE;
        const float* krow = Kg + j * RE;
        float dot = 0.f;
        #pragma unroll 4
        for (int e4 = 0; e4 < Ec; e4 += 4) {
          const float4 q = *reinterpret_cast<const float4*>(&qrow[e4]);
          const float4 kk = *reinterpret_cast<const float4*>(&krow[e4]);
          dot += q.x * kk.x + q.y * kk.y + q.z * kk.z + q.w * kk.w;
        }
        sc = dot * SCL2E;
      }
      Ls[(row << 2) + jj] = sc;
    }
  }
  // ---- cross-warp lsum combine ----
  if (wid < 4) LsumS[sub * 32 + lane] = lsum;
  __syncthreads();
  if (wid >= 4) LsumS[sub * 32 + lane] += lsum;
  __syncthreads();

  // ---- combine global + local, write output (this warp's e-column half) ----
  {
    const int r = sub * 32 + lane;
    const int ig = m0 + r;
    const float4 lsc = *reinterpret_cast<const float4*>(&Ls[r << 2]);
    const float mx = fmaxf(fmaxf(lsc.x, lsc.y), fmaxf(lsc.z, lsc.w));
    const float w0 = ex2f(lsc.x - mx), w1 = ex2f(lsc.y - mx);
    const float w2 = ex2f(lsc.z - mx), w3 = ex2f(lsc.w - mx);
    const float winv = 1.f / (w0 + w1 + w2 + w3);
    const float n0w = w0 * winv, n1w = w1 * winv, n2w = w2 * winv, n3w = w3 * winv;
    const float invl = 1.f / LsumS[r];
    const bool b0 = (ig - 2) >= 0;
    const bool b1 = (ig - 1) >= 0;
    const bool b3 = (ig + 1) < Lc;
    const float* vp0 = Vg + (ig - 2) * RE;
    const float* vp1 = Vg + (ig - 1) * RE;
    const float* vp2 = Vg + ig * RE;
    const float* vp3 = Vg + (ig + 1) * RE;
    const int e0 = 32 * half;
    #pragma unroll
    for (int c4 = 0; c4 < 32; c4 += 4) {
      const int e4 = e0 + c4;
      float4 o;
      o.x = __uint_as_float(orr[c4 + 0]) * invl;
      o.y = __uint_as_float(orr[c4 + 1]) * invl;
      o.z = __uint_as_float(orr[c4 + 2]) * invl;
      o.w = __uint_as_float(orr[c4 + 3]) * invl;
      if (b0) { const float4 vv = *reinterpret_cast<const float4*>(&vp0[e4]);
                o.x += n0w * vv.x; o.y += n0w * vv.y; o.z += n0w * vv.z; o.w += n0w * vv.w; }
      if (b1) { const float4 vv = *reinterpret_cast<const float4*>(&vp1[e4]);
                o.x += n1w * vv.x; o.y += n1w * vv.y; o.z += n1w * vv.z; o.w += n1w * vv.w; }
      {       const float4 vv = *reinterpret_cast<const float4*>(&vp2[e4]);
                o.x += n2w * vv.x; o.y += n2w * vv.y; o.z += n2w * vv.z; o.w += n2w * vv.w; }
      if (b3) { const float4 vv = *reinterpret_cast<const float4*>(&vp3[e4]);
                o.x += n3w * vv.x; o.y += n3w * vv.y; o.z += n3w * vv.z; o.w += n3w * vv.w; }
      *reinterpret_cast<float4*>(&Og[ig * RE + e4]) = o;
    }
  }

  __syncthreads();
  if (wid == 0) tc_dealloc(tb, TM_COLS);
#endif  // HAS_TC
}

// ===================== SIMT fallback (plain sm_103 path) ====================

constexpr int BM = 64, BN = 128;
constexpr int TSQ = 68;
constexpr int TSK = 132;
constexpr int OFF_Q = 0;
constexpr int OFF_KP = OFF_Q + Ec * TSQ;
constexpr int OFF_V = OFF_KP + 64 * TSK;
constexpr int OFF_L = OFF_V + BN * Ec;
constexpr int SMEM_FLOATS = OFF_L + BM * 4;

#if !HAS_TC
__device__ __forceinline__ void fma2(ull& d, ull a, ull b) {
  asm("fma.rn.f32x2 %0, %1, %2, %0;" : "+l"(d) : "l"(a), "l"(b));
}
__device__ __forceinline__ void mul2(ull& d, ull a) {
  asm("mul.rn.f32x2 %0, %0, %1;" : "+l"(d) : "l"(a));
}
__device__ __forceinline__ ull bcast2(float x) {
  ull r; asm("mov.b64 %0, {%1, %1};" : "=l"(r) : "f"(x)); return r;
}
__device__ __forceinline__ void unp2(ull v, float& lo, float& hi) {
  asm("mov.b64 {%0, %1}, %2;" : "=f"(lo), "=f"(hi) : "l"(v));
}
#endif

__global__ __launch_bounds__(128, 2)
void hybrid_attn_simt(const float* __restrict__ Q, const float* __restrict__ K,
                      const float* __restrict__ V, float* __restrict__ O) {
#if !HAS_TC
  extern __shared__ float smf[];
  float* Qs = smf + OFF_Q;
  float* KP = smf + OFF_KP;
  float* Vs = smf + OFF_V;
  float* Ls = smf + OFF_L;

  const int tid = threadIdx.x;
  const int tx = tid & 15;
  const int ty = tid >> 4;
  const int r0 = ty << 3;
  const int c0 = tx << 2;
  const int c1 = 64 + c0;

  const int m0 = blockIdx.x * BM;
  const int bh = blockIdx.y;
  const int base = ((bh >> 3) * Lc * Hc + (bh & 7)) * Ec;
  const float* Qg = Q + base;
  const float* Kg = K + base;
  const float* Vg = V + base;
  float* Og = O + base;

  const int le4 = (tid & 15) << 2;
  const int lr = tid >> 4;

  #pragma unroll
  for (int it = 0; it < 8; ++it) {
    const int r = lr + it * 8;
    const float4 q = *reinterpret_cast<const float4*>(&Qg[(m0 + r) * RE + le4]);
    Qs[(le4 + 0) * TSQ + r] = q.x * SCL2E;
    Qs[(le4 + 1) * TSQ + r] = q.y * SCL2E;
    Qs[(le4 + 2) * TSQ + r] = q.z * SCL2E;
    Qs[(le4 + 3) * TSQ + r] = q.w * SCL2E;
  }

  float mi[8], li[8];
  ull acc[8][2];
  #pragma unroll
  for (int i = 0; i < 8; ++i) { mi[i] = -1e30f; li[i] = 0.f; acc[i][0] = 0ull; acc[i][1] = 0ull; }

  for (int n0 = 0; n0 < Lc; n0 += BN) {
    __syncthreads();
    #pragma unroll
    for (int it = 0; it < 16; ++it) {
      const int r = lr + it * 8;
      const float4 kk = *reinterpret_cast<const float4*>(&Kg[(n0 + r) * RE + le4]);
      KP[(le4 + 0) * TSK + r] = kk.x;
      KP[(le4 + 1) * TSK + r] = kk.y;
      KP[(le4 + 2) * TSK + r] = kk.z;
      KP[(le4 + 3) * TSK + r] = kk.w;
      const float4 vv = *reinterpret_cast<const float4*>(&Vg[(n0 + r) * RE + le4]);
      *reinterpret_cast<float4*>(&Vs[r * Ec + le4]) = vv;
    }
    __syncthreads();

    ull s[8][4];
    #pragma unroll
    for (int i = 0; i < 8; ++i)
      #pragma unroll
      for (int p = 0; p < 4; ++p) s[i][p] = 0ull;

    #pragma unroll 4
    for (int e = 0; e < Ec; ++e) {
      const ulonglong2 b0 = *reinterpret_cast<const ulonglong2*>(&KP[e * TSK + c0]);
      const ulonglong2 b1 = *reinterpret_cast<const ulonglong2*>(&KP[e * TSK + c1]);
      const float4 a0 = *reinterpret_cast<const float4*>(&Qs[e * TSQ + r0]);
      const float4 a1 = *reinterpret_cast<const float4*>(&Qs[e * TSQ + r0 + 4]);
      ull aa;
      aa = bcast2(a0.x); fma2(s[0][0], aa, b0.x); fma2(s[0][1], aa, b0.y); fma2(s[0][2], aa, b1.x); fma2(s[0][3], aa, b1.y);
      aa = bcast2(a0.y); fma2(s[1][0], aa, b0.x); fma2(s[1][1], aa, b0.y); fma2(s[1][2], aa, b1.x); fma2(s[1][3], aa, b1.y);
      aa = bcast2(a0.z); fma2(s[2][0], aa, b0.x); fma2(s[2][1], aa, b0.y); fma2(s[2][2], aa, b1.x); fma2(s[2][3], aa, b1.y);
      aa = bcast2(a0.w); fma2(s[3][0], aa, b0.x); fma2(s[3][1], aa, b0.y); fma2(s[3][2], aa, b1.x); fma2(s[3][3], aa, b1.y);
      aa = bcast2(a1.x); fma2(s[4][0], aa, b0.x); fma2(s[4][1], aa, b0.y); fma2(s[4][2], aa, b1.x); fma2(s[4][3], aa, b1.y);
      aa = bcast2(a1.y); fma2(s[5][0], aa, b0.x); fma2(s[5][1], aa, b0.y); fma2(s[5][2], aa, b1.x); fma2(s[5][3], aa, b1.y);
      aa = bcast2(a1.z); fma2(s[6][0], aa, b0.x); fma2(s[6][1], aa, b0.y); fma2(s[6][2], aa, b1.x); fma2(s[6][3], aa, b1.y);
      aa = bcast2(a1.w); fma2(s[7][0], aa, b0.x); fma2(s[7][1], aa, b0.y); fma2(s[7][2], aa, b1.x); fma2(s[7][3], aa, b1.y);
    }
    __syncthreads();

    #pragma unroll
    for (int i = 0; i < 8; ++i) {
      float v0, v1, v2, v3, v4, v5, v6, v7;
      unp2(s[i][0], v0, v1); unp2(s[i][1], v2, v3);
      unp2(s[i][2], v4, v5); unp2(s[i][3], v6, v7);
      float tm = fmaxf(fmaxf(fmaxf(v0, v1), fmaxf(v2, v3)),
                       fmaxf(fmaxf(v4, v5), fmaxf(v6, v7)));
      #pragma unroll
      for (int off = 8; off; off >>= 1)
        tm = fmaxf(tm, __shfl_xor_sync(0xffffffffu, tm, off));
      const float newm = fmaxf(mi[i], tm);
      const float fac = ex2f(mi[i] - newm);
      v0 = ex2f(v0 - newm); v1 = ex2f(v1 - newm); v2 = ex2f(v2 - newm); v3 = ex2f(v3 - newm);
      v4 = ex2f(v4 - newm); v5 = ex2f(v5 - newm); v6 = ex2f(v6 - newm); v7 = ex2f(v7 - newm);
      float psum = (v0 + v1) + (v2 + v3) + (v4 + v5) + (v6 + v7);
      #pragma unroll
      for (int off = 8; off; off >>= 1)
        psum += __shfl_xor_sync(0xffffffffu, psum, off);
      li[i] = li[i] * fac + psum;
      mi[i] = newm;
      const ull fv = bcast2(fac);
      mul2(acc[i][0], fv); mul2(acc[i][1], fv);
      *reinterpret_cast<float4*>(&KP[(r0 + i) * TSK + c0]) = make_float4(v0, v1, v2, v3);
      *reinterpret_cast<float4*>(&KP[(r0 + i) * TSK + c1]) = make_float4(v4, v5, v6, v7);
    }
    __syncthreads();

    #pragma unroll 2
    for (int j0 = 0; j0 < BN; j0 += 4) {
      const ulonglong2 w0 = *reinterpret_cast<const ulonglong2*>(&Vs[(j0 + 0) * Ec + c0]);
      const ulonglong2 w1 = *reinterpret_cast<const ulonglong2*>(&Vs[(j0 + 1) * Ec + c0]);
      const ulonglong2 w2 = *reinterpret_cast<const ulonglong2*>(&Vs[(j0 + 2) * Ec + c0]);
      const ulonglong2 w3 = *reinterpret_cast<const ulonglong2*>(&Vs[(j0 + 3) * Ec + c0]);
      #pragma unroll
      for (int i = 0; i < 8; ++i) {
        const float4 p = *reinterpret_cast<const float4*>(&KP[(r0 + i) * TSK + j0]);
        ull aa;
        aa = bcast2(p.x); fma2(acc[i][0], aa, w0.x); fma2(acc[i][1], aa, w0.y);
        aa = bcast2(p.y); fma2(acc[i][0], aa, w1.x); fma2(acc[i][1], aa, w1.y);
        aa = bcast2(p.z); fma2(acc[i][0], aa, w2.x); fma2(acc[i][1], aa, w2.y);
        aa = bcast2(p.w); fma2(acc[i][0], aa, w3.x); fma2(acc[i][1], aa, w3.y);
      }
    }
  }

  __syncthreads();
  {
    const int row = tid >> 1;
    const int jbase = (tid & 1) << 1;
    #pragma unroll
    for (int t = 0; t < 2; ++t) {
      const int jj = jbase + t;
      const int ig = m0 + row;
      const int j = ig - 2 + jj;
      float sc = -1e30f;
      if (j >= 0 && j < Lc) {
        float dot = 0.f;
        #pragma unroll
        for (int e4 = 0; e4 < Ec; e4 += 4) {
          const float4 kk = *reinterpret_cast<const float4*>(&Kg[j * RE + e4]);
          dot += Qs[(e4 + 0) * TSQ + row] * kk.x
               + Qs[(e4 + 1) * TSQ + row] * kk.y
               + Qs[(e4 + 2) * TSQ + row] * kk.z
               + Qs[(e4 + 3) * TSQ + row] * kk.w;
        }
        sc = dot;
      }
      Ls[(row << 2) + jj] = sc;
    }
  }
  __syncthreads();

  #pragma unroll
  for (int i = 0; i < 8; ++i) {
    const int r = r0 + i;
    const int ig = m0 + r;
    const float4 lsc = *reinterpret_cast<const float4*>(&Ls[r << 2]);
    const float mx = fmaxf(fmaxf(lsc.x, lsc.y), fmaxf(lsc.z, lsc.w));
    float w[4];
    w[0] = ex2f(lsc.x - mx); w[1] = ex2f(lsc.y - mx);
    w[2] = ex2f(lsc.z - mx); w[3] = ex2f(lsc.w - mx);
    const float winv = 1.f / (w[0] + w[1] + w[2] + w[3]);
    const float invl = 1.f / li[i];
    float o0, o1, o2, o3;
    unp2(acc[i][0], o0, o1); unp2(acc[i][1], o2, o3);
    float4 outv = make_float4(o0 * invl, o1 * invl, o2 * invl, o3 * invl);
    #pragma unroll
    for (int jj = 0; jj < 4; ++jj) {
      const int j = ig - 2 + jj;
      if (j >= 0 && j < Lc) {
        const float wj = w[jj] * winv;
        const float4 v = *reinterpret_cast<const float4*>(&Vg[j * RE + c0]);
        outv.x += wj * v.x; outv.y += wj * v.y;
        outv.z += wj * v.z; outv.w += wj * v.w;
      }
    }
    *reinterpret_cast<float4*>(&Og[ig * RE + c0]) = outv;
  }
#endif  // !HAS_TC
}

}  // namespace

extern "C" void kernel_launch(void* const* d_in, const int* in_sizes, int n_in,
                              void* d_out, int out_size) {
  const float* Q = (const float*)d_in[0];
  const float* K = (const float*)d_in[1];
  const float* V = (const float*)d_in[2];
  float* O = (float*)d_out;

  cudaFuncSetAttribute(hybrid_attn_tc, cudaFuncAttributeMaxDynamicSharedMemorySize, SMEM_TC);
  const size_t smemS = (size_t)SMEM_FLOATS * sizeof(float);
  cudaFuncSetAttribute(hybrid_attn_simt, cudaFuncAttributeMaxDynamicSharedMemorySize, (int)smemS);

  dim3 gridTC(Lc / BMt, 4 * Hc);
  hybrid_attn_tc<<<gridTC, 256, SMEM_TC>>>(Q, K, V, O);
  dim3 gridS(Lc / BM, 4 * Hc);
  hybrid_attn_simt<<<gridS, 128, smemS>>>(Q, K, V, O);
}

// round 13
// speedup vs baseline: 6.9255x; 1.2302x over previous
#include <cuda_runtime.h>
#include <cuda_fp16.h>
#include <cstdint>

// tcgen05 is only legal on arch-specific (sm_103a/sm_100a) device passes.
#if defined(__CUDA_ARCH_FEAT_SM103_ALL) || defined(__CUDA_ARCH_FEAT_SM100_ALL) || \
    defined(__CUDA_ARCH_FEAT_SM101_ALL) ||                                        \
    (defined(__CUDA_ARCH_SPECIFIC__) && (__CUDA_ARCH_SPECIFIC__ >= 1000)) ||       \
    (defined(__CUDA_ARCH_FAMILY_SPECIFIC__) && (__CUDA_ARCH_FAMILY_SPECIFIC__ >= 1000))
#define HAS_TC 1
#else
#define HAS_TC 0
#endif

namespace {

using ull = unsigned long long;

constexpr int Lc = 2048, Hc = 8, Ec = 64;
constexpr int RE = Hc * Ec;                  // 512
constexpr float SCL2E = 0.125f * 1.44269504088896340736f;

__device__ __forceinline__ float ex2f(float x) {
  float y; asm("ex2.approx.ftz.f32 %0, %1;" : "=f"(y) : "f"(x)); return y;
}

// ======================= TC kernel (sm_103a path) ==========================

constexpr int BMt = 128, BNt = 128;
constexpr int NTt = Lc / BNt;                // 16 key tiles
constexpr float PBIAS = 4.0f;
constexpr unsigned IDESC_S = 0x08200010u;    // kind::f16: F32 acc, f16, M=128, N=128
constexpr unsigned IDESC_O = 0x08100010u;    // kind::f16: F32 acc, f16, M=128, N=64

// TMEM columns (256 total, 2 CTAs/SM)
constexpr unsigned TM_S = 0;       // 128 cols: S[128 q][128 j] fp32
constexpr unsigned TM_O = 128;     // 64 cols:  O[128 q][64 e] fp32
constexpr unsigned TM_PH = 192;    // 64 cols:  P[128 q][128 j] fp16 packed
constexpr unsigned TM_COLS = 256;

constexpr int OFF_PTR = 0, OFF_MB_S = 8, OFF_MB_O = 16;
constexpr int OFF_QH = 1024;                 // Q fp16 [128 q][64 e], 128B rows
constexpr int OFF_K0 = OFF_QH + 16384;       // K fp16 [128 j][64 e], 128B rows
constexpr int OFF_K1 = OFF_K0 + 16384;
constexpr int OFF_V0 = OFF_K1 + 16384;       // Vt fp16: half0 [64 e][j 0..63] @+0, half1 @+8192
constexpr int OFF_V1 = OFF_V0 + 16384;
constexpr int OFF_LS = OFF_V1 + 16384;       // float Ls[128][4]
constexpr int OFF_LSUM = OFF_LS + 2048;      // float Lsum[128]
constexpr int SMEM_TC = OFF_LSUM + 512;      // ~85 KB

#if HAS_TC

// K-major SW128 descriptor: LBO=1, SBO=64
constexpr unsigned long long DESC_BASE =
    (2ull << 61) | (1ull << 46) | (64ull << 32) | (1ull << 16);

__device__ __forceinline__ unsigned sm32(const void* p) {
  unsigned a;
  asm("{ .reg .u64 t; cvta.to.shared.u64 t, %1; cvt.u32.u64 %0, t; }" : "=r"(a) : "l"(p));
  return a;
}
__device__ __forceinline__ unsigned long long mkdesc(unsigned addr) {
  return DESC_BASE | ((unsigned long long)(addr >> 4) & 0x3FFF);
}
__device__ __forceinline__ unsigned swzb(unsigned off) { return off ^ ((off >> 3) & 0x70); }
__device__ __forceinline__ unsigned packh2(float a, float b) {
  __half2 t = __floats2half2_rn(a, b);
  return reinterpret_cast<unsigned&>(t);
}
__device__ __forceinline__ unsigned elect1() {
  unsigned p;
  asm volatile("{\n\t.reg .pred p;\n\telect.sync _|p, 0xFFFFFFFF;\n\tselp.b32 %0, 1, 0, p;\n\t}" : "=r"(p));
  return p;
}
__device__ __forceinline__ void mbar_init(unsigned mbar, unsigned cnt) {
  asm volatile("mbarrier.init.shared.b64 [%0], %1;" :: "r"(mbar), "r"(cnt) : "memory");
}
__device__ __forceinline__ void mbar_wait(unsigned mbar, unsigned parity) {
  asm volatile(
      "{\n\t.reg .pred P1;\n\t"
      "LWAIT_%=:\n\t"
      "mbarrier.try_wait.parity.acquire.cta.shared::cta.b64 P1, [%0], %1, 0x989680;\n\t"
      "@P1 bra.uni LDONE_%=;\n\t"
      "bra.uni LWAIT_%=;\n\t"
      "LDONE_%=:\n\t}"
      :: "r"(mbar), "r"(parity) : "memory");
}
__device__ __forceinline__ void tc_commit(unsigned mbar) {
  asm volatile(
      "tcgen05.commit.cta_group::1.mbarrier::arrive::one.shared::cluster.b64 [%0];"
      :: "r"(mbar) : "memory");
}
__device__ __forceinline__ void tc_alloc(unsigned dst, unsigned ncols) {
  asm volatile("tcgen05.alloc.cta_group::1.sync.aligned.shared::cta.b32 [%0], %1;"
               :: "r"(dst), "r"(ncols) : "memory");
}
__device__ __forceinline__ void tc_relinq() {
  asm volatile("tcgen05.relinquish_alloc_permit.cta_group::1.sync.aligned;");
}
__device__ __forceinline__ void tc_dealloc(unsigned base, unsigned ncols) {
  asm volatile("tcgen05.dealloc.cta_group::1.sync.aligned.b32 %0, %1;" :: "r"(base), "r"(ncols));
}
__device__ __forceinline__ void fence_before() {
  asm volatile("tcgen05.fence::before_thread_sync;" ::: "memory");
}
__device__ __forceinline__ void fence_after() {
  asm volatile("tcgen05.fence::after_thread_sync;" ::: "memory");
}
__device__ __forceinline__ void fence_proxy() {
  asm volatile("fence.proxy.async.shared::cta;" ::: "memory");
}
__device__ __forceinline__ void wait_ld() { asm volatile("tcgen05.wait::ld.sync.aligned;" ::: "memory"); }
__device__ __forceinline__ void wait_st() { asm volatile("tcgen05.wait::st.sync.aligned;" ::: "memory"); }

__device__ __forceinline__ void mma_ss(unsigned d, unsigned long long ad,
                                       unsigned long long bd, unsigned idesc, bool en) {
  unsigned e = en ? 1u : 0u;
  asm volatile(
      "{\n\t.reg .pred p;\n\tsetp.ne.u32 p, %5, 0;\n\t"
      "tcgen05.mma.cta_group::1.kind::f16 [%0], %1, %2, %3, {%4, %4, %4, %4}, p;\n\t}"
      :: "r"(d), "l"(ad), "l"(bd), "r"(idesc), "r"(0u), "r"(e) : "memory");
}
__device__ __forceinline__ void mma_ts(unsigned d, unsigned a,
                                       unsigned long long bd, unsigned idesc, bool en) {
  unsigned e = en ? 1u : 0u;
  asm volatile(
      "{\n\t.reg .pred p;\n\tsetp.ne.u32 p, %5, 0;\n\t"
      "tcgen05.mma.cta_group::1.kind::f16 [%0], [%1], %2, %3, {%4, %4, %4, %4}, p;\n\t}"
      :: "r"(d), "r"(a), "l"(bd), "r"(idesc), "r"(0u), "r"(e) : "memory");
}

#define TLD32(r, addr)                                                        \
  asm volatile(                                                               \
      "tcgen05.ld.sync.aligned.32x32b.x32.b32 "                               \
      "{%0, %1, %2, %3, %4, %5, %6, %7, "                                     \
      " %8, %9, %10, %11, %12, %13, %14, %15, "                               \
      " %16, %17, %18, %19, %20, %21, %22, %23, "                             \
      " %24, %25, %26, %27, %28, %29, %30, %31}, [%32];"                      \
      : "=r"((r)[0]),  "=r"((r)[1]),  "=r"((r)[2]),  "=r"((r)[3]),            \
        "=r"((r)[4]),  "=r"((r)[5]),  "=r"((r)[6]),  "=r"((r)[7]),            \
        "=r"((r)[8]),  "=r"((r)[9]),  "=r"((r)[10]), "=r"((r)[11]),           \
        "=r"((r)[12]), "=r"((r)[13]), "=r"((r)[14]), "=r"((r)[15]),           \
        "=r"((r)[16]), "=r"((r)[17]), "=r"((r)[18]), "=r"((r)[19]),           \
        "=r"((r)[20]), "=r"((r)[21]), "=r"((r)[22]), "=r"((r)[23]),           \
        "=r"((r)[24]), "=r"((r)[25]), "=r"((r)[26]), "=r"((r)[27]),           \
        "=r"((r)[28]), "=r"((r)[29]), "=r"((r)[30]), "=r"((r)[31])            \
      : "r"(addr))

#define TST16(addr, r)                                                        \
  asm volatile(                                                               \
      "tcgen05.st.sync.aligned.32x32b.x16.b32 [%0], "                         \
      "{%1, %2, %3, %4, %5, %6, %7, %8, "                                     \
      " %9, %10, %11, %12, %13, %14, %15, %16};"                              \
      :: "r"(addr),                                                           \
         "r"((r)[0]),  "r"((r)[1]),  "r"((r)[2]),  "r"((r)[3]),               \
         "r"((r)[4]),  "r"((r)[5]),  "r"((r)[6]),  "r"((r)[7]),               \
         "r"((r)[8]),  "r"((r)[9]),  "r"((r)[10]), "r"((r)[11]),              \
         "r"((r)[12]), "r"((r)[13]), "r"((r)[14]), "r"((r)[15])               \
      : "memory")

#endif  // HAS_TC

__global__ __launch_bounds__(256, 2)
void hybrid_attn_tc(const float* __restrict__ Q, const float* __restrict__ K,
                    const float* __restrict__ V, float* __restrict__ O) {
#if HAS_TC
  extern __shared__ char smc[];
  const unsigned sb = sm32(smc);
  const int tid = threadIdx.x;
  const int wid = tid >> 5;
  const int lane = tid & 31;
  const int sub = wid & 3;          // TMEM subpartition (SMSP = wid % 4)
  const int half = wid >> 2;        // column half this warp owns
  const int m0 = blockIdx.x * BMt;
  const int bh = blockIdx.y;
  const int base = ((bh >> 3) * Lc * Hc + (bh & 7)) * Ec;
  const float* Qg = Q + base;
  const float* Kg = K + base;
  const float* Vg = V + base;
  float* Og = O + base;

  if (tid == 0) { mbar_init(sb + OFF_MB_S, 1); mbar_init(sb + OFF_MB_O, 1); }
  if (wid == 0) { tc_alloc(sb + OFF_PTR, TM_COLS); tc_relinq(); }
  __syncthreads();
  unsigned tb;
  asm volatile("ld.shared.b32 %0, [%1];" : "=r"(tb) : "r"(sb + OFF_PTR));

  const unsigned long long dq = mkdesc(sb + OFF_QH);

  // ---- Q tile -> fp16 (SW128, 128B rows) ----
  #pragma unroll
  for (int it = 0; it < 8; ++it) {
    const int idx = tid + it * 256;
    const int r = idx >> 4, e4 = (idx & 15) << 2;
    const float4 q = *reinterpret_cast<const float4*>(&Qg[(m0 + r) * RE + e4]);
    const unsigned sw = swzb((unsigned)(r * 128 + e4 * 2));
    *reinterpret_cast<unsigned*>(smc + OFF_QH + sw)     = packh2(q.x, q.y);
    *reinterpret_cast<unsigned*>(smc + OFF_QH + sw + 4) = packh2(q.z, q.w);
  }

  // ---- K/V tile 0 ----
  #pragma unroll
  for (int it = 0; it < 8; ++it) {
    const int idx = tid + it * 256;
    const int j = idx >> 4, e4 = (idx & 15) << 2;
    const float4 kk = *reinterpret_cast<const float4*>(&Kg[j * RE + e4]);
    const unsigned sw = swzb((unsigned)(j * 128 + e4 * 2));
    *reinterpret_cast<unsigned*>(smc + OFF_K0 + sw)     = packh2(kk.x, kk.y);
    *reinterpret_cast<unsigned*>(smc + OFF_K0 + sw + 4) = packh2(kk.z, kk.w);
  }
  #pragma unroll
  for (int it = 0; it < 4; ++it) {          // paired V transpose: 2 j-rows per thread
    const int idx = tid + it * 256;
    const int jp = idx >> 4, e4 = (idx & 15) << 2;
    const int j0 = jp << 1;
    const float4 a = *reinterpret_cast<const float4*>(&Vg[(j0 + 0) * RE + e4]);
    const float4 b = *reinterpret_cast<const float4*>(&Vg[(j0 + 1) * RE + e4]);
    const int vhb = OFF_V0 + ((j0 >> 6) << 13);
    const int jl = j0 & 63;
    *reinterpret_cast<unsigned*>(smc + vhb + swzb((unsigned)((e4 + 0) * 128 + jl * 2))) = packh2(a.x, b.x);
    *reinterpret_cast<unsigned*>(smc + vhb + swzb((unsigned)((e4 + 1) * 128 + jl * 2))) = packh2(a.y, b.y);
    *reinterpret_cast<unsigned*>(smc + vhb + swzb((unsigned)((e4 + 2) * 128 + jl * 2))) = packh2(a.z, b.z);
    *reinterpret_cast<unsigned*>(smc + vhb + swzb((unsigned)((e4 + 3) * 128 + jl * 2))) = packh2(a.w, b.w);
  }
  fence_proxy();
  __syncthreads();

  // ---- S-MMA(0) ----
  if (wid == 0 && elect1()) {
    const unsigned long long dk = mkdesc(sb + OFF_K0);
    #pragma unroll
    for (int k = 0; k < 4; ++k) mma_ss(tb + TM_S, dq + 2 * k, dk + 2 * k, IDESC_S, k > 0);
    tc_commit(sb + OFF_MB_S);
  }

  unsigned ps = 0, po = 0;
  float lsum = 0.f;
  const unsigned woff = (unsigned)sub << 21;

  for (int nt = 0; nt < NTt; ++nt) {
    const int kb = (nt & 1) ? OFF_K1 : OFF_K0;
    const int vb = (nt & 1) ? OFF_V1 : OFF_V0;
    const int kb2 = (nt & 1) ? OFF_K0 : OFF_K1;
    const int vb2 = (nt & 1) ? OFF_V0 : OFF_V1;

    // ---- load K(nt+1); its prior reader S(nt-1) already completed ----
    if (nt + 1 < NTt) {
      const int n0 = (nt + 1) * BNt;
      #pragma unroll
      for (int it = 0; it < 8; ++it) {
        const int idx = tid + it * 256;
        const int j = idx >> 4, e4 = (idx & 15) << 2;
        const float4 kk = *reinterpret_cast<const float4*>(&Kg[(n0 + j) * RE + e4]);
        const unsigned sw = swzb((unsigned)(j * 128 + e4 * 2));
        *reinterpret_cast<unsigned*>(smc + kb2 + sw)     = packh2(kk.x, kk.y);
        *reinterpret_cast<unsigned*>(smc + kb2 + sw + 4) = packh2(kk.z, kk.w);
      }
    }

    // ---- O(nt-1) must finish before V-buffer and P reuse ----
    if (nt > 0) { mbar_wait(sb + OFF_MB_O, po); po ^= 1; }

    // ---- load V(nt+1), paired transpose ----
    if (nt + 1 < NTt) {
      const int n0 = (nt + 1) * BNt;
      #pragma unroll
      for (int it = 0; it < 4; ++it) {
        const int idx = tid + it * 256;
        const int jp = idx >> 4, e4 = (idx & 15) << 2;
        const int j0 = jp << 1;
        const float4 a = *reinterpret_cast<const float4*>(&Vg[(n0 + j0 + 0) * RE + e4]);
        const float4 b = *reinterpret_cast<const float4*>(&Vg[(n0 + j0 + 1) * RE + e4]);
        const int vhb = vb2 + ((j0 >> 6) << 13);
        const int jl = j0 & 63;
        *reinterpret_cast<unsigned*>(smc + vhb + swzb((unsigned)((e4 + 0) * 128 + jl * 2))) = packh2(a.x, b.x);
        *reinterpret_cast<unsigned*>(smc + vhb + swzb((unsigned)((e4 + 1) * 128 + jl * 2))) = packh2(a.y, b.y);
        *reinterpret_cast<unsigned*>(smc + vhb + swzb((unsigned)((e4 + 2) * 128 + jl * 2))) = packh2(a.z, b.z);
        *reinterpret_cast<unsigned*>(smc + vhb + swzb((unsigned)((e4 + 3) * 128 + jl * 2))) = packh2(a.w, b.w);
      }
    }
    fence_proxy();

    // ---- wait S(nt), drain it fully into registers ----
    mbar_wait(sb + OFF_MB_S, ps); ps ^= 1;
    fence_after();
    unsigned sr[64];
    TLD32(sr, tb + TM_S + 64 * half);
    TLD32(sr + 32, tb + TM_S + 64 * half + 32);
    wait_ld();
    fence_before();
    __syncthreads();   // all warps drained S; K/V(nt+1) stores visible

    // ---- issue S-MMA(nt+1) into the (now free) S buffer; overlaps exp work ----
    if (nt + 1 < NTt && wid == 0 && elect1()) {
      fence_after();
      const unsigned long long dk = mkdesc(sb + kb2);
      #pragma unroll
      for (int k = 0; k < 4; ++k) mma_ss(tb + TM_S, dq + 2 * k, dk + 2 * k, IDESC_S, k > 0);
      tc_commit(sb + OFF_MB_S);
    }

    // ---- epilogue: p = 2^(s*scl2e - bias), fp16, to PH ----
    #pragma unroll
    for (int hb = 0; hb < 2; ++hb) {
      unsigned ph[16];
      #pragma unroll
      for (int c = 0; c < 16; ++c) {
        const float s0 = __uint_as_float(sr[32 * hb + 2 * c]);
        const float s1 = __uint_as_float(sr[32 * hb + 2 * c + 1]);
        const float p0 = ex2f(fmaf(s0, SCL2E, -PBIAS));
        const float p1 = ex2f(fmaf(s1, SCL2E, -PBIAS));
        lsum += p0 + p1;
        ph[c] = packh2(p0, p1);
      }
      TST16(tb + TM_PH + 32 * half + 16 * hb + woff, ph);
    }
    wait_st();
    fence_before();
    __syncthreads();

    // ---- O[128 q][64 e] += P · Vt (8 K-chunks of 16 j) ----
    if (wid == 0 && elect1()) {
      fence_after();
      fence_proxy();
      const unsigned long long dv0 = mkdesc(sb + vb), dv1 = mkdesc(sb + vb + 8192);
      #pragma unroll
      for (int k = 0; k < 8; ++k) {
        const unsigned long long bd = (k < 4) ? (dv0 + 2 * k) : (dv1 + 2 * (k - 4));
        mma_ts(tb + TM_O, tb + TM_PH + 8 * k, bd, IDESC_O, !(nt == 0 && k == 0));
      }
      tc_commit(sb + OFF_MB_O);
    }
  }

  mbar_wait(sb + OFF_MB_O, po);
  fence_after();

  // Each warp reads its 32-column half of O for its subpartition rows.
  unsigned orr[32];
  TLD32(orr, tb + TM_O + 32 * half);
  wait_ld();
  fence_before();

  float* Ls = reinterpret_cast<float*>(smc + OFF_LS);
  float* LsumS = reinterpret_cast<float*>(smc + OFF_LSUM);

  // ---- local branch scores: 2 (row, jj) pairs per thread ----
  {
    const int row = tid >> 1;
    const int jb = (tid & 1) << 1;
    #pragma unroll
    for (int t = 0; t < 2; ++t) {
      const int jj = jb + t;
      const int ig = m0 + row;
      const int j = ig - 2 + jj;
      float sc = -1e30f;
      if (j >= 0 && j < Lc) {
        const float* qrow = Qg + ig * RE;
        const float* krow = Kg + j * RE;
        float dot = 0.f;
        #pragma unroll 4
        for (int e4 = 0; e4 < Ec; e4 += 4) {
          const float4 q = *reinterpret_cast<const float4*>(&qrow[e4]);
          const float4 kk = *reinterpret_cast<const float4*>(&krow[e4]);
          dot += q.x * kk.x + q.y * kk.y + q.z * kk.z + q.w * kk.w;
        }
        sc = dot * SCL2E;
      }
      Ls[(row << 2) + jj] = sc;
    }
  }
  // ---- cross-warp lsum combine ----
  if (wid < 4) LsumS[sub * 32 + lane] = lsum;
  __syncthreads();
  if (wid >= 4) LsumS[sub * 32 + lane] += lsum;
  __syncthreads();

  // ---- combine global + local, write output (this warp's e-column half) ----
  {
    const int r = sub * 32 + lane;
    const int ig = m0 + r;
    const float4 lsc = *reinterpret_cast<const float4*>(&Ls[r << 2]);
    const float mx = fmaxf(fmaxf(lsc.x, lsc.y), fmaxf(lsc.z, lsc.w));
    const float w0 = ex2f(lsc.x - mx), w1 = ex2f(lsc.y - mx);
    const float w2 = ex2f(lsc.z - mx), w3 = ex2f(lsc.w - mx);
    const float winv = 1.f / (w0 + w1 + w2 + w3);
    const float n0w = w0 * winv, n1w = w1 * winv, n2w = w2 * winv, n3w = w3 * winv;
    const float invl = 1.f / LsumS[r];
    const bool b0 = (ig - 2) >= 0;
    const bool b1 = (ig - 1) >= 0;
    const bool b3 = (ig + 1) < Lc;
    const float* vp0 = Vg + (ig - 2) * RE;
    const float* vp1 = Vg + (ig - 1) * RE;
    const float* vp2 = Vg + ig * RE;
    const float* vp3 = Vg + (ig + 1) * RE;
    const int e0 = 32 * half;
    #pragma unroll
    for (int c4 = 0; c4 < 32; c4 += 4) {
      const int e4 = e0 + c4;
      float4 o;
      o.x = __uint_as_float(orr[c4 + 0]) * invl;
      o.y = __uint_as_float(orr[c4 + 1]) * invl;
      o.z = __uint_as_float(orr[c4 + 2]) * invl;
      o.w = __uint_as_float(orr[c4 + 3]) * invl;
      if (b0) { const float4 vv = *reinterpret_cast<const float4*>(&vp0[e4]);
                o.x += n0w * vv.x; o.y += n0w * vv.y; o.z += n0w * vv.z; o.w += n0w * vv.w; }
      if (b1) { const float4 vv = *reinterpret_cast<const float4*>(&vp1[e4]);
                o.x += n1w * vv.x; o.y += n1w * vv.y; o.z += n1w * vv.z; o.w += n1w * vv.w; }
      {       const float4 vv = *reinterpret_cast<const float4*>(&vp2[e4]);
                o.x += n2w * vv.x; o.y += n2w * vv.y; o.z += n2w * vv.z; o.w += n2w * vv.w; }
      if (b3) { const float4 vv = *reinterpret_cast<const float4*>(&vp3[e4]);
                o.x += n3w * vv.x; o.y += n3w * vv.y; o.z += n3w * vv.z; o.w += n3w * vv.w; }
      *reinterpret_cast<float4*>(&Og[ig * RE + e4]) = o;
    }
  }

  __syncthreads();
  if (wid == 0) tc_dealloc(tb, TM_COLS);
#endif  // HAS_TC
}

// ===================== SIMT fallback (plain sm_103 path) ====================

constexpr int BM = 64, BN = 128;
constexpr int TSQ = 68;
constexpr int TSK = 132;
constexpr int OFF_Q = 0;
constexpr int OFF_KP = OFF_Q + Ec * TSQ;
constexpr int OFF_V = OFF_KP + 64 * TSK;
constexpr int OFF_L = OFF_V + BN * Ec;
constexpr int SMEM_FLOATS = OFF_L + BM * 4;

#if !HAS_TC
__device__ __forceinline__ void fma2(ull& d, ull a, ull b) {
  asm("fma.rn.f32x2 %0, %1, %2, %0;" : "+l"(d) : "l"(a), "l"(b));
}
__device__ __forceinline__ void mul2(ull& d, ull a) {
  asm("mul.rn.f32x2 %0, %0, %1;" : "+l"(d) : "l"(a));
}
__device__ __forceinline__ ull bcast2(float x) {
  ull r; asm("mov.b64 %0, {%1, %1};" : "=l"(r) : "f"(x)); return r;
}
__device__ __forceinline__ void unp2(ull v, float& lo, float& hi) {
  asm("mov.b64 {%0, %1}, %2;" : "=f"(lo), "=f"(hi) : "l"(v));
}
#endif

__global__ __launch_bounds__(128, 2)
void hybrid_attn_simt(const float* __restrict__ Q, const float* __restrict__ K,
                      const float* __restrict__ V, float* __restrict__ O) {
#if !HAS_TC
  extern __shared__ float smf[];
  float* Qs = smf + OFF_Q;
  float* KP = smf + OFF_KP;
  float* Vs = smf + OFF_V;
  float* Ls = smf + OFF_L;

  const int tid = threadIdx.x;
  const int tx = tid & 15;
  const int ty = tid >> 4;
  const int r0 = ty << 3;
  const int c0 = tx << 2;
  const int c1 = 64 + c0;

  const int m0 = blockIdx.x * BM;
  const int bh = blockIdx.y;
  const int base = ((bh >> 3) * Lc * Hc + (bh & 7)) * Ec;
  const float* Qg = Q + base;
  const float* Kg = K + base;
  const float* Vg = V + base;
  float* Og = O + base;

  const int le4 = (tid & 15) << 2;
  const int lr = tid >> 4;

  #pragma unroll
  for (int it = 0; it < 8; ++it) {
    const int r = lr + it * 8;
    const float4 q = *reinterpret_cast<const float4*>(&Qg[(m0 + r) * RE + le4]);
    Qs[(le4 + 0) * TSQ + r] = q.x * SCL2E;
    Qs[(le4 + 1) * TSQ + r] = q.y * SCL2E;
    Qs[(le4 + 2) * TSQ + r] = q.z * SCL2E;
    Qs[(le4 + 3) * TSQ + r] = q.w * SCL2E;
  }

  float mi[8], li[8];
  ull acc[8][2];
  #pragma unroll
  for (int i = 0; i < 8; ++i) { mi[i] = -1e30f; li[i] = 0.f; acc[i][0] = 0ull; acc[i][1] = 0ull; }

  for (int n0 = 0; n0 < Lc; n0 += BN) {
    __syncthreads();
    #pragma unroll
    for (int it = 0; it < 16; ++it) {
      const int r = lr + it * 8;
      const float4 kk = *reinterpret_cast<const float4*>(&Kg[(n0 + r) * RE + le4]);
      KP[(le4 + 0) * TSK + r] = kk.x;
      KP[(le4 + 1) * TSK + r] = kk.y;
      KP[(le4 + 2) * TSK + r] = kk.z;
      KP[(le4 + 3) * TSK + r] = kk.w;
      const float4 vv = *reinterpret_cast<const float4*>(&Vg[(n0 + r) * RE + le4]);
      *reinterpret_cast<float4*>(&Vs[r * Ec + le4]) = vv;
    }
    __syncthreads();

    ull s[8][4];
    #pragma unroll
    for (int i = 0; i < 8; ++i)
      #pragma unroll
      for (int p = 0; p < 4; ++p) s[i][p] = 0ull;

    #pragma unroll 4
    for (int e = 0; e < Ec; ++e) {
      const ulonglong2 b0 = *reinterpret_cast<const ulonglong2*>(&KP[e * TSK + c0]);
      const ulonglong2 b1 = *reinterpret_cast<const ulonglong2*>(&KP[e * TSK + c1]);
      const float4 a0 = *reinterpret_cast<const float4*>(&Qs[e * TSQ + r0]);
      const float4 a1 = *reinterpret_cast<const float4*>(&Qs[e * TSQ + r0 + 4]);
      ull aa;
      aa = bcast2(a0.x); fma2(s[0][0], aa, b0.x); fma2(s[0][1], aa, b0.y); fma2(s[0][2], aa, b1.x); fma2(s[0][3], aa, b1.y);
      aa = bcast2(a0.y); fma2(s[1][0], aa, b0.x); fma2(s[1][1], aa, b0.y); fma2(s[1][2], aa, b1.x); fma2(s[1][3], aa, b1.y);
      aa = bcast2(a0.z); fma2(s[2][0], aa, b0.x); fma2(s[2][1], aa, b0.y); fma2(s[2][2], aa, b1.x); fma2(s[2][3], aa, b1.y);
      aa = bcast2(a0.w); fma2(s[3][0], aa, b0.x); fma2(s[3][1], aa, b0.y); fma2(s[3][2], aa, b1.x); fma2(s[3][3], aa, b1.y);
      aa = bcast2(a1.x); fma2(s[4][0], aa, b0.x); fma2(s[4][1], aa, b0.y); fma2(s[4][2], aa, b1.x); fma2(s[4][3], aa, b1.y);
      aa = bcast2(a1.y); fma2(s[5][0], aa, b0.x); fma2(s[5][1], aa, b0.y); fma2(s[5][2], aa, b1.x); fma2(s[5][3], aa, b1.y);
      aa = bcast2(a1.z); fma2(s[6][0], aa, b0.x); fma2(s[6][1], aa, b0.y); fma2(s[6][2], aa, b1.x); fma2(s[6][3], aa, b1.y);
      aa = bcast2(a1.w); fma2(s[7][0], aa, b0.x); fma2(s[7][1], aa, b0.y); fma2(s[7][2], aa, b1.x); fma2(s[7][3], aa, b1.y);
    }
    __syncthreads();

    #pragma unroll
    for (int i = 0; i < 8; ++i) {
      float v0, v1, v2, v3, v4, v5, v6, v7;
      unp2(s[i][0], v0, v1); unp2(s[i][1], v2, v3);
      unp2(s[i][2], v4, v5); unp2(s[i][3], v6, v7);
      float tm = fmaxf(fmaxf(fmaxf(v0, v1), fmaxf(v2, v3)),
                       fmaxf(fmaxf(v4, v5), fmaxf(v6, v7)));
      #pragma unroll
      for (int off = 8; off; off >>= 1)
        tm = fmaxf(tm, __shfl_xor_sync(0xffffffffu, tm, off));
      const float newm = fmaxf(mi[i], tm);
      const float fac = ex2f(mi[i] - newm);
      v0 = ex2f(v0 - newm); v1 = ex2f(v1 - newm); v2 = ex2f(v2 - newm); v3 = ex2f(v3 - newm);
      v4 = ex2f(v4 - newm); v5 = ex2f(v5 - newm); v6 = ex2f(v6 - newm); v7 = ex2f(v7 - newm);
      float psum = (v0 + v1) + (v2 + v3) + (v4 + v5) + (v6 + v7);
      #pragma unroll
      for (int off = 8; off; off >>= 1)
        psum += __shfl_xor_sync(0xffffffffu, psum, off);
      li[i] = li[i] * fac + psum;
      mi[i] = newm;
      const ull fv = bcast2(fac);
      mul2(acc[i][0], fv); mul2(acc[i][1], fv);
      *reinterpret_cast<float4*>(&KP[(r0 + i) * TSK + c0]) = make_float4(v0, v1, v2, v3);
      *reinterpret_cast<float4*>(&KP[(r0 + i) * TSK + c1]) = make_float4(v4, v5, v6, v7);
    }
    __syncthreads();

    #pragma unroll 2
    for (int j0 = 0; j0 < BN; j0 += 4) {
      const ulonglong2 w0 = *reinterpret_cast<const ulonglong2*>(&Vs[(j0 + 0) * Ec + c0]);
      const ulonglong2 w1 = *reinterpret_cast<const ulonglong2*>(&Vs[(j0 + 1) * Ec + c0]);
      const ulonglong2 w2 = *reinterpret_cast<const ulonglong2*>(&Vs[(j0 + 2) * Ec + c0]);
      const ulonglong2 w3 = *reinterpret_cast<const ulonglong2*>(&Vs[(j0 + 3) * Ec + c0]);
      #pragma unroll
      for (int i = 0; i < 8; ++i) {
        const float4 p = *reinterpret_cast<const float4*>(&KP[(r0 + i) * TSK + j0]);
        ull aa;
        aa = bcast2(p.x); fma2(acc[i][0], aa, w0.x); fma2(acc[i][1], aa, w0.y);
        aa = bcast2(p.y); fma2(acc[i][0], aa, w1.x); fma2(acc[i][1], aa, w1.y);
        aa = bcast2(p.z); fma2(acc[i][0], aa, w2.x); fma2(acc[i][1], aa, w2.y);
        aa = bcast2(p.w); fma2(acc[i][0], aa, w3.x); fma2(acc[i][1], aa, w3.y);
      }
    }
  }

  __syncthreads();
  {
    const int row = tid >> 1;
    const int jbase = (tid & 1) << 1;
    #pragma unroll
    for (int t = 0; t < 2; ++t) {
      const int jj = jbase + t;
      const int ig = m0 + row;
      const int j = ig - 2 + jj;
      float sc = -1e30f;
      if (j >= 0 && j < Lc) {
        float dot = 0.f;
        #pragma unroll
        for (int e4 = 0; e4 < Ec; e4 += 4) {
          const float4 kk = *reinterpret_cast<const float4*>(&Kg[j * RE + e4]);
          dot += Qs[(e4 + 0) * TSQ + row] * kk.x
               + Qs[(e4 + 1) * TSQ + row] * kk.y
               + Qs[(e4 + 2) * TSQ + row] * kk.z
               + Qs[(e4 + 3) * TSQ + row] * kk.w;
        }
        sc = dot;
      }
      Ls[(row << 2) + jj] = sc;
    }
  }
  __syncthreads();

  #pragma unroll
  for (int i = 0; i < 8; ++i) {
    const int r = r0 + i;
    const int ig = m0 + r;
    const float4 lsc = *reinterpret_cast<const float4*>(&Ls[r << 2]);
    const float mx = fmaxf(fmaxf(lsc.x, lsc.y), fmaxf(lsc.z, lsc.w));
    float w[4];
    w[0] = ex2f(lsc.x - mx); w[1] = ex2f(lsc.y - mx);
    w[2] = ex2f(lsc.z - mx); w[3] = ex2f(lsc.w - mx);
    const float winv = 1.f / (w[0] + w[1] + w[2] + w[3]);
    const float invl = 1.f / li[i];
    float o0, o1, o2, o3;
    unp2(acc[i][0], o0, o1); unp2(acc[i][1], o2, o3);
    float4 outv = make_float4(o0 * invl, o1 * invl, o2 * invl, o3 * invl);
    #pragma unroll
    for (int jj = 0; jj < 4; ++jj) {
      const int j = ig - 2 + jj;
      if (j >= 0 && j < Lc) {
        const float wj = w[jj] * winv;
        const float4 v = *reinterpret_cast<const float4*>(&Vg[j * RE + c0]);
        outv.x += wj * v.x; outv.y += wj * v.y;
        outv.z += wj * v.z; outv.w += wj * v.w;
      }
    }
    *reinterpret_cast<float4*>(&Og[ig * RE + c0]) = outv;
  }
#endif  // !HAS_TC
}

}  // namespace

extern "C" void kernel_launch(void* const* d_in, const int* in_sizes, int n_in,
                              void* d_out, int out_size) {
  const float* Q = (const float*)d_in[0];
  const float* K = (const float*)d_in[1];
  const float* V = (const float*)d_in[2];
  float* O = (float*)d_out;

  cudaFuncSetAttribute(hybrid_attn_tc, cudaFuncAttributeMaxDynamicSharedMemorySize, SMEM_TC);
  const size_t smemS = (size_t)SMEM_FLOATS * sizeof(float);
  cudaFuncSetAttribute(hybrid_attn_simt, cudaFuncAttributeMaxDynamicSharedMemorySize, (int)smemS);

  dim3 gridTC(Lc / BMt, 4 * Hc);
  hybrid_attn_tc<<<gridTC, 256, SMEM_TC>>>(Q, K, V, O);
  dim3 gridS(Lc / BM, 4 * Hc);
  hybrid_attn_simt<<<gridS, 128, smemS>>>(Q, K, V, O);
}

// round 14
// speedup vs baseline: 8.1863x; 1.1820x over previous
#include <cuda_runtime.h>
#include <cuda_fp16.h>
#include <cstdint>

// tcgen05 is only legal on arch-specific (sm_103a/sm_100a) device passes.
#if defined(__CUDA_ARCH_FEAT_SM103_ALL) || defined(__CUDA_ARCH_FEAT_SM100_ALL) || \
    defined(__CUDA_ARCH_FEAT_SM101_ALL) ||                                        \
    (defined(__CUDA_ARCH_SPECIFIC__) && (__CUDA_ARCH_SPECIFIC__ >= 1000)) ||       \
    (defined(__CUDA_ARCH_FAMILY_SPECIFIC__) && (__CUDA_ARCH_FAMILY_SPECIFIC__ >= 1000))
#define HAS_TC 1
#else
#define HAS_TC 0
#endif

namespace {

constexpr int Lc = 2048, Hc = 8, Ec = 64;
constexpr int RE = Hc * Ec;                  // 512
constexpr float SCL2E = 0.125f * 1.44269504088896340736f;

__device__ __forceinline__ float ex2f(float x) {
  float y; asm("ex2.approx.ftz.f32 %0, %1;" : "=f"(y) : "f"(x)); return y;
}
__device__ __forceinline__ unsigned packh2(float a, float b) {
  __half2 t = __floats2half2_rn(a, b);
  return reinterpret_cast<unsigned&>(t);
}

// fp16 scratch: K16g[bh][j][8 chunks of 16B, swizzle-permuted]
//               V16g[bh][jblk(32)][e(64)][8 chunks of 16B, swizzle-permuted]
__device__ __align__(16) __half K16g[32 * 2048 * 64];
__device__ __align__(16) __half V16g[32 * 2048 * 64];

// ======================= preprocessing kernels ==============================

__global__ __launch_bounds__(256)
void cvt_k(const float* __restrict__ K) {
  const int idx = blockIdx.x * 256 + threadIdx.x;   // 524288 chunks
  const int c = idx & 7;
  const int j = (idx >> 3) & 2047;
  const int bh = idx >> 14;
  const int b = bh >> 3, h = bh & 7;
  const float* src = K + ((size_t)(b * Lc + j) * Hc + h) * Ec + c * 8;
  const float4 a = *reinterpret_cast<const float4*>(src);
  const float4 d = *reinterpret_cast<const float4*>(src + 4);
  uint4 o;
  o.x = packh2(a.x, a.y); o.y = packh2(a.z, a.w);
  o.z = packh2(d.x, d.y); o.w = packh2(d.z, d.w);
  *reinterpret_cast<uint4*>(&K16g[(((size_t)bh * 2048 + j) * 8 + (c ^ (j & 7))) * 8]) = o;
}

__global__ __launch_bounds__(256)
void cvt_v(const float* __restrict__ V) {
  __shared__ __half sT[64 * 72];                    // [e][j-local], stride 72
  const int bh = blockIdx.x >> 5;
  const int jblk = blockIdx.x & 31;
  const int b = bh >> 3, h = bh & 7;
  const int j0 = jblk * 64;
  const int tid = threadIdx.x;

  #pragma unroll
  for (int it = 0; it < 4; ++it) {
    const int lin = tid + it * 256;
    const int r = lin >> 4;
    const int e4 = (lin & 15) << 2;
    const float4 v = *reinterpret_cast<const float4*>(
        V + ((size_t)(b * Lc + j0 + r) * Hc + h) * Ec + e4);
    sT[(e4 + 0) * 72 + r] = __float2half_rn(v.x);
    sT[(e4 + 1) * 72 + r] = __float2half_rn(v.y);
    sT[(e4 + 2) * 72 + r] = __float2half_rn(v.z);
    sT[(e4 + 3) * 72 + r] = __float2half_rn(v.w);
  }
  __syncthreads();
  #pragma unroll
  for (int it = 0; it < 2; ++it) {
    const int lin = tid + it * 256;
    const int e = lin >> 3;
    const int c = lin & 7;
    const uint4 val = *reinterpret_cast<const uint4*>(&sT[e * 72 + c * 8]);
    *reinterpret_cast<uint4*>(
        &V16g[((((size_t)bh * 32 + jblk) * 64 + e) * 8 + (c ^ (e & 7))) * 8]) = val;
  }
}

// ======================= TC kernel (sm_103a path) ==========================

constexpr int BMt = 128, BNt = 128;
constexpr int NTt = Lc / BNt;                // 16 key tiles
constexpr float PBIAS = 4.0f;
constexpr unsigned IDESC_S = 0x08200010u;    // kind::f16: F32 acc, f16, M=128, N=128
constexpr unsigned IDESC_O = 0x08100010u;    // kind::f16: F32 acc, f16, M=128, N=64

constexpr unsigned TM_S = 0;       // 128 cols: S[128 q][128 j] fp32
constexpr unsigned TM_O = 128;     // 64 cols:  O[128 q][64 e] fp32
constexpr unsigned TM_PH = 192;    // 64 cols:  P fp16 packed
constexpr unsigned TM_COLS = 256;

constexpr int OFF_PTR = 0, OFF_MB_S = 8, OFF_MB_O = 16;
constexpr int OFF_QH = 1024;                 // Q fp16 [128 q][64 e], 128B rows
constexpr int OFF_K0 = OFF_QH + 16384;
constexpr int OFF_K1 = OFF_K0 + 16384;
constexpr int OFF_V0 = OFF_K1 + 16384;       // Vt fp16: half0 @+0, half1 @+8192
constexpr int OFF_V1 = OFF_V0 + 16384;
constexpr int OFF_LS = OFF_V1 + 16384;       // float Ls[128][4]
constexpr int OFF_LSUM = OFF_LS + 2048;      // float Lsum[128]
constexpr int SMEM_TC = OFF_LSUM + 512;

#if HAS_TC

constexpr unsigned long long DESC_BASE =
    (2ull << 61) | (1ull << 46) | (64ull << 32) | (1ull << 16);

__device__ __forceinline__ unsigned sm32(const void* p) {
  unsigned a;
  asm("{ .reg .u64 t; cvta.to.shared.u64 t, %1; cvt.u32.u64 %0, t; }" : "=r"(a) : "l"(p));
  return a;
}
__device__ __forceinline__ unsigned long long mkdesc(unsigned addr) {
  return DESC_BASE | ((unsigned long long)(addr >> 4) & 0x3FFF);
}
__device__ __forceinline__ unsigned swzb(unsigned off) { return off ^ ((off >> 3) & 0x70); }
__device__ __forceinline__ unsigned elect1() {
  unsigned p;
  asm volatile("{\n\t.reg .pred p;\n\telect.sync _|p, 0xFFFFFFFF;\n\tselp.b32 %0, 1, 0, p;\n\t}" : "=r"(p));
  return p;
}
__device__ __forceinline__ void mbar_init(unsigned mbar, unsigned cnt) {
  asm volatile("mbarrier.init.shared.b64 [%0], %1;" :: "r"(mbar), "r"(cnt) : "memory");
}
__device__ __forceinline__ void mbar_wait(unsigned mbar, unsigned parity) {
  asm volatile(
      "{\n\t.reg .pred P1;\n\t"
      "LWAIT_%=:\n\t"
      "mbarrier.try_wait.parity.acquire.cta.shared::cta.b64 P1, [%0], %1, 0x989680;\n\t"
      "@P1 bra.uni LDONE_%=;\n\t"
      "bra.uni LWAIT_%=;\n\t"
      "LDONE_%=:\n\t}"
      :: "r"(mbar), "r"(parity) : "memory");
}
__device__ __forceinline__ void tc_commit(unsigned mbar) {
  asm volatile(
      "tcgen05.commit.cta_group::1.mbarrier::arrive::one.shared::cluster.b64 [%0];"
      :: "r"(mbar) : "memory");
}
__device__ __forceinline__ void tc_alloc(unsigned dst, unsigned ncols) {
  asm volatile("tcgen05.alloc.cta_group::1.sync.aligned.shared::cta.b32 [%0], %1;"
               :: "r"(dst), "r"(ncols) : "memory");
}
__device__ __forceinline__ void tc_relinq() {
  asm volatile("tcgen05.relinquish_alloc_permit.cta_group::1.sync.aligned;");
}
__device__ __forceinline__ void tc_dealloc(unsigned base, unsigned ncols) {
  asm volatile("tcgen05.dealloc.cta_group::1.sync.aligned.b32 %0, %1;" :: "r"(base), "r"(ncols));
}
__device__ __forceinline__ void fence_before() {
  asm volatile("tcgen05.fence::before_thread_sync;" ::: "memory");
}
__device__ __forceinline__ void fence_after() {
  asm volatile("tcgen05.fence::after_thread_sync;" ::: "memory");
}
__device__ __forceinline__ void fence_proxy() {
  asm volatile("fence.proxy.async.shared::cta;" ::: "memory");
}
__device__ __forceinline__ void wait_ld() { asm volatile("tcgen05.wait::ld.sync.aligned;" ::: "memory"); }
__device__ __forceinline__ void wait_st() { asm volatile("tcgen05.wait::st.sync.aligned;" ::: "memory"); }

__device__ __forceinline__ void mma_ss(unsigned d, unsigned long long ad,
                                       unsigned long long bd, unsigned idesc, bool en) {
  unsigned e = en ? 1u : 0u;
  asm volatile(
      "{\n\t.reg .pred p;\n\tsetp.ne.u32 p, %5, 0;\n\t"
      "tcgen05.mma.cta_group::1.kind::f16 [%0], %1, %2, %3, {%4, %4, %4, %4}, p;\n\t}"
      :: "r"(d), "l"(ad), "l"(bd), "r"(idesc), "r"(0u), "r"(e) : "memory");
}
__device__ __forceinline__ void mma_ts(unsigned d, unsigned a,
                                       unsigned long long bd, unsigned idesc, bool en) {
  unsigned e = en ? 1u : 0u;
  asm volatile(
      "{\n\t.reg .pred p;\n\tsetp.ne.u32 p, %5, 0;\n\t"
      "tcgen05.mma.cta_group::1.kind::f16 [%0], [%1], %2, %3, {%4, %4, %4, %4}, p;\n\t}"
      :: "r"(d), "r"(a), "l"(bd), "r"(idesc), "r"(0u), "r"(e) : "memory");
}

#define TLD32(r, addr)                                                        \
  asm volatile(                                                               \
      "tcgen05.ld.sync.aligned.32x32b.x32.b32 "                               \
      "{%0, %1, %2, %3, %4, %5, %6, %7, "                                     \
      " %8, %9, %10, %11, %12, %13, %14, %15, "                               \
      " %16, %17, %18, %19, %20, %21, %22, %23, "                             \
      " %24, %25, %26, %27, %28, %29, %30, %31}, [%32];"                      \
      : "=r"((r)[0]),  "=r"((r)[1]),  "=r"((r)[2]),  "=r"((r)[3]),            \
        "=r"((r)[4]),  "=r"((r)[5]),  "=r"((r)[6]),  "=r"((r)[7]),            \
        "=r"((r)[8]),  "=r"((r)[9]),  "=r"((r)[10]), "=r"((r)[11]),           \
        "=r"((r)[12]), "=r"((r)[13]), "=r"((r)[14]), "=r"((r)[15]),           \
        "=r"((r)[16]), "=r"((r)[17]), "=r"((r)[18]), "=r"((r)[19]),           \
        "=r"((r)[20]), "=r"((r)[21]), "=r"((r)[22]), "=r"((r)[23]),           \
        "=r"((r)[24]), "=r"((r)[25]), "=r"((r)[26]), "=r"((r)[27]),           \
        "=r"((r)[28]), "=r"((r)[29]), "=r"((r)[30]), "=r"((r)[31])            \
      : "r"(addr))

#define TST16(addr, r)                                                        \
  asm volatile(                                                               \
      "tcgen05.st.sync.aligned.32x32b.x16.b32 [%0], "                         \
      "{%1, %2, %3, %4, %5, %6, %7, %8, "                                     \
      " %9, %10, %11, %12, %13, %14, %15, %16};"                              \
      :: "r"(addr),                                                           \
         "r"((r)[0]),  "r"((r)[1]),  "r"((r)[2]),  "r"((r)[3]),               \
         "r"((r)[4]),  "r"((r)[5]),  "r"((r)[6]),  "r"((r)[7]),               \
         "r"((r)[8]),  "r"((r)[9]),  "r"((r)[10]), "r"((r)[11]),              \
         "r"((r)[12]), "r"((r)[13]), "r"((r)[14]), "r"((r)[15])               \
      : "memory")

#endif  // HAS_TC

__global__ __launch_bounds__(256, 2)
void hybrid_attn_tc(const float* __restrict__ Q, const float* __restrict__ K,
                    const float* __restrict__ V, float* __restrict__ O) {
#if HAS_TC
  extern __shared__ char smc[];
  const unsigned sb = sm32(smc);
  const int tid = threadIdx.x;
  const int wid = tid >> 5;
  const int lane = tid & 31;
  const int sub = wid & 3;          // TMEM subpartition (SMSP = wid % 4)
  const int half = wid >> 2;        // column half this warp owns
  const int m0 = blockIdx.x * BMt;
  const int bh = blockIdx.y;
  const int base = ((bh >> 3) * Lc * Hc + (bh & 7)) * Ec;
  const float* Qg = Q + base;
  const float* Kg = K + base;
  const float* Vg = V + base;
  float* Og = O + base;
  const __half* K16 = K16g + (size_t)bh * 2048 * 64;
  const __half* V16 = V16g + (size_t)bh * 2048 * 64;

  if (tid == 0) { mbar_init(sb + OFF_MB_S, 1); mbar_init(sb + OFF_MB_O, 1); }
  if (wid == 0) { tc_alloc(sb + OFF_PTR, TM_COLS); tc_relinq(); }
  __syncthreads();
  unsigned tb;
  asm volatile("ld.shared.b32 %0, [%1];" : "=r"(tb) : "r"(sb + OFF_PTR));

  const unsigned long long dq = mkdesc(sb + OFF_QH);

  // ---- Q tile -> fp16 (SW128, 128B rows), converted in-kernel (once) ----
  #pragma unroll
  for (int it = 0; it < 8; ++it) {
    const int idx = tid + it * 256;
    const int r = idx >> 4, e4 = (idx & 15) << 2;
    const float4 q = *reinterpret_cast<const float4*>(&Qg[(m0 + r) * RE + e4]);
    const unsigned sw = swzb((unsigned)(r * 128 + e4 * 2));
    *reinterpret_cast<unsigned*>(smc + OFF_QH + sw)     = packh2(q.x, q.y);
    *reinterpret_cast<unsigned*>(smc + OFF_QH + sw + 4) = packh2(q.z, q.w);
  }

  // ---- K/V tile 0: bulk copy from preconverted scratch ----
  #pragma unroll
  for (int it = 0; it < 4; ++it) {
    const int lin = tid + it * 256;         // 1024 chunks of 16B
    const uint4 kd = *reinterpret_cast<const uint4*>(&K16[(size_t)lin * 8]);
    *reinterpret_cast<uint4*>(smc + OFF_K0 + lin * 16) = kd;
    const uint4 vd = *reinterpret_cast<const uint4*>(&V16[(size_t)lin * 8]);
    *reinterpret_cast<uint4*>(smc + OFF_V0 + lin * 16) = vd;
  }
  fence_proxy();
  __syncthreads();

  // ---- S-MMA(0) ----
  if (wid == 0 && elect1()) {
    const unsigned long long dk = mkdesc(sb + OFF_K0);
    #pragma unroll
    for (int k = 0; k < 4; ++k) mma_ss(tb + TM_S, dq + 2 * k, dk + 2 * k, IDESC_S, k > 0);
    tc_commit(sb + OFF_MB_S);
  }

  unsigned ps = 0, po = 0;
  float lsum = 0.f;
  const unsigned woff = (unsigned)sub << 21;

  for (int nt = 0; nt < NTt; ++nt) {
    const int vb = (nt & 1) ? OFF_V1 : OFF_V0;
    const int kb2 = (nt & 1) ? OFF_K0 : OFF_K1;
    const int vb2 = (nt & 1) ? OFF_V0 : OFF_V1;

    // ---- load K(nt+1): prior reader S(nt-1) already completed ----
    if (nt + 1 < NTt) {
      const __half* ks = K16 + (size_t)(nt + 1) * 128 * 64;
      #pragma unroll
      for (int it = 0; it < 4; ++it) {
        const int lin = tid + it * 256;
        const uint4 kd = *reinterpret_cast<const uint4*>(&ks[(size_t)lin * 8]);
        *reinterpret_cast<uint4*>(smc + kb2 + lin * 16) = kd;
      }
    }

    // ---- O(nt-1) must finish before V-buffer and P reuse ----
    if (nt > 0) { mbar_wait(sb + OFF_MB_O, po); po ^= 1; }

    // ---- load V(nt+1) (pre-transposed) ----
    if (nt + 1 < NTt) {
      const __half* vs = V16 + (size_t)(nt + 1) * 128 * 64;
      #pragma unroll
      for (int it = 0; it < 4; ++it) {
        const int lin = tid + it * 256;
        const uint4 vd = *reinterpret_cast<const uint4*>(&vs[(size_t)lin * 8]);
        *reinterpret_cast<uint4*>(smc + vb2 + lin * 16) = vd;
      }
    }
    fence_proxy();

    // ---- wait S(nt), drain it fully into registers ----
    mbar_wait(sb + OFF_MB_S, ps); ps ^= 1;
    fence_after();
    unsigned sr[64];
    TLD32(sr, tb + TM_S + 64 * half);
    TLD32(sr + 32, tb + TM_S + 64 * half + 32);
    wait_ld();
    fence_before();
    __syncthreads();   // all warps drained S; K/V(nt+1) stores visible

    // ---- issue S-MMA(nt+1) into the (now free) S buffer; overlaps exp work ----
    if (nt + 1 < NTt && wid == 0 && elect1()) {
      fence_after();
      const unsigned long long dk = mkdesc(sb + kb2);
      #pragma unroll
      for (int k = 0; k < 4; ++k) mma_ss(tb + TM_S, dq + 2 * k, dk + 2 * k, IDESC_S, k > 0);
      tc_commit(sb + OFF_MB_S);
    }

    // ---- epilogue: p = 2^(s*scl2e - bias), fp16, to PH ----
    #pragma unroll
    for (int hb = 0; hb < 2; ++hb) {
      unsigned ph[16];
      #pragma unroll
      for (int c = 0; c < 16; ++c) {
        const float s0 = __uint_as_float(sr[32 * hb + 2 * c]);
        const float s1 = __uint_as_float(sr[32 * hb + 2 * c + 1]);
        const float p0 = ex2f(fmaf(s0, SCL2E, -PBIAS));
        const float p1 = ex2f(fmaf(s1, SCL2E, -PBIAS));
        lsum += p0 + p1;
        ph[c] = packh2(p0, p1);
      }
      TST16(tb + TM_PH + 32 * half + 16 * hb + woff, ph);
    }
    wait_st();
    fence_before();
    __syncthreads();

    // ---- O[128 q][64 e] += P · Vt (8 K-chunks of 16 j) ----
    if (wid == 0 && elect1()) {
      fence_after();
      fence_proxy();
      const unsigned long long dv0 = mkdesc(sb + vb), dv1 = mkdesc(sb + vb + 8192);
      #pragma unroll
      for (int k = 0; k < 8; ++k) {
        const unsigned long long bd = (k < 4) ? (dv0 + 2 * k) : (dv1 + 2 * (k - 4));
        mma_ts(tb + TM_O, tb + TM_PH + 8 * k, bd, IDESC_O, !(nt == 0 && k == 0));
      }
      tc_commit(sb + OFF_MB_O);
    }
  }

  mbar_wait(sb + OFF_MB_O, po);
  fence_after();

  unsigned orr[32];
  TLD32(orr, tb + TM_O + 32 * half);
  wait_ld();
  fence_before();

  float* Ls = reinterpret_cast<float*>(smc + OFF_LS);
  float* LsumS = reinterpret_cast<float*>(smc + OFF_LSUM);

  // ---- local branch scores: 2 (row, jj) pairs per thread (fp32 from gmem) ----
  {
    const int row = tid >> 1;
    const int jb = (tid & 1) << 1;
    #pragma unroll
    for (int t = 0; t < 2; ++t) {
      const int jj = jb + t;
      const int ig = m0 + row;
      const int j = ig - 2 + jj;
      float sc = -1e30f;
      if (j >= 0 && j < Lc) {
        const float* qrow = Qg + ig * RE;
        const float* krow = Kg + j * RE;
        float dot = 0.f;
        #pragma unroll 4
        for (int e4 = 0; e4 < Ec; e4 += 4) {
          const float4 q = *reinterpret_cast<const float4*>(&qrow[e4]);
          const float4 kk = *reinterpret_cast<const float4*>(&krow[e4]);
          dot += q.x * kk.x + q.y * kk.y + q.z * kk.z + q.w * kk.w;
        }
        sc = dot * SCL2E;
      }
      Ls[(row << 2) + jj] = sc;
    }
  }
  // ---- cross-warp lsum combine ----
  if (wid < 4) LsumS[sub * 32 + lane] = lsum;
  __syncthreads();
  if (wid >= 4) LsumS[sub * 32 + lane] += lsum;
  __syncthreads();

  // ---- combine global + local, write output (this warp's e-column half) ----
  {
    const int r = sub * 32 + lane;
    const int ig = m0 + r;
    const float4 lsc = *reinterpret_cast<const float4*>(&Ls[r << 2]);
    const float mx = fmaxf(fmaxf(lsc.x, lsc.y), fmaxf(lsc.z, lsc.w));
    const float w0 = ex2f(lsc.x - mx), w1 = ex2f(lsc.y - mx);
    const float w2 = ex2f(lsc.z - mx), w3 = ex2f(lsc.w - mx);
    const float winv = 1.f / (w0 + w1 + w2 + w3);
    const float n0w = w0 * winv, n1w = w1 * winv, n2w = w2 * winv, n3w = w3 * winv;
    const float invl = 1.f / LsumS[r];
    const bool b0 = (ig - 2) >= 0;
    const bool b1 = (ig - 1) >= 0;
    const bool b3 = (ig + 1) < Lc;
    const float* vp0 = Vg + (ig - 2) * RE;
    const float* vp1 = Vg + (ig - 1) * RE;
    const float* vp2 = Vg + ig * RE;
    const float* vp3 = Vg + (ig + 1) * RE;
    const int e0 = 32 * half;
    #pragma unroll
    for (int c4 = 0; c4 < 32; c4 += 4) {
      const int e4 = e0 + c4;
      float4 o;
      o.x = __uint_as_float(orr[c4 + 0]) * invl;
      o.y = __uint_as_float(orr[c4 + 1]) * invl;
      o.z = __uint_as_float(orr[c4 + 2]) * invl;
      o.w = __uint_as_float(orr[c4 + 3]) * invl;
      if (b0) { const float4 vv = *reinterpret_cast<const float4*>(&vp0[e4]);
                o.x += n0w * vv.x; o.y += n0w * vv.y; o.z += n0w * vv.z; o.w += n0w * vv.w; }
      if (b1) { const float4 vv = *reinterpret_cast<const float4*>(&vp1[e4]);
                o.x += n1w * vv.x; o.y += n1w * vv.y; o.z += n1w * vv.z; o.w += n1w * vv.w; }
      {       const float4 vv = *reinterpret_cast<const float4*>(&vp2[e4]);
                o.x += n2w * vv.x; o.y += n2w * vv.y; o.z += n2w * vv.z; o.w += n2w * vv.w; }
      if (b3) { const float4 vv = *reinterpret_cast<const float4*>(&vp3[e4]);
                o.x += n3w * vv.x; o.y += n3w * vv.y; o.z += n3w * vv.z; o.w += n3w * vv.w; }
      *reinterpret_cast<float4*>(&Og[ig * RE + e4]) = o;
    }
  }

  __syncthreads();
  if (wid == 0) tc_dealloc(tb, TM_COLS);
#endif  // HAS_TC
}

}  // namespace

extern "C" void kernel_launch(void* const* d_in, const int* in_sizes, int n_in,
                              void* d_out, int out_size) {
  const float* Q = (const float*)d_in[0];
  const float* K = (const float*)d_in[1];
  const float* V = (const float*)d_in[2];
  float* O = (float*)d_out;

  cudaFuncSetAttribute(hybrid_attn_tc, cudaFuncAttributeMaxDynamicSharedMemorySize, SMEM_TC);

  cvt_k<<<2048, 256>>>(K);
  cvt_v<<<1024, 256>>>(V);

  dim3 gridTC(Lc / BMt, 4 * Hc);
  hybrid_attn_tc<<<gridTC, 256, SMEM_TC>>>(Q, K, V, O);
}

// round 15
// speedup vs baseline: 9.2141x; 1.1256x over previous
#include <cuda_runtime.h>
#include <cuda_fp16.h>
#include <cstdint>

// tcgen05 is only legal on arch-specific (sm_103a/sm_100a) device passes.
#if defined(__CUDA_ARCH_FEAT_SM103_ALL) || defined(__CUDA_ARCH_FEAT_SM100_ALL) || \
    defined(__CUDA_ARCH_FEAT_SM101_ALL) ||                                        \
    (defined(__CUDA_ARCH_SPECIFIC__) && (__CUDA_ARCH_SPECIFIC__ >= 1000)) ||       \
    (defined(__CUDA_ARCH_FAMILY_SPECIFIC__) && (__CUDA_ARCH_FAMILY_SPECIFIC__ >= 1000))
#define HAS_TC 1
#else
#define HAS_TC 0
#endif

namespace {

constexpr int Lc = 2048, Hc = 8, Ec = 64;
constexpr int RE = Hc * Ec;                  // 512
constexpr float SCL2E = 0.125f * 1.44269504088896340736f;

__device__ __forceinline__ float ex2f(float x) {
  float y; asm("ex2.approx.ftz.f32 %0, %1;" : "=f"(y) : "f"(x)); return y;
}
__device__ __forceinline__ unsigned packh2(float a, float b) {
  __half2 t = __floats2half2_rn(a, b);
  return reinterpret_cast<unsigned&>(t);
}

// fp16 scratch: K16g[bh][j][8 chunks of 16B, swizzle-permuted]
//               V16g[bh][jblk(32)][e(64)][8 chunks of 16B, swizzle-permuted]
__device__ __align__(16) __half K16g[32 * 2048 * 64];
__device__ __align__(16) __half V16g[32 * 2048 * 64];

// ======================= preprocessing kernels ==============================

__global__ __launch_bounds__(256)
void cvt_k(const float* __restrict__ K) {
  const int idx = blockIdx.x * 256 + threadIdx.x;   // 524288 chunks
  const int c = idx & 7;
  const int j = (idx >> 3) & 2047;
  const int bh = idx >> 14;
  const int b = bh >> 3, h = bh & 7;
  const float* src = K + ((size_t)(b * Lc + j) * Hc + h) * Ec + c * 8;
  const float4 a = *reinterpret_cast<const float4*>(src);
  const float4 d = *reinterpret_cast<const float4*>(src + 4);
  uint4 o;
  o.x = packh2(a.x, a.y); o.y = packh2(a.z, a.w);
  o.z = packh2(d.x, d.y); o.w = packh2(d.z, d.w);
  *reinterpret_cast<uint4*>(&K16g[(((size_t)bh * 2048 + j) * 8 + (c ^ (j & 7))) * 8]) = o;
}

__global__ __launch_bounds__(256)
void cvt_v(const float* __restrict__ V) {
  __shared__ __half sT[64 * 72];                    // [e][j-local], stride 72
  const int bh = blockIdx.x >> 5;
  const int jblk = blockIdx.x & 31;
  const int b = bh >> 3, h = bh & 7;
  const int j0 = jblk * 64;
  const int tid = threadIdx.x;

  #pragma unroll
  for (int it = 0; it < 4; ++it) {
    const int lin = tid + it * 256;
    const int r = lin >> 4;
    const int e4 = (lin & 15) << 2;
    const float4 v = *reinterpret_cast<const float4*>(
        V + ((size_t)(b * Lc + j0 + r) * Hc + h) * Ec + e4);
    sT[(e4 + 0) * 72 + r] = __float2half_rn(v.x);
    sT[(e4 + 1) * 72 + r] = __float2half_rn(v.y);
    sT[(e4 + 2) * 72 + r] = __float2half_rn(v.z);
    sT[(e4 + 3) * 72 + r] = __float2half_rn(v.w);
  }
  __syncthreads();
  #pragma unroll
  for (int it = 0; it < 2; ++it) {
    const int lin = tid + it * 256;
    const int e = lin >> 3;
    const int c = lin & 7;
    const uint4 val = *reinterpret_cast<const uint4*>(&sT[e * 72 + c * 8]);
    *reinterpret_cast<uint4*>(
        &V16g[((((size_t)bh * 32 + jblk) * 64 + e) * 8 + (c ^ (e & 7))) * 8]) = val;
  }
}

// ======================= TC kernel (sm_103a path) ==========================

constexpr int BMt = 128, BNt = 128;
constexpr int NTt = Lc / BNt;                // 16 key tiles
constexpr float PBIAS = 4.0f;
constexpr unsigned IDESC_S = 0x08200010u;    // kind::f16: F32 acc, f16, M=128, N=128
constexpr unsigned IDESC_O = 0x08100010u;    // kind::f16: F32 acc, f16, M=128, N=64

constexpr unsigned TM_S = 0;       // 128 cols: S[128 q][128 j] fp32
constexpr unsigned TM_O = 128;     // 64 cols:  O[128 q][64 e] fp32
constexpr unsigned TM_PH = 192;    // 64 cols:  P fp16 packed
constexpr unsigned TM_COLS = 256;

constexpr int OFF_PTR = 0, OFF_MB_S = 8, OFF_MB_O = 16, OFF_MB_L = 24;
constexpr int OFF_QH = 1024;                 // Q fp16 [128 q][64 e], 128B rows
constexpr int OFF_K0 = OFF_QH + 16384;
constexpr int OFF_K1 = OFF_K0 + 16384;
constexpr int OFF_V0 = OFF_K1 + 16384;       // Vt fp16: half0 @+0, half1 @+8192
constexpr int OFF_V1 = OFF_V0 + 16384;
constexpr int OFF_LS = OFF_V1 + 16384;       // float Ls[128][4]
constexpr int OFF_LSUM = OFF_LS + 2048;      // float Lsum[128]
constexpr int SMEM_TC = OFF_LSUM + 512;

#if HAS_TC

constexpr unsigned long long DESC_BASE =
    (2ull << 61) | (1ull << 46) | (64ull << 32) | (1ull << 16);

__device__ __forceinline__ unsigned sm32(const void* p) {
  unsigned a;
  asm("{ .reg .u64 t; cvta.to.shared.u64 t, %1; cvt.u32.u64 %0, t; }" : "=r"(a) : "l"(p));
  return a;
}
__device__ __forceinline__ unsigned long long mkdesc(unsigned addr) {
  return DESC_BASE | ((unsigned long long)(addr >> 4) & 0x3FFF);
}
__device__ __forceinline__ unsigned swzb(unsigned off) { return off ^ ((off >> 3) & 0x70); }
__device__ __forceinline__ unsigned elect1() {
  unsigned p;
  asm volatile("{\n\t.reg .pred p;\n\telect.sync _|p, 0xFFFFFFFF;\n\tselp.b32 %0, 1, 0, p;\n\t}" : "=r"(p));
  return p;
}
__device__ __forceinline__ void mbar_init(unsigned mbar, unsigned cnt) {
  asm volatile("mbarrier.init.shared.b64 [%0], %1;" :: "r"(mbar), "r"(cnt) : "memory");
}
__device__ __forceinline__ void mbar_wait(unsigned mbar, unsigned parity) {
  asm volatile(
      "{\n\t.reg .pred P1;\n\t"
      "LWAIT_%=:\n\t"
      "mbarrier.try_wait.parity.acquire.cta.shared::cta.b64 P1, [%0], %1, 0x989680;\n\t"
      "@P1 bra.uni LDONE_%=;\n\t"
      "bra.uni LWAIT_%=;\n\t"
      "LDONE_%=:\n\t}"
      :: "r"(mbar), "r"(parity) : "memory");
}
__device__ __forceinline__ void mbar_expect(unsigned mbar, unsigned bytes) {
  asm volatile("mbarrier.arrive.expect_tx.shared.b64 _, [%0], %1;"
               :: "r"(mbar), "r"(bytes) : "memory");
}
__device__ __forceinline__ void bulk_cp(unsigned dst, const void* src,
                                        unsigned bytes, unsigned mbar) {
  asm volatile(
      "cp.async.bulk.shared::cta.global.mbarrier::complete_tx::bytes [%0], [%1], %2, [%3];"
      :: "r"(dst), "l"(src), "r"(bytes), "r"(mbar) : "memory");
}
__device__ __forceinline__ void tc_commit(unsigned mbar) {
  asm volatile(
      "tcgen05.commit.cta_group::1.mbarrier::arrive::one.shared::cluster.b64 [%0];"
      :: "r"(mbar) : "memory");
}
__device__ __forceinline__ void tc_alloc(unsigned dst, unsigned ncols) {
  asm volatile("tcgen05.alloc.cta_group::1.sync.aligned.shared::cta.b32 [%0], %1;"
               :: "r"(dst), "r"(ncols) : "memory");
}
__device__ __forceinline__ void tc_relinq() {
  asm volatile("tcgen05.relinquish_alloc_permit.cta_group::1.sync.aligned;");
}
__device__ __forceinline__ void tc_dealloc(unsigned base, unsigned ncols) {
  asm volatile("tcgen05.dealloc.cta_group::1.sync.aligned.b32 %0, %1;" :: "r"(base), "r"(ncols));
}
__device__ __forceinline__ void fence_before() {
  asm volatile("tcgen05.fence::before_thread_sync;" ::: "memory");
}
__device__ __forceinline__ void fence_after() {
  asm volatile("tcgen05.fence::after_thread_sync;" ::: "memory");
}
__device__ __forceinline__ void fence_proxy() {
  asm volatile("fence.proxy.async.shared::cta;" ::: "memory");
}
__device__ __forceinline__ void wait_ld() { asm volatile("tcgen05.wait::ld.sync.aligned;" ::: "memory"); }
__device__ __forceinline__ void wait_st() { asm volatile("tcgen05.wait::st.sync.aligned;" ::: "memory"); }

__device__ __forceinline__ void mma_ss(unsigned d, unsigned long long ad,
                                       unsigned long long bd, unsigned idesc, bool en) {
  unsigned e = en ? 1u : 0u;
  asm volatile(
      "{\n\t.reg .pred p;\n\tsetp.ne.u32 p, %5, 0;\n\t"
      "tcgen05.mma.cta_group::1.kind::f16 [%0], %1, %2, %3, {%4, %4, %4, %4}, p;\n\t}"
      :: "r"(d), "l"(ad), "l"(bd), "r"(idesc), "r"(0u), "r"(e) : "memory");
}
__device__ __forceinline__ void mma_ts(unsigned d, unsigned a,
                                       unsigned long long bd, unsigned idesc, bool en) {
  unsigned e = en ? 1u : 0u;
  asm volatile(
      "{\n\t.reg .pred p;\n\tsetp.ne.u32 p, %5, 0;\n\t"
      "tcgen05.mma.cta_group::1.kind::f16 [%0], [%1], %2, %3, {%4, %4, %4, %4}, p;\n\t}"
      :: "r"(d), "r"(a), "l"(bd), "r"(idesc), "r"(0u), "r"(e) : "memory");
}

#define TLD32(r, addr)                                                        \
  asm volatile(                                                               \
      "tcgen05.ld.sync.aligned.32x32b.x32.b32 "                               \
      "{%0, %1, %2, %3, %4, %5, %6, %7, "                                     \
      " %8, %9, %10, %11, %12, %13, %14, %15, "                               \
      " %16, %17, %18, %19, %20, %21, %22, %23, "                             \
      " %24, %25, %26, %27, %28, %29, %30, %31}, [%32];"                      \
      : "=r"((r)[0]),  "=r"((r)[1]),  "=r"((r)[2]),  "=r"((r)[3]),            \
        "=r"((r)[4]),  "=r"((r)[5]),  "=r"((r)[6]),  "=r"((r)[7]),            \
        "=r"((r)[8]),  "=r"((r)[9]),  "=r"((r)[10]), "=r"((r)[11]),           \
        "=r"((r)[12]), "=r"((r)[13]), "=r"((r)[14]), "=r"((r)[15]),           \
        "=r"((r)[16]), "=r"((r)[17]), "=r"((r)[18]), "=r"((r)[19]),           \
        "=r"((r)[20]), "=r"((r)[21]), "=r"((r)[22]), "=r"((r)[23]),           \
        "=r"((r)[24]), "=r"((r)[25]), "=r"((r)[26]), "=r"((r)[27]),           \
        "=r"((r)[28]), "=r"((r)[29]), "=r"((r)[30]), "=r"((r)[31])            \
      : "r"(addr))

#define TST16(addr, r)                                                        \
  asm volatile(                                                               \
      "tcgen05.st.sync.aligned.32x32b.x16.b32 [%0], "                         \
      "{%1, %2, %3, %4, %5, %6, %7, %8, "                                     \
      " %9, %10, %11, %12, %13, %14, %15, %16};"                              \
      :: "r"(addr),                                                           \
         "r"((r)[0]),  "r"((r)[1]),  "r"((r)[2]),  "r"((r)[3]),               \
         "r"((r)[4]),  "r"((r)[5]),  "r"((r)[6]),  "r"((r)[7]),               \
         "r"((r)[8]),  "r"((r)[9]),  "r"((r)[10]), "r"((r)[11]),              \
         "r"((r)[12]), "r"((r)[13]), "r"((r)[14]), "r"((r)[15])               \
      : "memory")

#endif  // HAS_TC

__global__ __launch_bounds__(256, 2)
void hybrid_attn_tc(const float* __restrict__ Q, const float* __restrict__ K,
                    const float* __restrict__ V, float* __restrict__ O) {
#if HAS_TC
  extern __shared__ char smc[];
  const unsigned sb = sm32(smc);
  const int tid = threadIdx.x;
  const int wid = tid >> 5;
  const int lane = tid & 31;
  const int sub = wid & 3;          // TMEM subpartition (SMSP = wid % 4)
  const int half = wid >> 2;        // column half this warp owns
  const int m0 = blockIdx.x * BMt;
  const int bh = blockIdx.y;
  const int base = ((bh >> 3) * Lc * Hc + (bh & 7)) * Ec;
  const float* Qg = Q + base;
  const float* Kg = K + base;
  const float* Vg = V + base;
  float* Og = O + base;
  const __half* K16 = K16g + (size_t)bh * 2048 * 64;
  const __half* V16 = V16g + (size_t)bh * 2048 * 64;

  if (tid == 0) {
    mbar_init(sb + OFF_MB_S, 1);
    mbar_init(sb + OFF_MB_O, 1);
    mbar_init(sb + OFF_MB_L, 1);
  }
  if (wid == 0) { tc_alloc(sb + OFF_PTR, TM_COLS); tc_relinq(); }
  __syncthreads();
  unsigned tb;
  asm volatile("ld.shared.b32 %0, [%1];" : "=r"(tb) : "r"(sb + OFF_PTR));

  const unsigned long long dq = mkdesc(sb + OFF_QH);

  // ---- kick off bulk copies of K/V tile 0 ----
  if (wid == 0 && elect1()) {
    mbar_expect(sb + OFF_MB_L, 32768u);
    bulk_cp(sb + OFF_K0, K16, 16384u, sb + OFF_MB_L);
    bulk_cp(sb + OFF_V0, V16, 16384u, sb + OFF_MB_L);
  }

  // ---- Q tile -> fp16 (SW128, 128B rows), converted in-kernel (once) ----
  #pragma unroll
  for (int it = 0; it < 8; ++it) {
    const int idx = tid + it * 256;
    const int r = idx >> 4, e4 = (idx & 15) << 2;
    const float4 q = *reinterpret_cast<const float4*>(&Qg[(m0 + r) * RE + e4]);
    const unsigned sw = swzb((unsigned)(r * 128 + e4 * 2));
    *reinterpret_cast<unsigned*>(smc + OFF_QH + sw)     = packh2(q.x, q.y);
    *reinterpret_cast<unsigned*>(smc + OFF_QH + sw + 4) = packh2(q.z, q.w);
  }
  fence_proxy();
  __syncthreads();

  // ---- S-MMA(0) after tile-0 loads land ----
  if (wid == 0 && elect1()) {
    mbar_wait(sb + OFF_MB_L, 0);
    const unsigned long long dk = mkdesc(sb + OFF_K0);
    #pragma unroll
    for (int k = 0; k < 4; ++k) mma_ss(tb + TM_S, dq + 2 * k, dk + 2 * k, IDESC_S, k > 0);
    tc_commit(sb + OFF_MB_S);
  }

  unsigned ps = 0, po = 0, pl = 1;
  float lsum = 0.f;
  const unsigned woff = (unsigned)sub << 21;

  for (int nt = 0; nt < NTt; ++nt) {
    const int vb = (nt & 1) ? OFF_V1 : OFF_V0;
    const int kb2 = (nt & 1) ? OFF_K0 : OFF_K1;
    const int vb2 = (nt & 1) ? OFF_V0 : OFF_V1;
    const bool more = (nt + 1 < NTt);

    // ---- bulk copy K(nt+1): prior reader S(nt-1) already completed ----
    if (more && wid == 0 && elect1()) {
      mbar_expect(sb + OFF_MB_L, 32768u);
      bulk_cp(sb + kb2, K16 + (size_t)(nt + 1) * 8192, 16384u, sb + OFF_MB_L);
    }

    // ---- O(nt-1) must finish before V-buffer and P reuse ----
    if (nt > 0) { mbar_wait(sb + OFF_MB_O, po); po ^= 1; }

    // ---- bulk copy V(nt+1) (reader O(nt-1) just completed) ----
    if (more && wid == 0 && elect1()) {
      bulk_cp(sb + vb2, V16 + (size_t)(nt + 1) * 8192, 16384u, sb + OFF_MB_L);
    }

    // ---- wait S(nt), drain it fully into registers ----
    mbar_wait(sb + OFF_MB_S, ps); ps ^= 1;
    fence_after();
    unsigned sr[64];
    TLD32(sr, tb + TM_S + 64 * half);
    TLD32(sr + 32, tb + TM_S + 64 * half + 32);
    wait_ld();
    fence_before();
    __syncthreads();   // all warps drained S

    // ---- issue S-MMA(nt+1) once loads land (overlaps exp work) ----
    if (more && wid == 0 && elect1()) {
      fence_after();
      mbar_wait(sb + OFF_MB_L, pl);
      const unsigned long long dk = mkdesc(sb + kb2);
      #pragma unroll
      for (int k = 0; k < 4; ++k) mma_ss(tb + TM_S, dq + 2 * k, dk + 2 * k, IDESC_S, k > 0);
      tc_commit(sb + OFF_MB_S);
    }
    if (more) pl ^= 1;

    // ---- epilogue: p = 2^(s*scl2e - bias), fp16, to PH ----
    #pragma unroll
    for (int hb = 0; hb < 2; ++hb) {
      unsigned ph[16];
      #pragma unroll
      for (int c = 0; c < 16; ++c) {
        const float s0 = __uint_as_float(sr[32 * hb + 2 * c]);
        const float s1 = __uint_as_float(sr[32 * hb + 2 * c + 1]);
        const float p0 = ex2f(fmaf(s0, SCL2E, -PBIAS));
        const float p1 = ex2f(fmaf(s1, SCL2E, -PBIAS));
        lsum += p0 + p1;
        ph[c] = packh2(p0, p1);
      }
      TST16(tb + TM_PH + 32 * half + 16 * hb + woff, ph);
    }
    wait_st();
    fence_before();
    __syncthreads();

    // ---- O[128 q][64 e] += P · Vt (8 K-chunks of 16 j) ----
    if (wid == 0 && elect1()) {
      fence_after();
      const unsigned long long dv0 = mkdesc(sb + vb), dv1 = mkdesc(sb + vb + 8192);
      #pragma unroll
      for (int k = 0; k < 8; ++k) {
        const unsigned long long bd = (k < 4) ? (dv0 + 2 * k) : (dv1 + 2 * (k - 4));
        mma_ts(tb + TM_O, tb + TM_PH + 8 * k, bd, IDESC_O, !(nt == 0 && k == 0));
      }
      tc_commit(sb + OFF_MB_O);
    }
  }

  mbar_wait(sb + OFF_MB_O, po);
  fence_after();

  unsigned orr[32];
  TLD32(orr, tb + TM_O + 32 * half);
  wait_ld();
  fence_before();

  float* Ls = reinterpret_cast<float*>(smc + OFF_LS);
  float* LsumS = reinterpret_cast<float*>(smc + OFF_LSUM);

  // ---- local branch scores: 2 (row, jj) pairs per thread (fp32 from gmem) ----
  {
    const int row = tid >> 1;
    const int jb = (tid & 1) << 1;
    #pragma unroll
    for (int t = 0; t < 2; ++t) {
      const int jj = jb + t;
      const int ig = m0 + row;
      const int j = ig - 2 + jj;
      float sc = -1e30f;
      if (j >= 0 && j < Lc) {
        const float* qrow = Qg + ig * RE;
        const float* krow = Kg + j * RE;
        float dot = 0.f;
        #pragma unroll 4
        for (int e4 = 0; e4 < Ec; e4 += 4) {
          const float4 q = *reinterpret_cast<const float4*>(&qrow[e4]);
          const float4 kk = *reinterpret_cast<const float4*>(&krow[e4]);
          dot += q.x * kk.x + q.y * kk.y + q.z * kk.z + q.w * kk.w;
        }
        sc = dot * SCL2E;
      }
      Ls[(row << 2) + jj] = sc;
    }
  }
  // ---- cross-warp lsum combine ----
  if (wid < 4) LsumS[sub * 32 + lane] = lsum;
  __syncthreads();
  if (wid >= 4) LsumS[sub * 32 + lane] += lsum;
  __syncthreads();

  // ---- combine global + local, write output (this warp's e-column half) ----
  {
    const int r = sub * 32 + lane;
    const int ig = m0 + r;
    const float4 lsc = *reinterpret_cast<const float4*>(&Ls[r << 2]);
    const float mx = fmaxf(fmaxf(lsc.x, lsc.y), fmaxf(lsc.z, lsc.w));
    const float w0 = ex2f(lsc.x - mx), w1 = ex2f(lsc.y - mx);
    const float w2 = ex2f(lsc.z - mx), w3 = ex2f(lsc.w - mx);
    const float winv = 1.f / (w0 + w1 + w2 + w3);
    const float n0w = w0 * winv, n1w = w1 * winv, n2w = w2 * winv, n3w = w3 * winv;
    const float invl = 1.f / LsumS[r];
    const bool b0 = (ig - 2) >= 0;
    const bool b1 = (ig - 1) >= 0;
    const bool b3 = (ig + 1) < Lc;
    const float* vp0 = Vg + (ig - 2) * RE;
    const float* vp1 = Vg + (ig - 1) * RE;
    const float* vp2 = Vg + ig * RE;
    const float* vp3 = Vg + (ig + 1) * RE;
    const int e0 = 32 * half;
    #pragma unroll
    for (int c4 = 0; c4 < 32; c4 += 4) {
      const int e4 = e0 + c4;
      float4 o;
      o.x = __uint_as_float(orr[c4 + 0]) * invl;
      o.y = __uint_as_float(orr[c4 + 1]) * invl;
      o.z = __uint_as_float(orr[c4 + 2]) * invl;
      o.w = __uint_as_float(orr[c4 + 3]) * invl;
      if (b0) { const float4 vv = *reinterpret_cast<const float4*>(&vp0[e4]);
                o.x += n0w * vv.x; o.y += n0w * vv.y; o.z += n0w * vv.z; o.w += n0w * vv.w; }
      if (b1) { const float4 vv = *reinterpret_cast<const float4*>(&vp1[e4]);
                o.x += n1w * vv.x; o.y += n1w * vv.y; o.z += n1w * vv.z; o.w += n1w * vv.w; }
      {       const float4 vv = *reinterpret_cast<const float4*>(&vp2[e4]);
                o.x += n2w * vv.x; o.y += n2w * vv.y; o.z += n2w * vv.z; o.w += n2w * vv.w; }
      if (b3) { const float4 vv = *reinterpret_cast<const float4*>(&vp3[e4]);
                o.x += n3w * vv.x; o.y += n3w * vv.y; o.z += n3w * vv.z; o.w += n3w * vv.w; }
      *reinterpret_cast<float4*>(&Og[ig * RE + e4]) = o;
    }
  }

  __syncthreads();
  if (wid == 0) tc_dealloc(tb, TM_COLS);
#endif  // HAS_TC
}

}  // namespace

extern "C" void kernel_launch(void* const* d_in, const int* in_sizes, int n_in,
                              void* d_out, int out_size) {
  const float* Q = (const float*)d_in[0];
  const float* K = (const float*)d_in[1];
  const float* V = (const float*)d_in[2];
  float* O = (float*)d_out;

  cudaFuncSetAttribute(hybrid_attn_tc, cudaFuncAttributeMaxDynamicSharedMemorySize, SMEM_TC);

  cvt_k<<<2048, 256>>>(K);
  cvt_v<<<1024, 256>>>(V);

  dim3 gridTC(Lc / BMt, 4 * Hc);
  hybrid_attn_tc<<<gridTC, 256, SMEM_TC>>>(Q, K, V, O);
}

// round 17
// speedup vs baseline: 9.4090x; 1.0212x over previous
#include <cuda_runtime.h>
#include <cuda_fp16.h>
#include <cstdint>

// tcgen05 is only legal on arch-specific (sm_103a/sm_100a) device passes.
#if defined(__CUDA_ARCH_FEAT_SM103_ALL) || defined(__CUDA_ARCH_FEAT_SM100_ALL) || \
    defined(__CUDA_ARCH_FEAT_SM101_ALL) ||                                        \
    (defined(__CUDA_ARCH_SPECIFIC__) && (__CUDA_ARCH_SPECIFIC__ >= 1000)) ||       \
    (defined(__CUDA_ARCH_FAMILY_SPECIFIC__) && (__CUDA_ARCH_FAMILY_SPECIFIC__ >= 1000))
#define HAS_TC 1
#else
#define HAS_TC 0
#endif

namespace {

constexpr int Lc = 2048, Hc = 8, Ec = 64;
constexpr int RE = Hc * Ec;                  // 512
constexpr float SCL2E = 0.125f * 1.44269504088896340736f;

__device__ __forceinline__ float ex2f(float x) {
  float y; asm("ex2.approx.ftz.f32 %0, %1;" : "=f"(y) : "f"(x)); return y;
}
__device__ __forceinline__ unsigned packh2(float a, float b) {
  __half2 t = __floats2half2_rn(a, b);
  return reinterpret_cast<unsigned&>(t);
}

// fp16 scratch: K16g[bh][j][8 chunks of 16B, swizzle-permuted]
//               V16g[bh][jblk(32)][e(64)][8 chunks of 16B, swizzle-permuted]
__device__ __align__(16) __half K16g[32 * 2048 * 64];
__device__ __align__(16) __half V16g[32 * 2048 * 64];

// ======================= preprocessing kernel ==============================
// blocks [0, 2048): K conversion; blocks [2048, 3072): V transpose+conversion.

__global__ __launch_bounds__(256)
void cvt_kv(const float* __restrict__ K, const float* __restrict__ V) {
  __shared__ __half sT[64 * 72];                    // V path only
  if (blockIdx.x < 2048) {
    const int idx = blockIdx.x * 256 + threadIdx.x; // 524288 chunks
    const int c = idx & 7;
    const int j = (idx >> 3) & 2047;
    const int bh = idx >> 14;
    const int b = bh >> 3, h = bh & 7;
    const float* src = K + ((size_t)(b * Lc + j) * Hc + h) * Ec + c * 8;
    const float4 a = *reinterpret_cast<const float4*>(src);
    const float4 d = *reinterpret_cast<const float4*>(src + 4);
    uint4 o;
    o.x = packh2(a.x, a.y); o.y = packh2(a.z, a.w);
    o.z = packh2(d.x, d.y); o.w = packh2(d.z, d.w);
    *reinterpret_cast<uint4*>(&K16g[(((size_t)bh * 2048 + j) * 8 + (c ^ (j & 7))) * 8]) = o;
  } else {
    const int blk = blockIdx.x - 2048;
    const int bh = blk >> 5;
    const int jblk = blk & 31;
    const int b = bh >> 3, h = bh & 7;
    const int j0 = jblk * 64;
    const int tid = threadIdx.x;
    #pragma unroll
    for (int it = 0; it < 4; ++it) {
      const int lin = tid + it * 256;
      const int r = lin >> 4;
      const int e4 = (lin & 15) << 2;
      const float4 v = *reinterpret_cast<const float4*>(
          V + ((size_t)(b * Lc + j0 + r) * Hc + h) * Ec + e4);
      sT[(e4 + 0) * 72 + r] = __float2half_rn(v.x);
      sT[(e4 + 1) * 72 + r] = __float2half_rn(v.y);
      sT[(e4 + 2) * 72 + r] = __float2half_rn(v.z);
      sT[(e4 + 3) * 72 + r] = __float2half_rn(v.w);
    }
    __syncthreads();
    #pragma unroll
    for (int it = 0; it < 2; ++it) {
      const int lin = tid + it * 256;
      const int e = lin >> 3;
      const int c = lin & 7;
      const uint4 val = *reinterpret_cast<const uint4*>(&sT[e * 72 + c * 8]);
      *reinterpret_cast<uint4*>(
          &V16g[((((size_t)bh * 32 + jblk) * 64 + e) * 8 + (c ^ (e & 7))) * 8]) = val;
    }
  }
}

// ======================= TC kernel (sm_103a path) ==========================

constexpr int BMt = 128, BNt = 128;
constexpr int NTt = Lc / BNt;                // 16 key tiles
constexpr float PBIAS = 4.0f;
constexpr unsigned IDESC_S = 0x08200010u;    // kind::f16: F32 acc, f16, M=128, N=128
constexpr unsigned IDESC_O = 0x08100010u;    // kind::f16: F32 acc, f16, M=128, N=64

constexpr unsigned TM_S = 0;       // 128 cols: S[128 q][128 j] fp32
constexpr unsigned TM_O = 128;     // 64 cols:  O[128 q][64 e] fp32
constexpr unsigned TM_PH = 192;    // 64 cols:  P fp16 packed
constexpr unsigned TM_COLS = 256;

constexpr int OFF_PTR = 0, OFF_MB_S = 8, OFF_MB_O = 16, OFF_MB_LK = 24, OFF_MB_LV = 32;
constexpr int OFF_QH = 1024;                 // Q fp16 [128 q][64 e], 128B rows
constexpr int OFF_K0 = OFF_QH + 16384;
constexpr int OFF_K1 = OFF_K0 + 16384;
constexpr int OFF_V0 = OFF_K1 + 16384;       // Vt fp16: half0 @+0, half1 @+8192
constexpr int OFF_V1 = OFF_V0 + 16384;
constexpr int OFF_LS = OFF_V1 + 16384;       // float Ls[128][4]
constexpr int OFF_LSUM = OFF_LS + 2048;      // float Lsum[128]
constexpr int SMEM_TC = OFF_LSUM + 512;

#if HAS_TC

constexpr unsigned long long DESC_BASE =
    (2ull << 61) | (1ull << 46) | (64ull << 32) | (1ull << 16);

__device__ __forceinline__ unsigned sm32(const void* p) {
  unsigned a;
  asm("{ .reg .u64 t; cvta.to.shared.u64 t, %1; cvt.u32.u64 %0, t; }" : "=r"(a) : "l"(p));
  return a;
}
__device__ __forceinline__ unsigned long long mkdesc(unsigned addr) {
  return DESC_BASE | ((unsigned long long)(addr >> 4) & 0x3FFF);
}
__device__ __forceinline__ unsigned swzb(unsigned off) { return off ^ ((off >> 3) & 0x70); }
__device__ __forceinline__ unsigned elect1() {
  unsigned p;
  asm volatile("{\n\t.reg .pred p;\n\telect.sync _|p, 0xFFFFFFFF;\n\tselp.b32 %0, 1, 0, p;\n\t}" : "=r"(p));
  return p;
}
__device__ __forceinline__ void mbar_init(unsigned mbar, unsigned cnt) {
  asm volatile("mbarrier.init.shared.b64 [%0], %1;" :: "r"(mbar), "r"(cnt) : "memory");
}
__device__ __forceinline__ void mbar_wait(unsigned mbar, unsigned parity) {
  asm volatile(
      "{\n\t.reg .pred P1;\n\t"
      "LWAIT_%=:\n\t"
      "mbarrier.try_wait.parity.acquire.cta.shared::cta.b64 P1, [%0], %1, 0x989680;\n\t"
      "@P1 bra.uni LDONE_%=;\n\t"
      "bra.uni LWAIT_%=;\n\t"
      "LDONE_%=:\n\t}"
      :: "r"(mbar), "r"(parity) : "memory");
}
__device__ __forceinline__ void mbar_expect(unsigned mbar, unsigned bytes) {
  asm volatile("mbarrier.arrive.expect_tx.shared.b64 _, [%0], %1;"
               :: "r"(mbar), "r"(bytes) : "memory");
}
__device__ __forceinline__ void bulk_cp(unsigned dst, const void* src,
                                        unsigned bytes, unsigned mbar) {
  asm volatile(
      "cp.async.bulk.shared::cta.global.mbarrier::complete_tx::bytes [%0], [%1], %2, [%3];"
      :: "r"(dst), "l"(src), "r"(bytes), "r"(mbar) : "memory");
}
__device__ __forceinline__ void tc_commit(unsigned mbar) {
  asm volatile(
      "tcgen05.commit.cta_group::1.mbarrier::arrive::one.shared::cluster.b64 [%0];"
      :: "r"(mbar) : "memory");
}
__device__ __forceinline__ void tc_alloc(unsigned dst, unsigned ncols) {
  asm volatile("tcgen05.alloc.cta_group::1.sync.aligned.shared::cta.b32 [%0], %1;"
               :: "r"(dst), "r"(ncols) : "memory");
}
__device__ __forceinline__ void tc_relinq() {
  asm volatile("tcgen05.relinquish_alloc_permit.cta_group::1.sync.aligned;");
}
__device__ __forceinline__ void tc_dealloc(unsigned base, unsigned ncols) {
  asm volatile("tcgen05.dealloc.cta_group::1.sync.aligned.b32 %0, %1;" :: "r"(base), "r"(ncols));
}
__device__ __forceinline__ void fence_before() {
  asm volatile("tcgen05.fence::before_thread_sync;" ::: "memory");
}
__device__ __forceinline__ void fence_after() {
  asm volatile("tcgen05.fence::after_thread_sync;" ::: "memory");
}
__device__ __forceinline__ void fence_proxy() {
  asm volatile("fence.proxy.async.shared::cta;" ::: "memory");
}
__device__ __forceinline__ void wait_ld() { asm volatile("tcgen05.wait::ld.sync.aligned;" ::: "memory"); }
__device__ __forceinline__ void wait_st() { asm volatile("tcgen05.wait::st.sync.aligned;" ::: "memory"); }

__device__ __forceinline__ void mma_ss(unsigned d, unsigned long long ad,
                                       unsigned long long bd, unsigned idesc, bool en) {
  unsigned e = en ? 1u : 0u;
  asm volatile(
      "{\n\t.reg .pred p;\n\tsetp.ne.u32 p, %5, 0;\n\t"
      "tcgen05.mma.cta_group::1.kind::f16 [%0], %1, %2, %3, {%4, %4, %4, %4}, p;\n\t}"
      :: "r"(d), "l"(ad), "l"(bd), "r"(idesc), "r"(0u), "r"(e) : "memory");
}
__device__ __forceinline__ void mma_ts(unsigned d, unsigned a,
                                       unsigned long long bd, unsigned idesc, bool en) {
  unsigned e = en ? 1u : 0u;
  asm volatile(
      "{\n\t.reg .pred p;\n\tsetp.ne.u32 p, %5, 0;\n\t"
      "tcgen05.mma.cta_group::1.kind::f16 [%0], [%1], %2, %3, {%4, %4, %4, %4}, p;\n\t}"
      :: "r"(d), "r"(a), "l"(bd), "r"(idesc), "r"(0u), "r"(e) : "memory");
}

#define TLD32(r, addr)                                                        \
  asm volatile(                                                               \
      "tcgen05.ld.sync.aligned.32x32b.x32.b32 "                               \
      "{%0, %1, %2, %3, %4, %5, %6, %7, "                                     \
      " %8, %9, %10, %11, %12, %13, %14, %15, "                               \
      " %16, %17, %18, %19, %20, %21, %22, %23, "                             \
      " %24, %25, %26, %27, %28, %29, %30, %31}, [%32];"                      \
      : "=r"((r)[0]),  "=r"((r)[1]),  "=r"((r)[2]),  "=r"((r)[3]),            \
        "=r"((r)[4]),  "=r"((r)[5]),  "=r"((r)[6]),  "=r"((r)[7]),            \
        "=r"((r)[8]),  "=r"((r)[9]),  "=r"((r)[10]), "=r"((r)[11]),           \
        "=r"((r)[12]), "=r"((r)[13]), "=r"((r)[14]), "=r"((r)[15]),           \
        "=r"((r)[16]), "=r"((r)[17]), "=r"((r)[18]), "=r"((r)[19]),           \
        "=r"((r)[20]), "=r"((r)[21]), "=r"((r)[22]), "=r"((r)[23]),           \
        "=r"((r)[24]), "=r"((r)[25]), "=r"((r)[26]), "=r"((r)[27]),           \
        "=r"((r)[28]), "=r"((r)[29]), "=r"((r)[30]), "=r"((r)[31])            \
      : "r"(addr))

#define TST16(addr, r)                                                        \
  asm volatile(                                                               \
      "tcgen05.st.sync.aligned.32x32b.x16.b32 [%0], "                         \
      "{%1, %2, %3, %4, %5, %6, %7, %8, "                                     \
      " %9, %10, %11, %12, %13, %14, %15, %16};"                              \
      :: "r"(addr),                                                           \
         "r"((r)[0]),  "r"((r)[1]),  "r"((r)[2]),  "r"((r)[3]),               \
         "r"((r)[4]),  "r"((r)[5]),  "r"((r)[6]),  "r"((r)[7]),               \
         "r"((r)[8]),  "r"((r)[9]),  "r"((r)[10]), "r"((r)[11]),              \
         "r"((r)[12]), "r"((r)[13]), "r"((r)[14]), "r"((r)[15])               \
      : "memory")

#endif  // HAS_TC

__global__ __launch_bounds__(256, 2)
void hybrid_attn_tc(const float* __restrict__ Q, const float* __restrict__ K,
                    const float* __restrict__ V, float* __restrict__ O) {
#if HAS_TC
  extern __shared__ char smc[];
  const unsigned sb = sm32(smc);
  const int tid = threadIdx.x;
  const int wid = tid >> 5;
  const int lane = tid & 31;
  const int sub = wid & 3;          // TMEM subpartition (SMSP = wid % 4)
  const int half = wid >> 2;        // column half this warp owns
  const int m0 = blockIdx.x * BMt;
  const int bh = blockIdx.y;
  const int base = ((bh >> 3) * Lc * Hc + (bh & 7)) * Ec;
  const float* Qg = Q + base;
  const float* Kg = K + base;
  const float* Vg = V + base;
  float* Og = O + base;
  const __half* K16 = K16g + (size_t)bh * 2048 * 64;
  const __half* V16 = V16g + (size_t)bh * 2048 * 64;

  if (tid == 0) {
    mbar_init(sb + OFF_MB_S, 1);
    mbar_init(sb + OFF_MB_O, 1);
    mbar_init(sb + OFF_MB_LK, 1);
    mbar_init(sb + OFF_MB_LV, 1);
  }
  if (wid == 0) { tc_alloc(sb + OFF_PTR, TM_COLS); tc_relinq(); }
  __syncthreads();
  unsigned tb;
  asm volatile("ld.shared.b32 %0, [%1];" : "=r"(tb) : "r"(sb + OFF_PTR));

  const unsigned long long dq = mkdesc(sb + OFF_QH);

  // ---- kick off bulk copies of K/V tile 0 ----
  if (wid == 0 && elect1()) {
    mbar_expect(sb + OFF_MB_LK, 16384u);
    bulk_cp(sb + OFF_K0, K16, 16384u, sb + OFF_MB_LK);
    mbar_expect(sb + OFF_MB_LV, 16384u);
    bulk_cp(sb + OFF_V0, V16, 16384u, sb + OFF_MB_LV);
  }

  // ---- Q tile -> fp16 (SW128, 128B rows), converted in-kernel (once) ----
  #pragma unroll
  for (int it = 0; it < 8; ++it) {
    const int idx = tid + it * 256;
    const int r = idx >> 4, e4 = (idx & 15) << 2;
    const float4 q = *reinterpret_cast<const float4*>(&Qg[(m0 + r) * RE + e4]);
    const unsigned sw = swzb((unsigned)(r * 128 + e4 * 2));
    *reinterpret_cast<unsigned*>(smc + OFF_QH + sw)     = packh2(q.x, q.y);
    *reinterpret_cast<unsigned*>(smc + OFF_QH + sw + 4) = packh2(q.z, q.w);
  }
  fence_proxy();
  __syncthreads();

  // ---- S-MMA(0) after K tile 0 lands ----
  if (wid == 0 && elect1()) {
    mbar_wait(sb + OFF_MB_LK, 0);
    const unsigned long long dk = mkdesc(sb + OFF_K0);
    #pragma unroll
    for (int k = 0; k < 4; ++k) mma_ss(tb + TM_S, dq + 2 * k, dk + 2 * k, IDESC_S, k > 0);
    tc_commit(sb + OFF_MB_S);
  }

  unsigned ps = 0, po = 0, plk = 1;
  float lsum = 0.f;
  const unsigned woff = (unsigned)sub << 21;

  for (int nt = 0; nt < NTt; ++nt) {
    const int vb = (nt & 1) ? OFF_V1 : OFF_V0;
    const int kb2 = (nt & 1) ? OFF_K0 : OFF_K1;
    const int vb2 = (nt & 1) ? OFF_V0 : OFF_V1;
    const bool more = (nt + 1 < NTt);

    // ---- bulk copy K(nt+1). Phase-order safe: MB_LK's previous phase (K(nt))
    //      was observed complete at the S-MMA issue of iteration nt-1. ----
    if (more && wid == 0 && elect1()) {
      mbar_expect(sb + OFF_MB_LK, 16384u);
      bulk_cp(sb + kb2, K16 + (size_t)(nt + 1) * 8192, 16384u, sb + OFF_MB_LK);
    }

    // ---- O(nt-1) must finish before V-buffer and P reuse ----
    if (nt > 0) { mbar_wait(sb + OFF_MB_O, po); po ^= 1; }

    // ---- V: FIRST observe V(nt)'s phase complete, THEN issue expect for
    //      V(nt+1). Issuing expect_tx into a still-pending phase merges the
    //      phases and shifts parity forever (the R16 deadlock). ----
    if (wid == 0 && elect1()) {
      mbar_wait(sb + OFF_MB_LV, (unsigned)(nt & 1));   // V(nt) landed
      if (more) {
        mbar_expect(sb + OFF_MB_LV, 16384u);
        bulk_cp(sb + vb2, V16 + (size_t)(nt + 1) * 8192, 16384u, sb + OFF_MB_LV);
      }
    }

    // ---- wait S(nt), drain it fully into registers ----
    mbar_wait(sb + OFF_MB_S, ps); ps ^= 1;
    fence_after();
    unsigned sr[64];
    TLD32(sr, tb + TM_S + 64 * half);
    TLD32(sr + 32, tb + TM_S + 64 * half + 32);
    wait_ld();
    fence_before();
    __syncthreads();   // all warps drained S

    // ---- issue S-MMA(nt+1) once K(nt+1) lands (overlaps exp work) ----
    if (more && wid == 0 && elect1()) {
      fence_after();
      mbar_wait(sb + OFF_MB_LK, plk);
      const unsigned long long dk = mkdesc(sb + kb2);
      #pragma unroll
      for (int k = 0; k < 4; ++k) mma_ss(tb + TM_S, dq + 2 * k, dk + 2 * k, IDESC_S, k > 0);
      tc_commit(sb + OFF_MB_S);
    }
    if (more) plk ^= 1;

    // ---- epilogue: p = 2^(s*scl2e - bias), fp16, to PH ----
    #pragma unroll
    for (int hb = 0; hb < 2; ++hb) {
      unsigned ph[16];
      #pragma unroll
      for (int c = 0; c < 16; ++c) {
        const float s0 = __uint_as_float(sr[32 * hb + 2 * c]);
        const float s1 = __uint_as_float(sr[32 * hb + 2 * c + 1]);
        const float p0 = ex2f(fmaf(s0, SCL2E, -PBIAS));
        const float p1 = ex2f(fmaf(s1, SCL2E, -PBIAS));
        lsum += p0 + p1;
        ph[c] = packh2(p0, p1);
      }
      TST16(tb + TM_PH + 32 * half + 16 * hb + woff, ph);
    }
    wait_st();
    fence_before();
    __syncthreads();

    // ---- O[128 q][64 e] += P · Vt (V(nt) observed landed above) ----
    if (wid == 0 && elect1()) {
      fence_after();
      const unsigned long long dv0 = mkdesc(sb + vb), dv1 = mkdesc(sb + vb + 8192);
      #pragma unroll
      for (int k = 0; k < 8; ++k) {
        const unsigned long long bd = (k < 4) ? (dv0 + 2 * k) : (dv1 + 2 * (k - 4));
        mma_ts(tb + TM_O, tb + TM_PH + 8 * k, bd, IDESC_O, !(nt == 0 && k == 0));
      }
      tc_commit(sb + OFF_MB_O);
    }
  }

  mbar_wait(sb + OFF_MB_O, po);
  fence_after();

  unsigned orr[32];
  TLD32(orr, tb + TM_O + 32 * half);
  wait_ld();
  fence_before();

  float* Ls = reinterpret_cast<float*>(smc + OFF_LS);
  float* LsumS = reinterpret_cast<float*>(smc + OFF_LSUM);

  // ---- local branch scores: 2 (row, jj) pairs per thread (fp32 from gmem) ----
  {
    const int row = tid >> 1;
    const int jb = (tid & 1) << 1;
    #pragma unroll
    for (int t = 0; t < 2; ++t) {
      const int jj = jb + t;
      const int ig = m0 + row;
      const int j = ig - 2 + jj;
      float sc = -1e30f;
      if (j >= 0 && j < Lc) {
        const float* qrow = Qg + ig * RE;
        const float* krow = Kg + j * RE;
        float dot = 0.f;
        #pragma unroll 4
        for (int e4 = 0; e4 < Ec; e4 += 4) {
          const float4 q = *reinterpret_cast<const float4*>(&qrow[e4]);
          const float4 kk = *reinterpret_cast<const float4*>(&krow[e4]);
          dot += q.x * kk.x + q.y * kk.y + q.z * kk.z + q.w * kk.w;
        }
        sc = dot * SCL2E;
      }
      Ls[(row << 2) + jj] = sc;
    }
  }
  // ---- cross-warp lsum combine ----
  if (wid < 4) LsumS[sub * 32 + lane] = lsum;
  __syncthreads();
  if (wid >= 4) LsumS[sub * 32 + lane] += lsum;
  __syncthreads();

  // ---- combine global + local, write output (this warp's e-column half) ----
  {
    const int r = sub * 32 + lane;
    const int ig = m0 + r;
    const float4 lsc = *reinterpret_cast<const float4*>(&Ls[r << 2]);
    const float mx = fmaxf(fmaxf(lsc.x, lsc.y), fmaxf(lsc.z, lsc.w));
    const float w0 = ex2f(lsc.x - mx), w1 = ex2f(lsc.y - mx);
    const float w2 = ex2f(lsc.z - mx), w3 = ex2f(lsc.w - mx);
    const float winv = 1.f / (w0 + w1 + w2 + w3);
    const float n0w = w0 * winv, n1w = w1 * winv, n2w = w2 * winv, n3w = w3 * winv;
    const float invl = 1.f / LsumS[r];
    const bool b0 = (ig - 2) >= 0;
    const bool b1 = (ig - 1) >= 0;
    const bool b3 = (ig + 1) < Lc;
    const float* vp0 = Vg + (ig - 2) * RE;
    const float* vp1 = Vg + (ig - 1) * RE;
    const float* vp2 = Vg + ig * RE;
    const float* vp3 = Vg + (ig + 1) * RE;
    const int e0 = 32 * half;
    #pragma unroll
    for (int c4 = 0; c4 < 32; c4 += 4) {
      const int e4 = e0 + c4;
      float4 o;
      o.x = __uint_as_float(orr[c4 + 0]) * invl;
      o.y = __uint_as_float(orr[c4 + 1]) * invl;
      o.z = __uint_as_float(orr[c4 + 2]) * invl;
      o.w = __uint_as_float(orr[c4 + 3]) * invl;
      if (b0) { const float4 vv = *reinterpret_cast<const float4*>(&vp0[e4]);
                o.x += n0w * vv.x; o.y += n0w * vv.y; o.z += n0w * vv.z; o.w += n0w * vv.w; }
      if (b1) { const float4 vv = *reinterpret_cast<const float4*>(&vp1[e4]);
                o.x += n1w * vv.x; o.y += n1w * vv.y; o.z += n1w * vv.z; o.w += n1w * vv.w; }
      {       const float4 vv = *reinterpret_cast<const float4*>(&vp2[e4]);
                o.x += n2w * vv.x; o.y += n2w * vv.y; o.z += n2w * vv.z; o.w += n2w * vv.w; }
      if (b3) { const float4 vv = *reinterpret_cast<const float4*>(&vp3[e4]);
                o.x += n3w * vv.x; o.y += n3w * vv.y; o.z += n3w * vv.z; o.w += n3w * vv.w; }
      *reinterpret_cast<float4*>(&Og[ig * RE + e4]) = o;
    }
  }

  __syncthreads();
  if (wid == 0) tc_dealloc(tb, TM_COLS);
#endif  // HAS_TC
}

}  // namespace

extern "C" void kernel_launch(void* const* d_in, const int* in_sizes, int n_in,
                              void* d_out, int out_size) {
  const float* Q = (const float*)d_in[0];
  const float* K = (const float*)d_in[1];
  const float* V = (const float*)d_in[2];
  float* O = (float*)d_out;

  cudaFuncSetAttribute(hybrid_attn_tc, cudaFuncAttributeMaxDynamicSharedMemorySize, SMEM_TC);

  cvt_kv<<<3072, 256>>>(K, V);

  dim3 gridTC(Lc / BMt, 4 * Hc);
  hybrid_attn_tc<<<gridTC, 256, SMEM_TC>>>(Q, K, V, O);
}